// round 1
// baseline (speedup 1.0000x reference)
#include <cuda_runtime.h>

// Problem constants (fixed by the dataset)
#define NN   50000
#define EE   600000
#define FD   128
#define EDIM 16
#define HH   4
#define DD   32
#define HIDD 128
#define CC   10

// ---------------------------------------------------------------------------
// Scratch (device globals; allocation-free per harness rules)
// ---------------------------------------------------------------------------
__device__ __align__(16) float d_qkvs[(size_t)NN * 512];   // q|k|v|skip packed per node
__device__ __align__(16) float d_e[(size_t)EE * 128];      // edge embeddings
__device__ __align__(16) float d_logits[(size_t)EE * 4];
__device__ __align__(16) float d_m[(size_t)NN * 4];
__device__ __align__(16) float d_denom[(size_t)NN * 4];
__device__ __align__(16) float d_acc[(size_t)NN * 128];
__device__ __align__(16) float d_h[(size_t)NN * 128];      // layer output
__device__ __align__(16) float d_Wp[128 * 512];            // packed [K=128, 4*128]
__device__ __align__(16) float d_bp[512];

// ---------------------------------------------------------------------------
// Helpers
// ---------------------------------------------------------------------------
__device__ __forceinline__ void atomicMaxFloat(float* addr, float value) {
    if (value >= 0.0f)
        atomicMax((int*)addr, __float_as_int(value));
    else
        atomicMin((unsigned int*)addr, __float_as_uint(value));
}

// ---------------------------------------------------------------------------
// Pack 4 weight matrices [128,128] into one [128,512] (col blocks q,k,v,s)
// ---------------------------------------------------------------------------
__global__ void pack_kernel(const float* __restrict__ Wq, const float* __restrict__ Wk,
                            const float* __restrict__ Wv, const float* __restrict__ Ws,
                            const float* __restrict__ bq, const float* __restrict__ bk,
                            const float* __restrict__ bv, const float* __restrict__ bs) {
    int idx = blockIdx.x * blockDim.x + threadIdx.x;
    if (idx < 128 * 512) {
        int k = idx >> 9, j = idx & 511;
        int sel = j >> 7, jc = j & 127;
        const float* W = sel == 0 ? Wq : sel == 1 ? Wk : sel == 2 ? Wv : Ws;
        d_Wp[idx] = W[k * 128 + jc];
    }
    if (idx < 512) {
        int sel = idx >> 7, jc = idx & 127;
        const float* b = sel == 0 ? bq : sel == 1 ? bk : sel == 2 ? bv : bs;
        d_bp[idx] = b[jc];
    }
}

// ---------------------------------------------------------------------------
// SGEMM: C[M,512] = A[M,128] @ d_Wp[128,512] + d_bp, A = x (layer 0) or d_h
// 128x128 block tile, BK=8, 256 threads, 8x8 per thread.
// ---------------------------------------------------------------------------
__global__ void __launch_bounds__(256) sgemm_qkvs(const float* __restrict__ x, int layer, int M) {
    const float* A = (layer == 0) ? x : (const float*)d_h;

    __shared__ __align__(16) float As[8][128];   // transposed A tile
    __shared__ __align__(16) float Bs[8][128];

    int tid = threadIdx.x;
    int bx = blockIdx.x;           // 0..3  (N blocks of 128)
    int by = blockIdx.y;           // M blocks
    int trow = tid >> 4;           // 0..15
    int tcol = tid & 15;           // 0..15

    float acc[8][8];
#pragma unroll
    for (int i = 0; i < 8; i++)
#pragma unroll
        for (int j = 0; j < 8; j++) acc[i][j] = 0.0f;

    int aRow = tid >> 1;
    int aCol = (tid & 1) * 4;
    int bRow = tid >> 5;
    int bCol = (tid & 31) * 4;
    int rowBase = by * 128;

    for (int k0 = 0; k0 < 128; k0 += 8) {
        int gr = rowBase + aRow;
        float4 a4 = make_float4(0.f, 0.f, 0.f, 0.f);
        if (gr < M) a4 = *(const float4*)(A + (size_t)gr * 128 + k0 + aCol);
        As[aCol + 0][aRow] = a4.x;
        As[aCol + 1][aRow] = a4.y;
        As[aCol + 2][aRow] = a4.z;
        As[aCol + 3][aRow] = a4.w;

        float4 b4 = *(const float4*)(d_Wp + (k0 + bRow) * 512 + bx * 128 + bCol);
        *(float4*)&Bs[bRow][bCol] = b4;
        __syncthreads();

#pragma unroll
        for (int kk = 0; kk < 8; kk++) {
            float4 a0 = *(const float4*)&As[kk][trow * 8];
            float4 a1 = *(const float4*)&As[kk][trow * 8 + 4];
            float4 b0 = *(const float4*)&Bs[kk][tcol * 8];
            float4 b1 = *(const float4*)&Bs[kk][tcol * 8 + 4];
            float ar[8] = {a0.x, a0.y, a0.z, a0.w, a1.x, a1.y, a1.z, a1.w};
            float br[8] = {b0.x, b0.y, b0.z, b0.w, b1.x, b1.y, b1.z, b1.w};
#pragma unroll
            for (int i = 0; i < 8; i++)
#pragma unroll
                for (int j = 0; j < 8; j++) acc[i][j] += ar[i] * br[j];
        }
        __syncthreads();
    }

    int c = bx * 128 + tcol * 8;
    float4 bias0 = *(const float4*)(d_bp + c);
    float4 bias1 = *(const float4*)(d_bp + c + 4);
#pragma unroll
    for (int i = 0; i < 8; i++) {
        int r = rowBase + trow * 8 + i;
        if (r < M) {
            float4 o0 = make_float4(acc[i][0] + bias0.x, acc[i][1] + bias0.y,
                                    acc[i][2] + bias0.z, acc[i][3] + bias0.w);
            float4 o1 = make_float4(acc[i][4] + bias1.x, acc[i][5] + bias1.y,
                                    acc[i][6] + bias1.z, acc[i][7] + bias1.w);
            *(float4*)(d_qkvs + (size_t)r * 512 + c) = o0;
            *(float4*)(d_qkvs + (size_t)r * 512 + c + 4) = o1;
        }
    }
}

// ---------------------------------------------------------------------------
// Edge embedding: d_e[E,128] = edge_attr[E,16] @ We[16,128]
// one warp per edge
// ---------------------------------------------------------------------------
__global__ void __launch_bounds__(256) egemm(const float* __restrict__ eattr,
                                             const float* __restrict__ We) {
    __shared__ __align__(16) float sW[16 * 128];
    int tid = threadIdx.x;
    for (int i = tid; i < 16 * 128; i += 256) sW[i] = We[i];
    __syncthreads();

    int warp = (blockIdx.x * 256 + tid) >> 5;
    int lane = tid & 31;
    if (warp >= EE) return;

    const float* ea = eattr + (size_t)warp * 16;
    float4 o = make_float4(0.f, 0.f, 0.f, 0.f);
#pragma unroll
    for (int k = 0; k < 16; k++) {
        float a = __ldg(ea + k);
        float4 w = *(const float4*)&sW[k * 128 + lane * 4];
        o.x += a * w.x; o.y += a * w.y; o.z += a * w.z; o.w += a * w.w;
    }
    *(float4*)(d_e + (size_t)warp * 128 + lane * 4) = o;
}

// ---------------------------------------------------------------------------
// Init accumulators
// ---------------------------------------------------------------------------
__global__ void init_kernel() {
    int idx = blockIdx.x * blockDim.x + threadIdx.x;
    if (idx < NN * 128) d_acc[idx] = 0.0f;
    if (idx < NN * 4) {
        d_m[idx] = __int_as_float(0xff800000);  // -inf
        d_denom[idx] = 0.0f;
    }
}

// ---------------------------------------------------------------------------
// Edge pass 1: logits + segment max. One warp per edge.
// ---------------------------------------------------------------------------
__global__ void __launch_bounds__(256) pass1(const int* __restrict__ src,
                                             const int* __restrict__ dst) {
    int gid = blockIdx.x * 256 + threadIdx.x;
    int e = gid >> 5;
    if (e >= EE) return;
    int lane = gid & 31;

    int s = src[e], d = dst[e];
    float4 q  = *(const float4*)(d_qkvs + (size_t)d * 512 + lane * 4);
    float4 k  = *(const float4*)(d_qkvs + (size_t)s * 512 + 128 + lane * 4);
    float4 ev = *(const float4*)(d_e + (size_t)e * 128 + lane * 4);

    float p = q.x * (k.x + ev.x) + q.y * (k.y + ev.y) +
              q.z * (k.z + ev.z) + q.w * (k.w + ev.w);
    p += __shfl_xor_sync(0xffffffff, p, 1);
    p += __shfl_xor_sync(0xffffffff, p, 2);
    p += __shfl_xor_sync(0xffffffff, p, 4);

    if ((lane & 7) == 0) {
        int h = lane >> 3;
        float logit = p * 0.17677669529663687f;  // 1/sqrt(32)
        d_logits[(size_t)e * 4 + h] = logit;
        atomicMaxFloat(&d_m[d * 4 + h], logit);
    }
}

// ---------------------------------------------------------------------------
// Edge pass 2: exp, denom, weighted scatter of (v[src]+e). One warp per edge.
// ---------------------------------------------------------------------------
__global__ void __launch_bounds__(256) pass2(const int* __restrict__ src,
                                             const int* __restrict__ dst) {
    int gid = blockIdx.x * 256 + threadIdx.x;
    int e = gid >> 5;
    if (e >= EE) return;
    int lane = gid & 31;

    int s = src[e], d = dst[e];
    int h = lane >> 3;
    float logit = d_logits[(size_t)e * 4 + h];
    float mv = d_m[d * 4 + h];
    float ex = __expf(logit - mv);
    if ((lane & 7) == 0) atomicAdd(&d_denom[d * 4 + h], ex);

    float4 v  = *(const float4*)(d_qkvs + (size_t)s * 512 + 256 + lane * 4);
    float4 ev = *(const float4*)(d_e + (size_t)e * 128 + lane * 4);
    float vx = (v.x + ev.x) * ex;
    float vy = (v.y + ev.y) * ex;
    float vz = (v.z + ev.z) * ex;
    float vw = (v.w + ev.w) * ex;

    float* ap = d_acc + (size_t)d * 128 + lane * 4;
    asm volatile("red.global.add.v4.f32 [%0], {%1,%2,%3,%4};"
                 :: "l"(ap), "f"(vx), "f"(vy), "f"(vz), "f"(vw) : "memory");
}

// ---------------------------------------------------------------------------
// Finalize: h = relu(acc/(denom+eps) + skip)
// ---------------------------------------------------------------------------
__global__ void finalize_kernel() {
    int idx = blockIdx.x * blockDim.x + threadIdx.x;
    if (idx >= NN * 128) return;
    int n = idx >> 7, j = idx & 127, h = j >> 5;
    float val = d_acc[idx] / (d_denom[n * 4 + h] + 1e-16f) + d_qkvs[(size_t)n * 512 + 384 + j];
    d_h[idx] = fmaxf(val, 0.0f);
}

// ---------------------------------------------------------------------------
// Output head: logits = h @ Wout + bout; log_softmax. One warp per node.
// ---------------------------------------------------------------------------
__global__ void __launch_bounds__(256) out_kernel(const float* __restrict__ Wout,
                                                  const float* __restrict__ bout,
                                                  float* __restrict__ out) {
    __shared__ float sW[128 * 10];
    __shared__ float sb[10];
    int tid = threadIdx.x;
    for (int i = tid; i < 128 * 10; i += 256) sW[i] = Wout[i];
    if (tid < 10) sb[tid] = bout[tid];
    __syncthreads();

    int warp = (blockIdx.x * 256 + tid) >> 5;
    int lane = tid & 31;
    if (warp >= NN) return;

    float4 hv = *(const float4*)(d_h + (size_t)warp * 128 + lane * 4);
    float lg[10];
#pragma unroll
    for (int c = 0; c < 10; c++) {
        float p = hv.x * sW[(lane * 4 + 0) * 10 + c] +
                  hv.y * sW[(lane * 4 + 1) * 10 + c] +
                  hv.z * sW[(lane * 4 + 2) * 10 + c] +
                  hv.w * sW[(lane * 4 + 3) * 10 + c];
        p += __shfl_xor_sync(0xffffffff, p, 16);
        p += __shfl_xor_sync(0xffffffff, p, 8);
        p += __shfl_xor_sync(0xffffffff, p, 4);
        p += __shfl_xor_sync(0xffffffff, p, 2);
        p += __shfl_xor_sync(0xffffffff, p, 1);
        lg[c] = p + sb[c];
    }
    float mx = lg[0];
#pragma unroll
    for (int c = 1; c < 10; c++) mx = fmaxf(mx, lg[c]);
    float ss = 0.0f;
#pragma unroll
    for (int c = 0; c < 10; c++) ss += __expf(lg[c] - mx);
    float lse = mx + logf(ss);
    if (lane == 0) {
#pragma unroll
        for (int c = 0; c < 10; c++)
            out[(size_t)warp * 10 + c] = lg[c] - lse;
    }
}

// ---------------------------------------------------------------------------
// Launch
// ---------------------------------------------------------------------------
extern "C" void kernel_launch(void* const* d_in, const int* in_sizes, int n_in,
                              void* d_out, int out_size) {
    const float* x     = (const float*)d_in[0];
    const int*   ei    = (const int*)d_in[1];
    const float* eattr = (const float*)d_in[2];
    // layer 0: 3..11  (Wq,bq,Wk,bk,Wv,bv,We,Ws,bs)
    // layer 1: 12..20
    const float* Wout = (const float*)d_in[21];
    const float* bout = (const float*)d_in[22];
    float* out = (float*)d_out;

    const int* src = ei;       // edge_index[0]
    const int* dst = ei + EE;  // edge_index[1]

    const int PACK_BLKS = (128 * 512 + 255) / 256;
    const int EDGE_BLKS = (EE + 7) / 8;           // warp/edge, 8 edges per block
    const int NODE_BLKS = (NN * 128 + 255) / 256;
    const int OUT_BLKS  = (NN * 32 + 255) / 256;
    dim3 gemmGrid(4, (NN + 127) / 128);

    for (int layer = 0; layer < 2; layer++) {
        int base = 3 + layer * 9;
        const float* Wq = (const float*)d_in[base + 0];
        const float* bq = (const float*)d_in[base + 1];
        const float* Wk = (const float*)d_in[base + 2];
        const float* bk = (const float*)d_in[base + 3];
        const float* Wv = (const float*)d_in[base + 4];
        const float* bv = (const float*)d_in[base + 5];
        const float* We = (const float*)d_in[base + 6];
        const float* Ws = (const float*)d_in[base + 7];
        const float* bs = (const float*)d_in[base + 8];

        pack_kernel<<<PACK_BLKS, 256>>>(Wq, Wk, Wv, Ws, bq, bk, bv, bs);
        sgemm_qkvs<<<gemmGrid, 256>>>(x, layer, NN);
        egemm<<<EDGE_BLKS, 256>>>(eattr, We);
        init_kernel<<<NODE_BLKS, 256>>>();
        pass1<<<EDGE_BLKS, 256>>>(src, dst);
        pass2<<<EDGE_BLKS, 256>>>(src, dst);
        finalize_kernel<<<NODE_BLKS, 256>>>();
    }
    out_kernel<<<OUT_BLKS, 256>>>(Wout, bout, out);
}

// round 2
// speedup vs baseline: 1.4159x; 1.4159x over previous
#include <cuda_runtime.h>

// Problem constants (fixed by the dataset)
#define NN   50000
#define EE   600000
#define FD   128
#define EDIM 16
#define HH   4
#define DD   32
#define HIDD 128
#define CC   10

#define NCHUNK 196   // ceil(NN/256)

// ---------------------------------------------------------------------------
// Scratch (device globals; allocation-free per harness rules)
// ---------------------------------------------------------------------------
__device__ __align__(16) float d_qkvs[(size_t)NN * 512];   // q|k|v|skip packed per node
__device__ __align__(16) float d_h[(size_t)NN * 128];      // layer output
__device__ __align__(16) float d_Wp[128 * 512];            // packed [K=128, 4*128]
__device__ __align__(16) float d_bp[512];

// CSR-by-dst (built once per launch, shared by both layers)
__device__ int d_deg[NN];
__device__ int d_start[NN];
__device__ int d_cursor[NN];
__device__ int d_perm[EE];
__device__ int d_csums[256];
__device__ int d_coffs[256];

// ---------------------------------------------------------------------------
// Scan helpers
// ---------------------------------------------------------------------------
__device__ __forceinline__ int warp_incl_scan(int v, int lane) {
#pragma unroll
    for (int o = 1; o < 32; o <<= 1) {
        int n = __shfl_up_sync(0xffffffffu, v, o);
        if (lane >= o) v += n;
    }
    return v;
}

// ---------------------------------------------------------------------------
// CSR build: zero deg -> histogram -> chunk sums -> chunk offsets -> scan -> scatter
// ---------------------------------------------------------------------------
__global__ void zero_deg() {
    int i = blockIdx.x * blockDim.x + threadIdx.x;
    if (i < NN) d_deg[i] = 0;
}

__global__ void hist_kernel(const int* __restrict__ dst) {
    int e = blockIdx.x * blockDim.x + threadIdx.x;
    if (e < EE) atomicAdd(&d_deg[dst[e]], 1);
}

__global__ void chunk_sums() {
    int tid = threadIdx.x, b = blockIdx.x, i = b * 256 + tid;
    int v = (i < NN) ? d_deg[i] : 0;
#pragma unroll
    for (int o = 16; o > 0; o >>= 1) v += __shfl_xor_sync(0xffffffffu, v, o);
    __shared__ int ws[8];
    if ((tid & 31) == 0) ws[tid >> 5] = v;
    __syncthreads();
    if (tid == 0) {
        int s = 0;
#pragma unroll
        for (int k = 0; k < 8; k++) s += ws[k];
        d_csums[b] = s;
    }
}

__global__ void chunk_offsets() {   // single block, 256 threads
    int tid = threadIdx.x;
    int lane = tid & 31, w = tid >> 5;
    __shared__ int ws[8];
    int v = (tid < NCHUNK) ? d_csums[tid] : 0;
    int incl = warp_incl_scan(v, lane);
    if (lane == 31) ws[w] = incl;
    __syncthreads();
    if (w == 0) {
        int t = (lane < 8) ? ws[lane] : 0;
        t = warp_incl_scan(t, lane);
        if (lane < 8) ws[lane] = t;
    }
    __syncthreads();
    int excl = incl - v + (w > 0 ? ws[w - 1] : 0);
    d_coffs[tid] = excl;
}

__global__ void scan_chunks() {
    int tid = threadIdx.x, b = blockIdx.x, i = b * 256 + tid;
    int lane = tid & 31, w = tid >> 5;
    __shared__ int ws[8];
    int v = (i < NN) ? d_deg[i] : 0;
    int incl = warp_incl_scan(v, lane);
    if (lane == 31) ws[w] = incl;
    __syncthreads();
    if (w == 0) {
        int t = (lane < 8) ? ws[lane] : 0;
        t = warp_incl_scan(t, lane);
        if (lane < 8) ws[lane] = t;
    }
    __syncthreads();
    int excl = incl - v + (w > 0 ? ws[w - 1] : 0) + d_coffs[b];
    if (i < NN) { d_start[i] = excl; d_cursor[i] = excl; }
}

__global__ void scatter_perm(const int* __restrict__ dst) {
    int e = blockIdx.x * blockDim.x + threadIdx.x;
    if (e < EE) {
        int pos = atomicAdd(&d_cursor[dst[e]], 1);
        d_perm[pos] = e;
    }
}

// ---------------------------------------------------------------------------
// Pack 4 weight matrices [128,128] into one [128,512] (col blocks q,k,v,s)
// ---------------------------------------------------------------------------
__global__ void pack_kernel(const float* __restrict__ Wq, const float* __restrict__ Wk,
                            const float* __restrict__ Wv, const float* __restrict__ Ws,
                            const float* __restrict__ bq, const float* __restrict__ bk,
                            const float* __restrict__ bv, const float* __restrict__ bs) {
    int idx = blockIdx.x * blockDim.x + threadIdx.x;
    if (idx < 128 * 512) {
        int k = idx >> 9, j = idx & 511;
        int sel = j >> 7, jc = j & 127;
        const float* W = sel == 0 ? Wq : sel == 1 ? Wk : sel == 2 ? Wv : Ws;
        d_Wp[idx] = W[k * 128 + jc];
    }
    if (idx < 512) {
        int sel = idx >> 7, jc = idx & 127;
        const float* b = sel == 0 ? bq : sel == 1 ? bk : sel == 2 ? bv : bs;
        d_bp[idx] = b[jc];
    }
}

// ---------------------------------------------------------------------------
// SGEMM: C[M,512] = A[M,128] @ d_Wp[128,512] + d_bp
// ---------------------------------------------------------------------------
__global__ void __launch_bounds__(256) sgemm_qkvs(const float* __restrict__ x, int layer, int M) {
    const float* A = (layer == 0) ? x : (const float*)d_h;

    __shared__ __align__(16) float As[8][128];
    __shared__ __align__(16) float Bs[8][128];

    int tid = threadIdx.x;
    int bx = blockIdx.x;
    int by = blockIdx.y;
    int trow = tid >> 4;
    int tcol = tid & 15;

    float acc[8][8];
#pragma unroll
    for (int i = 0; i < 8; i++)
#pragma unroll
        for (int j = 0; j < 8; j++) acc[i][j] = 0.0f;

    int aRow = tid >> 1;
    int aCol = (tid & 1) * 4;
    int bRow = tid >> 5;
    int bCol = (tid & 31) * 4;
    int rowBase = by * 128;

    for (int k0 = 0; k0 < 128; k0 += 8) {
        int gr = rowBase + aRow;
        float4 a4 = make_float4(0.f, 0.f, 0.f, 0.f);
        if (gr < M) a4 = *(const float4*)(A + (size_t)gr * 128 + k0 + aCol);
        As[aCol + 0][aRow] = a4.x;
        As[aCol + 1][aRow] = a4.y;
        As[aCol + 2][aRow] = a4.z;
        As[aCol + 3][aRow] = a4.w;

        float4 b4 = *(const float4*)(d_Wp + (k0 + bRow) * 512 + bx * 128 + bCol);
        *(float4*)&Bs[bRow][bCol] = b4;
        __syncthreads();

#pragma unroll
        for (int kk = 0; kk < 8; kk++) {
            float4 a0 = *(const float4*)&As[kk][trow * 8];
            float4 a1 = *(const float4*)&As[kk][trow * 8 + 4];
            float4 b0 = *(const float4*)&Bs[kk][tcol * 8];
            float4 b1 = *(const float4*)&Bs[kk][tcol * 8 + 4];
            float ar[8] = {a0.x, a0.y, a0.z, a0.w, a1.x, a1.y, a1.z, a1.w};
            float br[8] = {b0.x, b0.y, b0.z, b0.w, b1.x, b1.y, b1.z, b1.w};
#pragma unroll
            for (int i = 0; i < 8; i++)
#pragma unroll
                for (int j = 0; j < 8; j++) acc[i][j] += ar[i] * br[j];
        }
        __syncthreads();
    }

    int c = bx * 128 + tcol * 8;
    float4 bias0 = *(const float4*)(d_bp + c);
    float4 bias1 = *(const float4*)(d_bp + c + 4);
#pragma unroll
    for (int i = 0; i < 8; i++) {
        int r = rowBase + trow * 8 + i;
        if (r < M) {
            float4 o0 = make_float4(acc[i][0] + bias0.x, acc[i][1] + bias0.y,
                                    acc[i][2] + bias0.z, acc[i][3] + bias0.w);
            float4 o1 = make_float4(acc[i][4] + bias1.x, acc[i][5] + bias1.y,
                                    acc[i][6] + bias1.z, acc[i][7] + bias1.w);
            *(float4*)(d_qkvs + (size_t)r * 512 + c) = o0;
            *(float4*)(d_qkvs + (size_t)r * 512 + c + 4) = o1;
        }
    }
}

// ---------------------------------------------------------------------------
// Node-centric fused attention. One warp per destination node.
// Recomputes e = edge_attr @ We on the fly with We held in registers
// (each lane owns 4 output columns). Max-free softmax (logits are O(1)),
// register accumulation, fused normalize + skip + relu.
// ---------------------------------------------------------------------------
__global__ void __launch_bounds__(256) attn_node(const int* __restrict__ src,
                                                 const float* __restrict__ eattr,
                                                 const float* __restrict__ We) {
    int warp = (blockIdx.x * 256 + threadIdx.x) >> 5;
    int lane = threadIdx.x & 31;
    if (warp >= NN) return;
    int n = warp;

    // per-lane We columns: wreg[k] = We[k, lane*4 .. lane*4+3]
    float4 wreg[16];
#pragma unroll
    for (int k = 0; k < 16; k++)
        wreg[k] = __ldg((const float4*)(We + k * 128) + lane);

    float4 q4 = *(const float4*)(d_qkvs + (size_t)n * 512 + lane * 4);
    float4 acc = make_float4(0.f, 0.f, 0.f, 0.f);
    float dsum = 0.0f;

    int start = d_start[n];
    int deg = d_deg[n];

    int e_cur = 0, s_cur = 0;
    if (deg > 0) {
        e_cur = __ldg(&d_perm[start]);
        s_cur = __ldg(&src[e_cur]);
    }

    for (int j = 0; j < deg; j++) {
        int e = e_cur, s = s_cur;
        if (j + 1 < deg) {                      // prefetch next edge's src
            e_cur = __ldg(&d_perm[start + j + 1]);
            s_cur = __ldg(&src[e_cur]);
        }

        const float4* ea4 = (const float4*)(eattr + (size_t)e * 16);
        float4 a0 = __ldg(ea4 + 0);
        float4 a1 = __ldg(ea4 + 1);
        float4 a2 = __ldg(ea4 + 2);
        float4 a3 = __ldg(ea4 + 3);
        float ea[16] = {a0.x, a0.y, a0.z, a0.w, a1.x, a1.y, a1.z, a1.w,
                        a2.x, a2.y, a2.z, a2.w, a3.x, a3.y, a3.z, a3.w};

        float4 ev = make_float4(0.f, 0.f, 0.f, 0.f);
#pragma unroll
        for (int k = 0; k < 16; k++) {
            ev.x = fmaf(ea[k], wreg[k].x, ev.x);
            ev.y = fmaf(ea[k], wreg[k].y, ev.y);
            ev.z = fmaf(ea[k], wreg[k].z, ev.z);
            ev.w = fmaf(ea[k], wreg[k].w, ev.w);
        }

        const float* base = d_qkvs + (size_t)s * 512;
        float4 k4 = *(const float4*)(base + 128 + lane * 4);
        float4 v4 = *(const float4*)(base + 256 + lane * 4);

        float t = q4.x * (k4.x + ev.x) + q4.y * (k4.y + ev.y) +
                  q4.z * (k4.z + ev.z) + q4.w * (k4.w + ev.w);
        // reduce within 8-lane head group (head = lane>>3 covers 32 channels)
        t += __shfl_xor_sync(0xffffffffu, t, 1);
        t += __shfl_xor_sync(0xffffffffu, t, 2);
        t += __shfl_xor_sync(0xffffffffu, t, 4);

        float ex = __expf(t * 0.17677669529663687f);   // 1/sqrt(32)
        dsum += ex;
        acc.x = fmaf(v4.x + ev.x, ex, acc.x);
        acc.y = fmaf(v4.y + ev.y, ex, acc.y);
        acc.z = fmaf(v4.z + ev.z, ex, acc.z);
        acc.w = fmaf(v4.w + ev.w, ex, acc.w);
    }

    float inv = 1.0f / (dsum + 1e-16f);
    float4 sk = *(const float4*)(d_qkvs + (size_t)n * 512 + 384 + lane * 4);
    float4 o;
    o.x = fmaxf(fmaf(acc.x, inv, sk.x), 0.0f);
    o.y = fmaxf(fmaf(acc.y, inv, sk.y), 0.0f);
    o.z = fmaxf(fmaf(acc.z, inv, sk.z), 0.0f);
    o.w = fmaxf(fmaf(acc.w, inv, sk.w), 0.0f);
    *(float4*)(d_h + (size_t)n * 128 + lane * 4) = o;
}

// ---------------------------------------------------------------------------
// Output head: logits = h @ Wout + bout; log_softmax. One warp per node.
// ---------------------------------------------------------------------------
__global__ void __launch_bounds__(256) out_kernel(const float* __restrict__ Wout,
                                                  const float* __restrict__ bout,
                                                  float* __restrict__ out) {
    __shared__ float sW[128 * 10];
    __shared__ float sb[10];
    int tid = threadIdx.x;
    for (int i = tid; i < 128 * 10; i += 256) sW[i] = Wout[i];
    if (tid < 10) sb[tid] = bout[tid];
    __syncthreads();

    int warp = (blockIdx.x * 256 + tid) >> 5;
    int lane = tid & 31;
    if (warp >= NN) return;

    float4 hv = *(const float4*)(d_h + (size_t)warp * 128 + lane * 4);
    float lg[10];
#pragma unroll
    for (int c = 0; c < 10; c++) {
        float p = hv.x * sW[(lane * 4 + 0) * 10 + c] +
                  hv.y * sW[(lane * 4 + 1) * 10 + c] +
                  hv.z * sW[(lane * 4 + 2) * 10 + c] +
                  hv.w * sW[(lane * 4 + 3) * 10 + c];
        p += __shfl_xor_sync(0xffffffffu, p, 16);
        p += __shfl_xor_sync(0xffffffffu, p, 8);
        p += __shfl_xor_sync(0xffffffffu, p, 4);
        p += __shfl_xor_sync(0xffffffffu, p, 2);
        p += __shfl_xor_sync(0xffffffffu, p, 1);
        lg[c] = p + sb[c];
    }
    float mx = lg[0];
#pragma unroll
    for (int c = 1; c < 10; c++) mx = fmaxf(mx, lg[c]);
    float ss = 0.0f;
#pragma unroll
    for (int c = 0; c < 10; c++) ss += __expf(lg[c] - mx);
    float lse = mx + logf(ss);
    if (lane == 0) {
#pragma unroll
        for (int c = 0; c < 10; c++)
            out[(size_t)warp * 10 + c] = lg[c] - lse;
    }
}

// ---------------------------------------------------------------------------
// Launch
// ---------------------------------------------------------------------------
extern "C" void kernel_launch(void* const* d_in, const int* in_sizes, int n_in,
                              void* d_out, int out_size) {
    const float* x     = (const float*)d_in[0];
    const int*   ei    = (const int*)d_in[1];
    const float* eattr = (const float*)d_in[2];
    const float* Wout = (const float*)d_in[21];
    const float* bout = (const float*)d_in[22];
    float* out = (float*)d_out;

    const int* src = ei;       // edge_index[0]
    const int* dst = ei + EE;  // edge_index[1]

    const int PACK_BLKS = (128 * 512 + 255) / 256;
    const int EDGE_BLKS = (EE + 255) / 256;
    const int NODE_BLKS = (NN + 255) / 256;
    const int WARP_NODE_BLKS = (NN * 32 + 255) / 256;
    dim3 gemmGrid(4, (NN + 127) / 128);

    // CSR-by-dst (dst identical for both layers) -------------------------
    zero_deg<<<NODE_BLKS, 256>>>();
    hist_kernel<<<EDGE_BLKS, 256>>>(dst);
    chunk_sums<<<NCHUNK, 256>>>();
    chunk_offsets<<<1, 256>>>();
    scan_chunks<<<NCHUNK, 256>>>();
    scatter_perm<<<EDGE_BLKS, 256>>>(dst);

    for (int layer = 0; layer < 2; layer++) {
        int base = 3 + layer * 9;
        const float* Wq = (const float*)d_in[base + 0];
        const float* bq = (const float*)d_in[base + 1];
        const float* Wk = (const float*)d_in[base + 2];
        const float* bk = (const float*)d_in[base + 3];
        const float* Wv = (const float*)d_in[base + 4];
        const float* bv = (const float*)d_in[base + 5];
        const float* We = (const float*)d_in[base + 6];
        const float* Ws = (const float*)d_in[base + 7];
        const float* bs = (const float*)d_in[base + 8];

        pack_kernel<<<PACK_BLKS, 256>>>(Wq, Wk, Wv, Ws, bq, bk, bv, bs);
        sgemm_qkvs<<<gemmGrid, 256>>>(x, layer, NN);
        attn_node<<<WARP_NODE_BLKS, 256>>>(src, eattr, We);
    }
    out_kernel<<<WARP_NODE_BLKS, 256>>>(Wout, bout, out);
}

// round 3
// speedup vs baseline: 1.5603x; 1.1019x over previous
#include <cuda_runtime.h>
#include <cstdint>

// Problem constants (fixed by the dataset)
#define NN   50000
#define EE   600000
#define FD   128
#define EDIM 16
#define HH   4
#define DD   32
#define HIDD 128
#define CC   10

#define NCHUNK 196   // ceil(NN/256)

// ---------------------------------------------------------------------------
// Scratch (device globals; allocation-free per harness rules)
// ---------------------------------------------------------------------------
__device__ __align__(16) float d_qkvs[(size_t)NN * 512];   // q|k|v|skip packed per node
__device__ __align__(16) float d_h[(size_t)NN * 128];      // layer output
__device__ __align__(16) float d_Wp[128 * 512];            // packed [K=128, 4*128]
__device__ __align__(16) float d_bp[512];

// CSR-by-dst (built once per launch, shared by both layers)
__device__ int d_deg[NN];
__device__ int d_start[NN];
__device__ int d_cursor[NN];
__device__ int d_perm[EE];
__device__ int d_csums[256];
__device__ int d_coffs[256];

// ---------------------------------------------------------------------------
// Scan helpers
// ---------------------------------------------------------------------------
__device__ __forceinline__ int warp_incl_scan(int v, int lane) {
#pragma unroll
    for (int o = 1; o < 32; o <<= 1) {
        int n = __shfl_up_sync(0xffffffffu, v, o);
        if (lane >= o) v += n;
    }
    return v;
}

__device__ __forceinline__ uint32_t f2tf32(float f) {
    uint32_t u;
    asm("cvt.rna.tf32.f32 %0, %1;" : "=r"(u) : "f"(f));
    return u;
}

// ---------------------------------------------------------------------------
// CSR build
// ---------------------------------------------------------------------------
__global__ void zero_deg() {
    int i = blockIdx.x * blockDim.x + threadIdx.x;
    if (i < NN) d_deg[i] = 0;
}

__global__ void hist_kernel(const int* __restrict__ dst) {
    int e = blockIdx.x * blockDim.x + threadIdx.x;
    if (e < EE) atomicAdd(&d_deg[dst[e]], 1);
}

__global__ void chunk_sums() {
    int tid = threadIdx.x, b = blockIdx.x, i = b * 256 + tid;
    int v = (i < NN) ? d_deg[i] : 0;
#pragma unroll
    for (int o = 16; o > 0; o >>= 1) v += __shfl_xor_sync(0xffffffffu, v, o);
    __shared__ int ws[8];
    if ((tid & 31) == 0) ws[tid >> 5] = v;
    __syncthreads();
    if (tid == 0) {
        int s = 0;
#pragma unroll
        for (int k = 0; k < 8; k++) s += ws[k];
        d_csums[b] = s;
    }
}

__global__ void chunk_offsets() {   // single block, 256 threads
    int tid = threadIdx.x;
    int lane = tid & 31, w = tid >> 5;
    __shared__ int ws[8];
    int v = (tid < NCHUNK) ? d_csums[tid] : 0;
    int incl = warp_incl_scan(v, lane);
    if (lane == 31) ws[w] = incl;
    __syncthreads();
    if (w == 0) {
        int t = (lane < 8) ? ws[lane] : 0;
        t = warp_incl_scan(t, lane);
        if (lane < 8) ws[lane] = t;
    }
    __syncthreads();
    int excl = incl - v + (w > 0 ? ws[w - 1] : 0);
    d_coffs[tid] = excl;
}

__global__ void scan_chunks() {
    int tid = threadIdx.x, b = blockIdx.x, i = b * 256 + tid;
    int lane = tid & 31, w = tid >> 5;
    __shared__ int ws[8];
    int v = (i < NN) ? d_deg[i] : 0;
    int incl = warp_incl_scan(v, lane);
    if (lane == 31) ws[w] = incl;
    __syncthreads();
    if (w == 0) {
        int t = (lane < 8) ? ws[lane] : 0;
        t = warp_incl_scan(t, lane);
        if (lane < 8) ws[lane] = t;
    }
    __syncthreads();
    int excl = incl - v + (w > 0 ? ws[w - 1] : 0) + d_coffs[b];
    if (i < NN) { d_start[i] = excl; d_cursor[i] = excl; }
}

__global__ void scatter_perm(const int* __restrict__ dst) {
    int e = blockIdx.x * blockDim.x + threadIdx.x;
    if (e < EE) {
        int pos = atomicAdd(&d_cursor[dst[e]], 1);
        d_perm[pos] = e;
    }
}

// ---------------------------------------------------------------------------
// Pack 4 weight matrices [128,128] into one [128,512] (col blocks q,k,v,s)
// ---------------------------------------------------------------------------
__global__ void pack_kernel(const float* __restrict__ Wq, const float* __restrict__ Wk,
                            const float* __restrict__ Wv, const float* __restrict__ Ws,
                            const float* __restrict__ bq, const float* __restrict__ bk,
                            const float* __restrict__ bv, const float* __restrict__ bs) {
    int idx = blockIdx.x * blockDim.x + threadIdx.x;
    if (idx < 128 * 512) {
        int k = idx >> 9, j = idx & 511;
        int sel = j >> 7, jc = j & 127;
        const float* W = sel == 0 ? Wq : sel == 1 ? Wk : sel == 2 ? Wv : Ws;
        d_Wp[idx] = W[k * 128 + jc];
    }
    if (idx < 512) {
        int sel = idx >> 7, jc = idx & 127;
        const float* b = sel == 0 ? bq : sel == 1 ? bk : sel == 2 ? bv : bs;
        d_bp[idx] = b[jc];
    }
}

// ---------------------------------------------------------------------------
// 3xTF32 tensor-core GEMM: C[M,512] = A[M,128] @ d_Wp[128,512] + d_bp
// 128x128 block tile, 8 warps (2x4), warp tile 64x32, mma m16n8k8 tf32.
// a = a_hi + a_lo; C += a_hi*b_hi + a_hi*b_lo + a_lo*b_hi  (~fp32 accuracy)
// ---------------------------------------------------------------------------
#define KC 16   // K chunk staged in smem

__global__ void __launch_bounds__(256) sgemm_tf32(const float* __restrict__ x,
                                                  int layer, int M) {
    const float* A = (layer == 0) ? x : (const float*)d_h;

    // padded layouts: As row stride 20 (bank (4r+k)%32 distinct), Bs row stride 132
    __shared__ uint32_t AsH[128][20];
    __shared__ uint32_t AsL[128][20];
    __shared__ uint32_t BsH[KC][132];
    __shared__ uint32_t BsL[KC][132];

    int tid = threadIdx.x;
    int bx = blockIdx.x;               // 0..3
    int by = blockIdx.y;               // 0..390
    int warp = tid >> 5, lane = tid & 31;
    int wm = warp >> 2, wn = warp & 3; // 2 x 4 warp grid
    int mbase = wm * 64, nbase = wn * 32;
    int rowBase = by * 128;
    int g = lane >> 2;                 // groupID
    int tg = lane & 3;                 // thread-in-group

    float c[4][4][4];
#pragma unroll
    for (int i = 0; i < 4; i++)
#pragma unroll
        for (int j = 0; j < 4; j++)
#pragma unroll
            for (int r = 0; r < 4; r++) c[i][j][r] = 0.0f;

    for (int k0 = 0; k0 < 128; k0 += KC) {
        // stage A chunk: 128 x 16 floats = 512 float4; 256 threads x 2
#pragma unroll
        for (int p = 0; p < 2; p++) {
            int idx4 = tid + 256 * p;
            int r = idx4 >> 2, cc = (idx4 & 3) * 4;
            int gr = rowBase + r;
            float4 v = (gr < M) ? *(const float4*)(A + (size_t)gr * 128 + k0 + cc)
                                : make_float4(0.f, 0.f, 0.f, 0.f);
            uint32_t hx = f2tf32(v.x), hy = f2tf32(v.y), hz = f2tf32(v.z), hw = f2tf32(v.w);
            AsH[r][cc + 0] = hx; AsH[r][cc + 1] = hy; AsH[r][cc + 2] = hz; AsH[r][cc + 3] = hw;
            AsL[r][cc + 0] = f2tf32(v.x - __uint_as_float(hx));
            AsL[r][cc + 1] = f2tf32(v.y - __uint_as_float(hy));
            AsL[r][cc + 2] = f2tf32(v.z - __uint_as_float(hz));
            AsL[r][cc + 3] = f2tf32(v.w - __uint_as_float(hw));
        }
        // stage B chunk: 16 x 128 floats = 512 float4; 256 threads x 2
#pragma unroll
        for (int p = 0; p < 2; p++) {
            int idx4 = tid + 256 * p;
            int r = idx4 >> 5, cc = (idx4 & 31) * 4;
            float4 v = *(const float4*)(d_Wp + (k0 + r) * 512 + bx * 128 + cc);
            uint32_t hx = f2tf32(v.x), hy = f2tf32(v.y), hz = f2tf32(v.z), hw = f2tf32(v.w);
            BsH[r][cc + 0] = hx; BsH[r][cc + 1] = hy; BsH[r][cc + 2] = hz; BsH[r][cc + 3] = hw;
            BsL[r][cc + 0] = f2tf32(v.x - __uint_as_float(hx));
            BsL[r][cc + 1] = f2tf32(v.y - __uint_as_float(hy));
            BsL[r][cc + 2] = f2tf32(v.z - __uint_as_float(hz));
            BsL[r][cc + 3] = f2tf32(v.w - __uint_as_float(hw));
        }
        __syncthreads();

#pragma unroll
        for (int ks = 0; ks < KC / 8; ks++) {
            int kq = ks * 8;
            // B fragments for this k-step (4 n-tiles), hi and lo
            uint32_t bh[4][2], bl[4][2];
#pragma unroll
            for (int nt = 0; nt < 4; nt++) {
                int nn = nbase + nt * 8 + g;
                bh[nt][0] = BsH[kq + tg][nn];     bh[nt][1] = BsH[kq + 4 + tg][nn];
                bl[nt][0] = BsL[kq + tg][nn];     bl[nt][1] = BsL[kq + 4 + tg][nn];
            }
#pragma unroll
            for (int mt = 0; mt < 4; mt++) {
                int r = mbase + mt * 16 + g;
                int kk = kq + tg;
                uint32_t ah[4], al[4];
                ah[0] = AsH[r][kk];     ah[1] = AsH[r + 8][kk];
                ah[2] = AsH[r][kk + 4]; ah[3] = AsH[r + 8][kk + 4];
                al[0] = AsL[r][kk];     al[1] = AsL[r + 8][kk];
                al[2] = AsL[r][kk + 4]; al[3] = AsL[r + 8][kk + 4];
#pragma unroll
                for (int nt = 0; nt < 4; nt++) {
                    float* cc = c[mt][nt];
                    asm volatile(
                        "mma.sync.aligned.m16n8k8.row.col.f32.tf32.tf32.f32 "
                        "{%0,%1,%2,%3},{%4,%5,%6,%7},{%8,%9},{%0,%1,%2,%3};"
                        : "+f"(cc[0]), "+f"(cc[1]), "+f"(cc[2]), "+f"(cc[3])
                        : "r"(ah[0]), "r"(ah[1]), "r"(ah[2]), "r"(ah[3]),
                          "r"(bh[nt][0]), "r"(bh[nt][1]));
                    asm volatile(
                        "mma.sync.aligned.m16n8k8.row.col.f32.tf32.tf32.f32 "
                        "{%0,%1,%2,%3},{%4,%5,%6,%7},{%8,%9},{%0,%1,%2,%3};"
                        : "+f"(cc[0]), "+f"(cc[1]), "+f"(cc[2]), "+f"(cc[3])
                        : "r"(ah[0]), "r"(ah[1]), "r"(ah[2]), "r"(ah[3]),
                          "r"(bl[nt][0]), "r"(bl[nt][1]));
                    asm volatile(
                        "mma.sync.aligned.m16n8k8.row.col.f32.tf32.tf32.f32 "
                        "{%0,%1,%2,%3},{%4,%5,%6,%7},{%8,%9},{%0,%1,%2,%3};"
                        : "+f"(cc[0]), "+f"(cc[1]), "+f"(cc[2]), "+f"(cc[3])
                        : "r"(al[0]), "r"(al[1]), "r"(al[2]), "r"(al[3]),
                          "r"(bh[nt][0]), "r"(bh[nt][1]));
                }
            }
        }
        __syncthreads();
    }

    // epilogue: bias add, write to d_qkvs
#pragma unroll
    for (int mt = 0; mt < 4; mt++) {
        int r0 = rowBase + mbase + mt * 16 + g;
        int r1 = r0 + 8;
#pragma unroll
        for (int nt = 0; nt < 4; nt++) {
            int col = bx * 128 + nbase + nt * 8 + 2 * tg;
            float2 b2 = *(const float2*)(d_bp + col);
            if (r0 < M) {
                float2 o = make_float2(c[mt][nt][0] + b2.x, c[mt][nt][1] + b2.y);
                *(float2*)(d_qkvs + (size_t)r0 * 512 + col) = o;
            }
            if (r1 < M) {
                float2 o = make_float2(c[mt][nt][2] + b2.x, c[mt][nt][3] + b2.y);
                *(float2*)(d_qkvs + (size_t)r1 * 512 + col) = o;
            }
        }
    }
}

// ---------------------------------------------------------------------------
// Node-centric fused attention. One warp per destination node.
// ---------------------------------------------------------------------------
__global__ void __launch_bounds__(256) attn_node(const int* __restrict__ src,
                                                 const float* __restrict__ eattr,
                                                 const float* __restrict__ We) {
    int warp = (blockIdx.x * 256 + threadIdx.x) >> 5;
    int lane = threadIdx.x & 31;
    if (warp >= NN) return;
    int n = warp;

    float4 wreg[16];
#pragma unroll
    for (int k = 0; k < 16; k++)
        wreg[k] = __ldg((const float4*)(We + k * 128) + lane);

    float4 q4 = *(const float4*)(d_qkvs + (size_t)n * 512 + lane * 4);
    float4 acc = make_float4(0.f, 0.f, 0.f, 0.f);
    float dsum = 0.0f;

    int start = d_start[n];
    int deg = d_deg[n];

    int e_cur = 0, s_cur = 0;
    if (deg > 0) {
        e_cur = __ldg(&d_perm[start]);
        s_cur = __ldg(&src[e_cur]);
    }

    for (int j = 0; j < deg; j++) {
        int e = e_cur, s = s_cur;
        if (j + 1 < deg) {
            e_cur = __ldg(&d_perm[start + j + 1]);
            s_cur = __ldg(&src[e_cur]);
        }

        const float4* ea4 = (const float4*)(eattr + (size_t)e * 16);
        float4 a0 = __ldg(ea4 + 0);
        float4 a1 = __ldg(ea4 + 1);
        float4 a2 = __ldg(ea4 + 2);
        float4 a3 = __ldg(ea4 + 3);
        float ea[16] = {a0.x, a0.y, a0.z, a0.w, a1.x, a1.y, a1.z, a1.w,
                        a2.x, a2.y, a2.z, a2.w, a3.x, a3.y, a3.z, a3.w};

        float4 ev = make_float4(0.f, 0.f, 0.f, 0.f);
#pragma unroll
        for (int k = 0; k < 16; k++) {
            ev.x = fmaf(ea[k], wreg[k].x, ev.x);
            ev.y = fmaf(ea[k], wreg[k].y, ev.y);
            ev.z = fmaf(ea[k], wreg[k].z, ev.z);
            ev.w = fmaf(ea[k], wreg[k].w, ev.w);
        }

        const float* base = d_qkvs + (size_t)s * 512;
        float4 k4 = *(const float4*)(base + 128 + lane * 4);
        float4 v4 = *(const float4*)(base + 256 + lane * 4);

        float t = q4.x * (k4.x + ev.x) + q4.y * (k4.y + ev.y) +
                  q4.z * (k4.z + ev.z) + q4.w * (k4.w + ev.w);
        t += __shfl_xor_sync(0xffffffffu, t, 1);
        t += __shfl_xor_sync(0xffffffffu, t, 2);
        t += __shfl_xor_sync(0xffffffffu, t, 4);

        float ex = __expf(t * 0.17677669529663687f);   // 1/sqrt(32)
        dsum += ex;
        acc.x = fmaf(v4.x + ev.x, ex, acc.x);
        acc.y = fmaf(v4.y + ev.y, ex, acc.y);
        acc.z = fmaf(v4.z + ev.z, ex, acc.z);
        acc.w = fmaf(v4.w + ev.w, ex, acc.w);
    }

    float inv = 1.0f / (dsum + 1e-16f);
    float4 sk = *(const float4*)(d_qkvs + (size_t)n * 512 + 384 + lane * 4);
    float4 o;
    o.x = fmaxf(fmaf(acc.x, inv, sk.x), 0.0f);
    o.y = fmaxf(fmaf(acc.y, inv, sk.y), 0.0f);
    o.z = fmaxf(fmaf(acc.z, inv, sk.z), 0.0f);
    o.w = fmaxf(fmaf(acc.w, inv, sk.w), 0.0f);
    *(float4*)(d_h + (size_t)n * 128 + lane * 4) = o;
}

// ---------------------------------------------------------------------------
// Output head: logits = h @ Wout + bout; log_softmax. One warp per node.
// ---------------------------------------------------------------------------
__global__ void __launch_bounds__(256) out_kernel(const float* __restrict__ Wout,
                                                  const float* __restrict__ bout,
                                                  float* __restrict__ out) {
    __shared__ float sW[128 * 10];
    __shared__ float sb[10];
    int tid = threadIdx.x;
    for (int i = tid; i < 128 * 10; i += 256) sW[i] = Wout[i];
    if (tid < 10) sb[tid] = bout[tid];
    __syncthreads();

    int warp = (blockIdx.x * 256 + tid) >> 5;
    int lane = tid & 31;
    if (warp >= NN) return;

    float4 hv = *(const float4*)(d_h + (size_t)warp * 128 + lane * 4);
    float lg[10];
#pragma unroll
    for (int c = 0; c < 10; c++) {
        float p = hv.x * sW[(lane * 4 + 0) * 10 + c] +
                  hv.y * sW[(lane * 4 + 1) * 10 + c] +
                  hv.z * sW[(lane * 4 + 2) * 10 + c] +
                  hv.w * sW[(lane * 4 + 3) * 10 + c];
        p += __shfl_xor_sync(0xffffffffu, p, 16);
        p += __shfl_xor_sync(0xffffffffu, p, 8);
        p += __shfl_xor_sync(0xffffffffu, p, 4);
        p += __shfl_xor_sync(0xffffffffu, p, 2);
        p += __shfl_xor_sync(0xffffffffu, p, 1);
        lg[c] = p + sb[c];
    }
    float mx = lg[0];
#pragma unroll
    for (int c = 1; c < 10; c++) mx = fmaxf(mx, lg[c]);
    float ss = 0.0f;
#pragma unroll
    for (int c = 0; c < 10; c++) ss += __expf(lg[c] - mx);
    float lse = mx + logf(ss);
    if (lane == 0) {
#pragma unroll
        for (int c = 0; c < 10; c++)
            out[(size_t)warp * 10 + c] = lg[c] - lse;
    }
}

// ---------------------------------------------------------------------------
// Launch
// ---------------------------------------------------------------------------
extern "C" void kernel_launch(void* const* d_in, const int* in_sizes, int n_in,
                              void* d_out, int out_size) {
    const float* x     = (const float*)d_in[0];
    const int*   ei    = (const int*)d_in[1];
    const float* eattr = (const float*)d_in[2];
    const float* Wout = (const float*)d_in[21];
    const float* bout = (const float*)d_in[22];
    float* out = (float*)d_out;

    const int* src = ei;       // edge_index[0]
    const int* dst = ei + EE;  // edge_index[1]

    const int PACK_BLKS = (128 * 512 + 255) / 256;
    const int EDGE_BLKS = (EE + 255) / 256;
    const int NODE_BLKS = (NN + 255) / 256;
    const int WARP_NODE_BLKS = (NN * 32 + 255) / 256;
    dim3 gemmGrid(4, (NN + 127) / 128);

    // CSR-by-dst (dst identical for both layers) -------------------------
    zero_deg<<<NODE_BLKS, 256>>>();
    hist_kernel<<<EDGE_BLKS, 256>>>(dst);
    chunk_sums<<<NCHUNK, 256>>>();
    chunk_offsets<<<1, 256>>>();
    scan_chunks<<<NCHUNK, 256>>>();
    scatter_perm<<<EDGE_BLKS, 256>>>(dst);

    for (int layer = 0; layer < 2; layer++) {
        int base = 3 + layer * 9;
        const float* Wq = (const float*)d_in[base + 0];
        const float* bq = (const float*)d_in[base + 1];
        const float* Wk = (const float*)d_in[base + 2];
        const float* bk = (const float*)d_in[base + 3];
        const float* Wv = (const float*)d_in[base + 4];
        const float* bv = (const float*)d_in[base + 5];
        const float* We = (const float*)d_in[base + 6];
        const float* Ws = (const float*)d_in[base + 7];
        const float* bs = (const float*)d_in[base + 8];

        pack_kernel<<<PACK_BLKS, 256>>>(Wq, Wk, Wv, Ws, bq, bk, bv, bs);
        sgemm_tf32<<<gemmGrid, 256>>>(x, layer, NN);
        attn_node<<<WARP_NODE_BLKS, 256>>>(src, eattr, We);
    }
    out_kernel<<<WARP_NODE_BLKS, 256>>>(Wout, bout, out);
}

// round 5
// speedup vs baseline: 1.6102x; 1.0320x over previous
#include <cuda_runtime.h>
#include <cstdint>

// Problem constants (fixed by the dataset)
#define NN   50000
#define EE   600000
#define FD   128
#define EDIM 16
#define HH   4
#define DD   32
#define HIDD 128
#define CC   10

#define NCHUNK 196   // ceil(NN/256)

// ---------------------------------------------------------------------------
// Scratch (device globals; allocation-free per harness rules)
// ---------------------------------------------------------------------------
__device__ __align__(16) float d_qkvs[(size_t)NN * 512];   // q|k|v|skip packed per node
__device__ __align__(16) float d_h[(size_t)NN * 128];      // layer output
__device__ __align__(16) float d_Wp[128 * 512];            // packed [K=128, 4*128]
__device__ __align__(16) float d_bp[512];

// CSR-by-dst (built once per launch, shared by both layers)
__device__ int d_deg[NN];
__device__ int d_start[NN];
__device__ int d_cursor[NN];
__device__ int d_perm[EE];
__device__ int d_csums[256];
__device__ int d_coffs[256];

// ---------------------------------------------------------------------------
// Scan helpers
// ---------------------------------------------------------------------------
__device__ __forceinline__ int warp_incl_scan(int v, int lane) {
#pragma unroll
    for (int o = 1; o < 32; o <<= 1) {
        int n = __shfl_up_sync(0xffffffffu, v, o);
        if (lane >= o) v += n;
    }
    return v;
}

__device__ __forceinline__ uint32_t f2tf32(float f) {
    uint32_t u;
    asm("cvt.rna.tf32.f32 %0, %1;" : "=r"(u) : "f"(f));
    return u;
}

// ---------------------------------------------------------------------------
// CSR build
// ---------------------------------------------------------------------------
__global__ void zero_deg() {
    int i = blockIdx.x * blockDim.x + threadIdx.x;
    if (i < NN) d_deg[i] = 0;
}

__global__ void hist_kernel(const int* __restrict__ dst) {
    int e = blockIdx.x * blockDim.x + threadIdx.x;
    if (e < EE) atomicAdd(&d_deg[dst[e]], 1);
}

__global__ void chunk_sums() {
    int tid = threadIdx.x, b = blockIdx.x, i = b * 256 + tid;
    int v = (i < NN) ? d_deg[i] : 0;
#pragma unroll
    for (int o = 16; o > 0; o >>= 1) v += __shfl_xor_sync(0xffffffffu, v, o);
    __shared__ int ws[8];
    if ((tid & 31) == 0) ws[tid >> 5] = v;
    __syncthreads();
    if (tid == 0) {
        int s = 0;
#pragma unroll
        for (int k = 0; k < 8; k++) s += ws[k];
        d_csums[b] = s;
    }
}

__global__ void chunk_offsets() {   // single block, 256 threads
    int tid = threadIdx.x;
    int lane = tid & 31, w = tid >> 5;
    __shared__ int ws[8];
    int v = (tid < NCHUNK) ? d_csums[tid] : 0;
    int incl = warp_incl_scan(v, lane);
    if (lane == 31) ws[w] = incl;
    __syncthreads();
    if (w == 0) {
        int t = (lane < 8) ? ws[lane] : 0;
        t = warp_incl_scan(t, lane);
        if (lane < 8) ws[lane] = t;
    }
    __syncthreads();
    int excl = incl - v + (w > 0 ? ws[w - 1] : 0);
    d_coffs[tid] = excl;
}

__global__ void scan_chunks() {
    int tid = threadIdx.x, b = blockIdx.x, i = b * 256 + tid;
    int lane = tid & 31, w = tid >> 5;
    __shared__ int ws[8];
    int v = (i < NN) ? d_deg[i] : 0;
    int incl = warp_incl_scan(v, lane);
    if (lane == 31) ws[w] = incl;
    __syncthreads();
    if (w == 0) {
        int t = (lane < 8) ? ws[lane] : 0;
        t = warp_incl_scan(t, lane);
        if (lane < 8) ws[lane] = t;
    }
    __syncthreads();
    int excl = incl - v + (w > 0 ? ws[w - 1] : 0) + d_coffs[b];
    if (i < NN) { d_start[i] = excl; d_cursor[i] = excl; }
}

__global__ void scatter_perm(const int* __restrict__ dst) {
    int e = blockIdx.x * blockDim.x + threadIdx.x;
    if (e < EE) {
        int pos = atomicAdd(&d_cursor[dst[e]], 1);
        d_perm[pos] = e;
    }
}

// ---------------------------------------------------------------------------
// Pack 4 weight matrices [128,128] into one [128,512] (col blocks q,k,v,s)
// ---------------------------------------------------------------------------
__global__ void pack_kernel(const float* __restrict__ Wq, const float* __restrict__ Wk,
                            const float* __restrict__ Wv, const float* __restrict__ Ws,
                            const float* __restrict__ bq, const float* __restrict__ bk,
                            const float* __restrict__ bv, const float* __restrict__ bs) {
    int idx = blockIdx.x * blockDim.x + threadIdx.x;
    if (idx < 128 * 512) {
        int k = idx >> 9, j = idx & 511;
        int sel = j >> 7, jc = j & 127;
        const float* W = sel == 0 ? Wq : sel == 1 ? Wk : sel == 2 ? Wv : Ws;
        d_Wp[idx] = W[k * 128 + jc];
    }
    if (idx < 512) {
        int sel = idx >> 7, jc = idx & 127;
        const float* b = sel == 0 ? bq : sel == 1 ? bk : sel == 2 ? bv : bs;
        d_bp[idx] = b[jc];
    }
}

// ---------------------------------------------------------------------------
// 3xTF32 tensor-core GEMM, double-buffered (KC=8, 41.5KB smem — fits 48KB).
// C[M,512] = A[M,128] @ d_Wp[128,512] + d_bp
// 128x128 block tile, 8 warps (2x4), warp tile 64x32, mma m16n8k8 tf32.
// ---------------------------------------------------------------------------
#define KC 8   // K chunk staged in smem (= one k8 mma step)

__global__ void __launch_bounds__(256) sgemm_tf32(const float* __restrict__ x,
                                                  int layer, int M) {
    const float* A = (layer == 0) ? x : (const float*)d_h;

    __shared__ uint32_t AsH[2][128][12];   // stride 12: conflict-free
    __shared__ uint32_t AsL[2][128][12];
    __shared__ uint32_t BsH[2][KC][132];
    __shared__ uint32_t BsL[2][KC][132];

    int tid = threadIdx.x;
    int bx = blockIdx.x;               // 0..3
    int by = blockIdx.y;
    int warp = tid >> 5, lane = tid & 31;
    int wm = warp >> 2, wn = warp & 3; // 2 x 4 warp grid
    int mbase = wm * 64, nbase = wn * 32;
    int rowBase = by * 128;
    int g = lane >> 2;                 // groupID
    int tg = lane & 3;                 // thread-in-group

    // staging coordinates: each thread owns 1 float4 of A, 1 float4 of B
    int aR = tid >> 1, aC = (tid & 1) * 4;       // 128 rows x 8 cols
    int bR = tid >> 5, bC = (tid & 31) * 4;      // 8 rows x 128 cols

    float c[4][4][4];
#pragma unroll
    for (int i = 0; i < 4; i++)
#pragma unroll
        for (int j = 0; j < 4; j++)
#pragma unroll
            for (int r = 0; r < 4; r++) c[i][j][r] = 0.0f;

    float4 aReg, bReg;
    int grA = rowBase + aR;
    bool aOK = (grA < M);

    auto loadChunk = [&](int k0) {
        aReg = aOK ? *(const float4*)(A + (size_t)grA * 128 + k0 + aC)
                   : make_float4(0.f, 0.f, 0.f, 0.f);
        bReg = *(const float4*)(d_Wp + (k0 + bR) * 512 + bx * 128 + bC);
    };

    auto storeChunk = [&](int st) {
        uint32_t hx = f2tf32(aReg.x), hy = f2tf32(aReg.y),
                 hz = f2tf32(aReg.z), hw = f2tf32(aReg.w);
        AsH[st][aR][aC + 0] = hx; AsH[st][aR][aC + 1] = hy;
        AsH[st][aR][aC + 2] = hz; AsH[st][aR][aC + 3] = hw;
        AsL[st][aR][aC + 0] = f2tf32(aReg.x - __uint_as_float(hx));
        AsL[st][aR][aC + 1] = f2tf32(aReg.y - __uint_as_float(hy));
        AsL[st][aR][aC + 2] = f2tf32(aReg.z - __uint_as_float(hz));
        AsL[st][aR][aC + 3] = f2tf32(aReg.w - __uint_as_float(hw));

        uint32_t gx = f2tf32(bReg.x), gy = f2tf32(bReg.y),
                 gz = f2tf32(bReg.z), gw = f2tf32(bReg.w);
        BsH[st][bR][bC + 0] = gx; BsH[st][bR][bC + 1] = gy;
        BsH[st][bR][bC + 2] = gz; BsH[st][bR][bC + 3] = gw;
        BsL[st][bR][bC + 0] = f2tf32(bReg.x - __uint_as_float(gx));
        BsL[st][bR][bC + 1] = f2tf32(bReg.y - __uint_as_float(gy));
        BsL[st][bR][bC + 2] = f2tf32(bReg.z - __uint_as_float(gz));
        BsL[st][bR][bC + 3] = f2tf32(bReg.w - __uint_as_float(gw));
    };

    auto computeChunk = [&](int st) {
        uint32_t bh[4][2], bl[4][2];
#pragma unroll
        for (int nt = 0; nt < 4; nt++) {
            int nn = nbase + nt * 8 + g;
            bh[nt][0] = BsH[st][tg][nn];     bh[nt][1] = BsH[st][4 + tg][nn];
            bl[nt][0] = BsL[st][tg][nn];     bl[nt][1] = BsL[st][4 + tg][nn];
        }
#pragma unroll
        for (int mt = 0; mt < 4; mt++) {
            int r = mbase + mt * 16 + g;
            uint32_t ah[4], al[4];
            ah[0] = AsH[st][r][tg];     ah[1] = AsH[st][r + 8][tg];
            ah[2] = AsH[st][r][tg + 4]; ah[3] = AsH[st][r + 8][tg + 4];
            al[0] = AsL[st][r][tg];     al[1] = AsL[st][r + 8][tg];
            al[2] = AsL[st][r][tg + 4]; al[3] = AsL[st][r + 8][tg + 4];
#pragma unroll
            for (int nt = 0; nt < 4; nt++) {
                float* cc = c[mt][nt];
                asm volatile(
                    "mma.sync.aligned.m16n8k8.row.col.f32.tf32.tf32.f32 "
                    "{%0,%1,%2,%3},{%4,%5,%6,%7},{%8,%9},{%0,%1,%2,%3};"
                    : "+f"(cc[0]), "+f"(cc[1]), "+f"(cc[2]), "+f"(cc[3])
                    : "r"(ah[0]), "r"(ah[1]), "r"(ah[2]), "r"(ah[3]),
                      "r"(bh[nt][0]), "r"(bh[nt][1]));
                asm volatile(
                    "mma.sync.aligned.m16n8k8.row.col.f32.tf32.tf32.f32 "
                    "{%0,%1,%2,%3},{%4,%5,%6,%7},{%8,%9},{%0,%1,%2,%3};"
                    : "+f"(cc[0]), "+f"(cc[1]), "+f"(cc[2]), "+f"(cc[3])
                    : "r"(ah[0]), "r"(ah[1]), "r"(ah[2]), "r"(ah[3]),
                      "r"(bl[nt][0]), "r"(bl[nt][1]));
                asm volatile(
                    "mma.sync.aligned.m16n8k8.row.col.f32.tf32.tf32.f32 "
                    "{%0,%1,%2,%3},{%4,%5,%6,%7},{%8,%9},{%0,%1,%2,%3};"
                    : "+f"(cc[0]), "+f"(cc[1]), "+f"(cc[2]), "+f"(cc[3])
                    : "r"(al[0]), "r"(al[1]), "r"(al[2]), "r"(al[3]),
                      "r"(bh[nt][0]), "r"(bh[nt][1]));
            }
        }
    };

    // ---- pipelined mainloop: 1 sync per chunk, 16 chunks ----
    loadChunk(0);
    storeChunk(0);
    __syncthreads();
#pragma unroll
    for (int ch = 0; ch < 16; ch++) {
        int cur = ch & 1;
        if (ch < 15) loadChunk((ch + 1) * KC);   // global prefetch overlaps compute
        computeChunk(cur);
        if (ch < 15) {
            storeChunk(cur ^ 1);
            __syncthreads();
        }
    }

    // epilogue: bias add, write to d_qkvs
#pragma unroll
    for (int mt = 0; mt < 4; mt++) {
        int r0 = rowBase + mbase + mt * 16 + g;
        int r1 = r0 + 8;
#pragma unroll
        for (int nt = 0; nt < 4; nt++) {
            int col = bx * 128 + nbase + nt * 8 + 2 * tg;
            float2 b2 = *(const float2*)(d_bp + col);
            if (r0 < M) {
                float2 o = make_float2(c[mt][nt][0] + b2.x, c[mt][nt][1] + b2.y);
                *(float2*)(d_qkvs + (size_t)r0 * 512 + col) = o;
            }
            if (r1 < M) {
                float2 o = make_float2(c[mt][nt][2] + b2.x, c[mt][nt][3] + b2.y);
                *(float2*)(d_qkvs + (size_t)r1 * 512 + col) = o;
            }
        }
    }
}

// ---------------------------------------------------------------------------
// Node-centric fused attention, 2-wide edge unroll for MLP.
// One warp per destination node.
// ---------------------------------------------------------------------------
__global__ void __launch_bounds__(256) attn_node(const int* __restrict__ src,
                                                 const float* __restrict__ eattr,
                                                 const float* __restrict__ We) {
    int warp = (blockIdx.x * 256 + threadIdx.x) >> 5;
    int lane = threadIdx.x & 31;
    if (warp >= NN) return;
    int n = warp;

    float4 wreg[16];
#pragma unroll
    for (int k = 0; k < 16; k++)
        wreg[k] = __ldg((const float4*)(We + k * 128) + lane);

    float4 q4 = *(const float4*)(d_qkvs + (size_t)n * 512 + lane * 4);
    float4 acc = make_float4(0.f, 0.f, 0.f, 0.f);
    float dsum = 0.0f;

    int start = d_start[n];
    int deg = d_deg[n];

    int j = 0;
    for (; j + 1 < deg; j += 2) {
        int e0 = __ldg(&d_perm[start + j]);
        int e1 = __ldg(&d_perm[start + j + 1]);
        int s0 = __ldg(&src[e0]);
        int s1 = __ldg(&src[e1]);

        const float4* ea40 = (const float4*)(eattr + (size_t)e0 * 16);
        const float4* ea41 = (const float4*)(eattr + (size_t)e1 * 16);
        float4 p00 = __ldg(ea40 + 0), p01 = __ldg(ea40 + 1),
               p02 = __ldg(ea40 + 2), p03 = __ldg(ea40 + 3);
        float4 p10 = __ldg(ea41 + 0), p11 = __ldg(ea41 + 1),
               p12 = __ldg(ea41 + 2), p13 = __ldg(ea41 + 3);

        const float* base0 = d_qkvs + (size_t)s0 * 512;
        const float* base1 = d_qkvs + (size_t)s1 * 512;
        float4 k40 = *(const float4*)(base0 + 128 + lane * 4);
        float4 v40 = *(const float4*)(base0 + 256 + lane * 4);
        float4 k41 = *(const float4*)(base1 + 128 + lane * 4);
        float4 v41 = *(const float4*)(base1 + 256 + lane * 4);

        float ea0[16] = {p00.x, p00.y, p00.z, p00.w, p01.x, p01.y, p01.z, p01.w,
                         p02.x, p02.y, p02.z, p02.w, p03.x, p03.y, p03.z, p03.w};
        float ea1[16] = {p10.x, p10.y, p10.z, p10.w, p11.x, p11.y, p11.z, p11.w,
                         p12.x, p12.y, p12.z, p12.w, p13.x, p13.y, p13.z, p13.w};

        float4 ev0 = make_float4(0.f, 0.f, 0.f, 0.f);
        float4 ev1 = make_float4(0.f, 0.f, 0.f, 0.f);
#pragma unroll
        for (int k = 0; k < 16; k++) {
            ev0.x = fmaf(ea0[k], wreg[k].x, ev0.x);
            ev0.y = fmaf(ea0[k], wreg[k].y, ev0.y);
            ev0.z = fmaf(ea0[k], wreg[k].z, ev0.z);
            ev0.w = fmaf(ea0[k], wreg[k].w, ev0.w);
            ev1.x = fmaf(ea1[k], wreg[k].x, ev1.x);
            ev1.y = fmaf(ea1[k], wreg[k].y, ev1.y);
            ev1.z = fmaf(ea1[k], wreg[k].z, ev1.z);
            ev1.w = fmaf(ea1[k], wreg[k].w, ev1.w);
        }

        float t0 = q4.x * (k40.x + ev0.x) + q4.y * (k40.y + ev0.y) +
                   q4.z * (k40.z + ev0.z) + q4.w * (k40.w + ev0.w);
        float t1 = q4.x * (k41.x + ev1.x) + q4.y * (k41.y + ev1.y) +
                   q4.z * (k41.z + ev1.z) + q4.w * (k41.w + ev1.w);
        t0 += __shfl_xor_sync(0xffffffffu, t0, 1);
        t1 += __shfl_xor_sync(0xffffffffu, t1, 1);
        t0 += __shfl_xor_sync(0xffffffffu, t0, 2);
        t1 += __shfl_xor_sync(0xffffffffu, t1, 2);
        t0 += __shfl_xor_sync(0xffffffffu, t0, 4);
        t1 += __shfl_xor_sync(0xffffffffu, t1, 4);

        float ex0 = __expf(t0 * 0.17677669529663687f);
        float ex1 = __expf(t1 * 0.17677669529663687f);
        dsum += ex0 + ex1;
        acc.x = fmaf(v40.x + ev0.x, ex0, acc.x);
        acc.y = fmaf(v40.y + ev0.y, ex0, acc.y);
        acc.z = fmaf(v40.z + ev0.z, ex0, acc.z);
        acc.w = fmaf(v40.w + ev0.w, ex0, acc.w);
        acc.x = fmaf(v41.x + ev1.x, ex1, acc.x);
        acc.y = fmaf(v41.y + ev1.y, ex1, acc.y);
        acc.z = fmaf(v41.z + ev1.z, ex1, acc.z);
        acc.w = fmaf(v41.w + ev1.w, ex1, acc.w);
    }

    if (j < deg) {   // tail edge
        int e = __ldg(&d_perm[start + j]);
        int s = __ldg(&src[e]);
        const float4* ea4 = (const float4*)(eattr + (size_t)e * 16);
        float4 a0 = __ldg(ea4 + 0), a1 = __ldg(ea4 + 1),
               a2 = __ldg(ea4 + 2), a3 = __ldg(ea4 + 3);
        float ea[16] = {a0.x, a0.y, a0.z, a0.w, a1.x, a1.y, a1.z, a1.w,
                        a2.x, a2.y, a2.z, a2.w, a3.x, a3.y, a3.z, a3.w};
        float4 ev = make_float4(0.f, 0.f, 0.f, 0.f);
#pragma unroll
        for (int k = 0; k < 16; k++) {
            ev.x = fmaf(ea[k], wreg[k].x, ev.x);
            ev.y = fmaf(ea[k], wreg[k].y, ev.y);
            ev.z = fmaf(ea[k], wreg[k].z, ev.z);
            ev.w = fmaf(ea[k], wreg[k].w, ev.w);
        }
        const float* base = d_qkvs + (size_t)s * 512;
        float4 k4 = *(const float4*)(base + 128 + lane * 4);
        float4 v4 = *(const float4*)(base + 256 + lane * 4);
        float t = q4.x * (k4.x + ev.x) + q4.y * (k4.y + ev.y) +
                  q4.z * (k4.z + ev.z) + q4.w * (k4.w + ev.w);
        t += __shfl_xor_sync(0xffffffffu, t, 1);
        t += __shfl_xor_sync(0xffffffffu, t, 2);
        t += __shfl_xor_sync(0xffffffffu, t, 4);
        float ex = __expf(t * 0.17677669529663687f);
        dsum += ex;
        acc.x = fmaf(v4.x + ev.x, ex, acc.x);
        acc.y = fmaf(v4.y + ev.y, ex, acc.y);
        acc.z = fmaf(v4.z + ev.z, ex, acc.z);
        acc.w = fmaf(v4.w + ev.w, ex, acc.w);
    }

    float inv = 1.0f / (dsum + 1e-16f);
    float4 sk = *(const float4*)(d_qkvs + (size_t)n * 512 + 384 + lane * 4);
    float4 o;
    o.x = fmaxf(fmaf(acc.x, inv, sk.x), 0.0f);
    o.y = fmaxf(fmaf(acc.y, inv, sk.y), 0.0f);
    o.z = fmaxf(fmaf(acc.z, inv, sk.z), 0.0f);
    o.w = fmaxf(fmaf(acc.w, inv, sk.w), 0.0f);
    *(float4*)(d_h + (size_t)n * 128 + lane * 4) = o;
}

// ---------------------------------------------------------------------------
// Output head: logits = h @ Wout + bout; log_softmax. One warp per node.
// ---------------------------------------------------------------------------
__global__ void __launch_bounds__(256) out_kernel(const float* __restrict__ Wout,
                                                  const float* __restrict__ bout,
                                                  float* __restrict__ out) {
    __shared__ float sW[128 * 10];
    __shared__ float sb[10];
    int tid = threadIdx.x;
    for (int i = tid; i < 128 * 10; i += 256) sW[i] = Wout[i];
    if (tid < 10) sb[tid] = bout[tid];
    __syncthreads();

    int warp = (blockIdx.x * 256 + tid) >> 5;
    int lane = tid & 31;
    if (warp >= NN) return;

    float4 hv = *(const float4*)(d_h + (size_t)warp * 128 + lane * 4);
    float lg[10];
#pragma unroll
    for (int c = 0; c < 10; c++) {
        float p = hv.x * sW[(lane * 4 + 0) * 10 + c] +
                  hv.y * sW[(lane * 4 + 1) * 10 + c] +
                  hv.z * sW[(lane * 4 + 2) * 10 + c] +
                  hv.w * sW[(lane * 4 + 3) * 10 + c];
        p += __shfl_xor_sync(0xffffffffu, p, 16);
        p += __shfl_xor_sync(0xffffffffu, p, 8);
        p += __shfl_xor_sync(0xffffffffu, p, 4);
        p += __shfl_xor_sync(0xffffffffu, p, 2);
        p += __shfl_xor_sync(0xffffffffu, p, 1);
        lg[c] = p + sb[c];
    }
    float mx = lg[0];
#pragma unroll
    for (int c = 1; c < 10; c++) mx = fmaxf(mx, lg[c]);
    float ss = 0.0f;
#pragma unroll
    for (int c = 0; c < 10; c++) ss += __expf(lg[c] - mx);
    float lse = mx + logf(ss);
    if (lane == 0) {
#pragma unroll
        for (int c = 0; c < 10; c++)
            out[(size_t)warp * 10 + c] = lg[c] - lse;
    }
}

// ---------------------------------------------------------------------------
// Launch
// ---------------------------------------------------------------------------
extern "C" void kernel_launch(void* const* d_in, const int* in_sizes, int n_in,
                              void* d_out, int out_size) {
    const float* x     = (const float*)d_in[0];
    const int*   ei    = (const int*)d_in[1];
    const float* eattr = (const float*)d_in[2];
    const float* Wout = (const float*)d_in[21];
    const float* bout = (const float*)d_in[22];
    float* out = (float*)d_out;

    const int* src = ei;       // edge_index[0]
    const int* dst = ei + EE;  // edge_index[1]

    const int PACK_BLKS = (128 * 512 + 255) / 256;
    const int EDGE_BLKS = (EE + 255) / 256;
    const int NODE_BLKS = (NN + 255) / 256;
    const int WARP_NODE_BLKS = (NN * 32 + 255) / 256;
    dim3 gemmGrid(4, (NN + 127) / 128);

    // CSR-by-dst (dst identical for both layers) -------------------------
    zero_deg<<<NODE_BLKS, 256>>>();
    hist_kernel<<<EDGE_BLKS, 256>>>(dst);
    chunk_sums<<<NCHUNK, 256>>>();
    chunk_offsets<<<1, 256>>>();
    scan_chunks<<<NCHUNK, 256>>>();
    scatter_perm<<<EDGE_BLKS, 256>>>(dst);

    for (int layer = 0; layer < 2; layer++) {
        int base = 3 + layer * 9;
        const float* Wq = (const float*)d_in[base + 0];
        const float* bq = (const float*)d_in[base + 1];
        const float* Wk = (const float*)d_in[base + 2];
        const float* bk = (const float*)d_in[base + 3];
        const float* Wv = (const float*)d_in[base + 4];
        const float* bv = (const float*)d_in[base + 5];
        const float* We = (const float*)d_in[base + 6];
        const float* Ws = (const float*)d_in[base + 7];
        const float* bs = (const float*)d_in[base + 8];

        pack_kernel<<<PACK_BLKS, 256>>>(Wq, Wk, Wv, Ws, bq, bk, bv, bs);
        sgemm_tf32<<<gemmGrid, 256>>>(x, layer, NN);
        attn_node<<<WARP_NODE_BLKS, 256>>>(src, eattr, We);
    }
    out_kernel<<<WARP_NODE_BLKS, 256>>>(Wout, bout, out);
}

// round 6
// speedup vs baseline: 1.9037x; 1.1823x over previous
#include <cuda_runtime.h>
#include <cuda_bf16.h>
#include <cstdint>

// Problem constants (fixed by the dataset)
#define NN   50000
#define EE   600000
#define FD   128
#define EDIM 16
#define HH   4
#define DD   32
#define HIDD 128
#define CC   10

#define NCHUNK 196   // ceil(NN/256)

// ---------------------------------------------------------------------------
// Scratch (device globals; allocation-free per harness rules)
// ---------------------------------------------------------------------------
__device__ __align__(16) float d_qkvs[(size_t)NN * 512];   // q|k|v|skip packed per node
__device__ __align__(16) float d_h[(size_t)NN * 128];      // layer output
__device__ __align__(16) uint32_t d_WpH[64 * 512];         // B hi, bf16x2 k-pairs [kp][512]
__device__ __align__(16) uint32_t d_WpL[64 * 512];         // B lo
__device__ __align__(16) float d_bp[512];

// CSR-by-dst (built once per launch, shared by both layers)
__device__ int d_deg[NN];
__device__ int d_start[NN];
__device__ int d_cursor[NN];
__device__ int d_perm[EE];
__device__ int d_csums[256];
__device__ int d_coffs[256];

// ---------------------------------------------------------------------------
// Helpers
// ---------------------------------------------------------------------------
__device__ __forceinline__ int warp_incl_scan(int v, int lane) {
#pragma unroll
    for (int o = 1; o < 32; o <<= 1) {
        int n = __shfl_up_sync(0xffffffffu, v, o);
        if (lane >= o) v += n;
    }
    return v;
}

// pack two floats into bf16x2 (lo half = first element) + residual pair
__device__ __forceinline__ void split_bf16x2(float f0, float f1,
                                             uint32_t& hi, uint32_t& lo) {
    __nv_bfloat162 hp = __float22bfloat162_rn(make_float2(f0, f1));
    hi = *reinterpret_cast<uint32_t*>(&hp);
    float r0 = f0 - __low2float(hp);
    float r1 = f1 - __high2float(hp);
    __nv_bfloat162 lp = __float22bfloat162_rn(make_float2(r0, r1));
    lo = *reinterpret_cast<uint32_t*>(&lp);
}

// ---------------------------------------------------------------------------
// CSR build
// ---------------------------------------------------------------------------
__global__ void zero_deg() {
    int i = blockIdx.x * blockDim.x + threadIdx.x;
    if (i < NN) d_deg[i] = 0;
}

__global__ void hist_kernel(const int* __restrict__ dst) {
    int e = blockIdx.x * blockDim.x + threadIdx.x;
    if (e < EE) atomicAdd(&d_deg[dst[e]], 1);
}

__global__ void chunk_sums() {
    int tid = threadIdx.x, b = blockIdx.x, i = b * 256 + tid;
    int v = (i < NN) ? d_deg[i] : 0;
#pragma unroll
    for (int o = 16; o > 0; o >>= 1) v += __shfl_xor_sync(0xffffffffu, v, o);
    __shared__ int ws[8];
    if ((tid & 31) == 0) ws[tid >> 5] = v;
    __syncthreads();
    if (tid == 0) {
        int s = 0;
#pragma unroll
        for (int k = 0; k < 8; k++) s += ws[k];
        d_csums[b] = s;
    }
}

__global__ void chunk_offsets() {   // single block, 256 threads
    int tid = threadIdx.x;
    int lane = tid & 31, w = tid >> 5;
    __shared__ int ws[8];
    int v = (tid < NCHUNK) ? d_csums[tid] : 0;
    int incl = warp_incl_scan(v, lane);
    if (lane == 31) ws[w] = incl;
    __syncthreads();
    if (w == 0) {
        int t = (lane < 8) ? ws[lane] : 0;
        t = warp_incl_scan(t, lane);
        if (lane < 8) ws[lane] = t;
    }
    __syncthreads();
    int excl = incl - v + (w > 0 ? ws[w - 1] : 0);
    d_coffs[tid] = excl;
}

__global__ void scan_chunks() {
    int tid = threadIdx.x, b = blockIdx.x, i = b * 256 + tid;
    int lane = tid & 31, w = tid >> 5;
    __shared__ int ws[8];
    int v = (i < NN) ? d_deg[i] : 0;
    int incl = warp_incl_scan(v, lane);
    if (lane == 31) ws[w] = incl;
    __syncthreads();
    if (w == 0) {
        int t = (lane < 8) ? ws[lane] : 0;
        t = warp_incl_scan(t, lane);
        if (lane < 8) ws[lane] = t;
    }
    __syncthreads();
    int excl = incl - v + (w > 0 ? ws[w - 1] : 0) + d_coffs[b];
    if (i < NN) { d_start[i] = excl; d_cursor[i] = excl; }
}

__global__ void scatter_perm(const int* __restrict__ dst) {
    int e = blockIdx.x * blockDim.x + threadIdx.x;
    if (e < EE) {
        int pos = atomicAdd(&d_cursor[dst[e]], 1);
        d_perm[pos] = e;
    }
}

// ---------------------------------------------------------------------------
// Pack weights: bf16 hi/lo split, k-pair packed: d_WpH/L[kp][4*128]
// ---------------------------------------------------------------------------
__global__ void pack_kernel(const float* __restrict__ Wq, const float* __restrict__ Wk,
                            const float* __restrict__ Wv, const float* __restrict__ Ws,
                            const float* __restrict__ bq, const float* __restrict__ bk,
                            const float* __restrict__ bv, const float* __restrict__ bs) {
    int idx = blockIdx.x * blockDim.x + threadIdx.x;
    if (idx < 64 * 512) {
        int kp = idx >> 9, j = idx & 511;
        int sel = j >> 7, jc = j & 127;
        const float* W = sel == 0 ? Wq : sel == 1 ? Wk : sel == 2 ? Wv : Ws;
        float f0 = W[(2 * kp) * 128 + jc];
        float f1 = W[(2 * kp + 1) * 128 + jc];
        uint32_t hi, lo;
        split_bf16x2(f0, f1, hi, lo);
        d_WpH[idx] = hi;
        d_WpL[idx] = lo;
    }
    if (idx < 512) {
        int sel = idx >> 7, jc = idx & 127;
        const float* b = sel == 0 ? bq : sel == 1 ? bk : sel == 2 ? bv : bs;
        d_bp[idx] = b[jc];
    }
}

// ---------------------------------------------------------------------------
// bf16x3 tensor-core GEMM, double-buffered, KC=16, mma m16n8k16.
// C[M,512] = A[M,128] @ W[128,512] + b;  A split to bf16 hi/lo on the fly,
// B pre-split in pack_kernel.  D += Ah*Bh + Ah*Bl + Al*Bh.
// 128x128 block tile, 8 warps (2x4), warp tile 64x32.
// ---------------------------------------------------------------------------
#define KC 16   // K per chunk = one m16n8k16 step

__global__ void __launch_bounds__(256) sgemm_bf16x3(const float* __restrict__ x,
                                                    int layer, int M) {
    const float* A = (layer == 0) ? x : (const float*)d_h;

    // pair-packed layouts: As [row][pair 0..7] stride 9; Bs [pair 0..7][col] stride 132
    __shared__ uint32_t AsH[2][128][9];
    __shared__ uint32_t AsL[2][128][9];
    __shared__ uint32_t BsH[2][8][132];
    __shared__ uint32_t BsL[2][8][132];

    int tid = threadIdx.x;
    int bx = blockIdx.x;               // 0..3
    int by = blockIdx.y;
    int warp = tid >> 5, lane = tid & 31;
    int wm = warp >> 2, wn = warp & 3; // 2 x 4 warp grid
    int mbase = wm * 64, nbase = wn * 32;
    int rowBase = by * 128;
    int g = lane >> 2;                 // groupID
    int tg = lane & 3;                 // thread-in-group

    // A staging: 512 float4 per chunk, 2 per thread
    int aR0 = tid >> 2,          aC0 = tid & 3;          // row, float4-within-row
    int aR1 = (tid + 256) >> 2,  aC1 = (tid + 256) & 3;
    // B staging: 8 pair-rows x 128 cols per buffer; one uint4 per thread
    int bR = tid >> 5, bC = (tid & 31) * 4;

    float c[4][4][4];
#pragma unroll
    for (int i = 0; i < 4; i++)
#pragma unroll
        for (int j = 0; j < 4; j++)
#pragma unroll
            for (int r = 0; r < 4; r++) c[i][j][r] = 0.0f;

    float4 aReg0, aReg1;
    uint4 bRegH, bRegL;
    int grA0 = rowBase + aR0, grA1 = rowBase + aR1;
    bool a0OK = (grA0 < M), a1OK = (grA1 < M);

    auto loadChunk = [&](int ch) {
        int k0 = ch * KC;
        aReg0 = a0OK ? *(const float4*)(A + (size_t)grA0 * 128 + k0 + aC0 * 4)
                     : make_float4(0.f, 0.f, 0.f, 0.f);
        aReg1 = a1OK ? *(const float4*)(A + (size_t)grA1 * 128 + k0 + aC1 * 4)
                     : make_float4(0.f, 0.f, 0.f, 0.f);
        int kp0 = ch * 8;  // pair base
        bRegH = *(const uint4*)(d_WpH + (kp0 + bR) * 512 + bx * 128 + bC);
        bRegL = *(const uint4*)(d_WpL + (kp0 + bR) * 512 + bx * 128 + bC);
    };

    auto storeChunk = [&](int st) {
        uint32_t h0, l0, h1, l1;
        split_bf16x2(aReg0.x, aReg0.y, h0, l0);
        split_bf16x2(aReg0.z, aReg0.w, h1, l1);
        AsH[st][aR0][2 * aC0] = h0;     AsH[st][aR0][2 * aC0 + 1] = h1;
        AsL[st][aR0][2 * aC0] = l0;     AsL[st][aR0][2 * aC0 + 1] = l1;
        split_bf16x2(aReg1.x, aReg1.y, h0, l0);
        split_bf16x2(aReg1.z, aReg1.w, h1, l1);
        AsH[st][aR1][2 * aC1] = h0;     AsH[st][aR1][2 * aC1 + 1] = h1;
        AsL[st][aR1][2 * aC1] = l0;     AsL[st][aR1][2 * aC1 + 1] = l1;
        BsH[st][bR][bC + 0] = bRegH.x;  BsH[st][bR][bC + 1] = bRegH.y;
        BsH[st][bR][bC + 2] = bRegH.z;  BsH[st][bR][bC + 3] = bRegH.w;
        BsL[st][bR][bC + 0] = bRegL.x;  BsL[st][bR][bC + 1] = bRegL.y;
        BsL[st][bR][bC + 2] = bRegL.z;  BsL[st][bR][bC + 3] = bRegL.w;
    };

    auto computeChunk = [&](int st) {
        uint32_t bh[4][2], bl[4][2];
#pragma unroll
        for (int nt = 0; nt < 4; nt++) {
            int nn = nbase + nt * 8 + g;
            bh[nt][0] = BsH[st][tg][nn];     bh[nt][1] = BsH[st][4 + tg][nn];
            bl[nt][0] = BsL[st][tg][nn];     bl[nt][1] = BsL[st][4 + tg][nn];
        }
#pragma unroll
        for (int mt = 0; mt < 4; mt++) {
            int r = mbase + mt * 16 + g;
            uint32_t ah[4], al[4];
            ah[0] = AsH[st][r][tg];     ah[1] = AsH[st][r + 8][tg];
            ah[2] = AsH[st][r][4 + tg]; ah[3] = AsH[st][r + 8][4 + tg];
            al[0] = AsL[st][r][tg];     al[1] = AsL[st][r + 8][tg];
            al[2] = AsL[st][r][4 + tg]; al[3] = AsL[st][r + 8][4 + tg];
#pragma unroll
            for (int nt = 0; nt < 4; nt++) {
                float* cc = c[mt][nt];
                asm volatile(
                    "mma.sync.aligned.m16n8k16.row.col.f32.bf16.bf16.f32 "
                    "{%0,%1,%2,%3},{%4,%5,%6,%7},{%8,%9},{%0,%1,%2,%3};"
                    : "+f"(cc[0]), "+f"(cc[1]), "+f"(cc[2]), "+f"(cc[3])
                    : "r"(ah[0]), "r"(ah[1]), "r"(ah[2]), "r"(ah[3]),
                      "r"(bh[nt][0]), "r"(bh[nt][1]));
                asm volatile(
                    "mma.sync.aligned.m16n8k16.row.col.f32.bf16.bf16.f32 "
                    "{%0,%1,%2,%3},{%4,%5,%6,%7},{%8,%9},{%0,%1,%2,%3};"
                    : "+f"(cc[0]), "+f"(cc[1]), "+f"(cc[2]), "+f"(cc[3])
                    : "r"(ah[0]), "r"(ah[1]), "r"(ah[2]), "r"(ah[3]),
                      "r"(bl[nt][0]), "r"(bl[nt][1]));
                asm volatile(
                    "mma.sync.aligned.m16n8k16.row.col.f32.bf16.bf16.f32 "
                    "{%0,%1,%2,%3},{%4,%5,%6,%7},{%8,%9},{%0,%1,%2,%3};"
                    : "+f"(cc[0]), "+f"(cc[1]), "+f"(cc[2]), "+f"(cc[3])
                    : "r"(al[0]), "r"(al[1]), "r"(al[2]), "r"(al[3]),
                      "r"(bh[nt][0]), "r"(bh[nt][1]));
            }
        }
    };

    // ---- pipelined mainloop: 8 chunks of K=16, 1 sync per chunk ----
    loadChunk(0);
    storeChunk(0);
    __syncthreads();
#pragma unroll
    for (int ch = 0; ch < 8; ch++) {
        int cur = ch & 1;
        if (ch < 7) loadChunk(ch + 1);      // global prefetch overlaps compute
        computeChunk(cur);
        if (ch < 7) {
            storeChunk(cur ^ 1);
            __syncthreads();
        }
    }

    // epilogue: bias add, write to d_qkvs
#pragma unroll
    for (int mt = 0; mt < 4; mt++) {
        int r0 = rowBase + mbase + mt * 16 + g;
        int r1 = r0 + 8;
#pragma unroll
        for (int nt = 0; nt < 4; nt++) {
            int col = bx * 128 + nbase + nt * 8 + 2 * tg;
            float2 b2 = *(const float2*)(d_bp + col);
            if (r0 < M) {
                float2 o = make_float2(c[mt][nt][0] + b2.x, c[mt][nt][1] + b2.y);
                *(float2*)(d_qkvs + (size_t)r0 * 512 + col) = o;
            }
            if (r1 < M) {
                float2 o = make_float2(c[mt][nt][2] + b2.x, c[mt][nt][3] + b2.y);
                *(float2*)(d_qkvs + (size_t)r1 * 512 + col) = o;
            }
        }
    }
}

// ---------------------------------------------------------------------------
// Node-centric fused attention, 2-wide edge unroll, 128-thread blocks
// (3 CTAs/SM for latency hiding). One warp per destination node.
// ---------------------------------------------------------------------------
__global__ void __launch_bounds__(128) attn_node(const int* __restrict__ src,
                                                 const float* __restrict__ eattr,
                                                 const float* __restrict__ We) {
    int warp = (blockIdx.x * 128 + threadIdx.x) >> 5;
    int lane = threadIdx.x & 31;
    if (warp >= NN) return;
    int n = warp;

    float4 wreg[16];
#pragma unroll
    for (int k = 0; k < 16; k++)
        wreg[k] = __ldg((const float4*)(We + k * 128) + lane);

    float4 q4 = *(const float4*)(d_qkvs + (size_t)n * 512 + lane * 4);
    float4 acc = make_float4(0.f, 0.f, 0.f, 0.f);
    float dsum = 0.0f;

    int start = d_start[n];
    int deg = d_deg[n];

    int j = 0;
    for (; j + 1 < deg; j += 2) {
        int e0 = __ldg(&d_perm[start + j]);
        int e1 = __ldg(&d_perm[start + j + 1]);
        int s0 = __ldg(&src[e0]);
        int s1 = __ldg(&src[e1]);

        const float4* ea40 = (const float4*)(eattr + (size_t)e0 * 16);
        const float4* ea41 = (const float4*)(eattr + (size_t)e1 * 16);
        float4 p00 = __ldg(ea40 + 0), p01 = __ldg(ea40 + 1),
               p02 = __ldg(ea40 + 2), p03 = __ldg(ea40 + 3);
        float4 p10 = __ldg(ea41 + 0), p11 = __ldg(ea41 + 1),
               p12 = __ldg(ea41 + 2), p13 = __ldg(ea41 + 3);

        const float* base0 = d_qkvs + (size_t)s0 * 512;
        const float* base1 = d_qkvs + (size_t)s1 * 512;
        float4 k40 = *(const float4*)(base0 + 128 + lane * 4);
        float4 v40 = *(const float4*)(base0 + 256 + lane * 4);
        float4 k41 = *(const float4*)(base1 + 128 + lane * 4);
        float4 v41 = *(const float4*)(base1 + 256 + lane * 4);

        float ea0[16] = {p00.x, p00.y, p00.z, p00.w, p01.x, p01.y, p01.z, p01.w,
                         p02.x, p02.y, p02.z, p02.w, p03.x, p03.y, p03.z, p03.w};
        float ea1[16] = {p10.x, p10.y, p10.z, p10.w, p11.x, p11.y, p11.z, p11.w,
                         p12.x, p12.y, p12.z, p12.w, p13.x, p13.y, p13.z, p13.w};

        float4 ev0 = make_float4(0.f, 0.f, 0.f, 0.f);
        float4 ev1 = make_float4(0.f, 0.f, 0.f, 0.f);
#pragma unroll
        for (int k = 0; k < 16; k++) {
            ev0.x = fmaf(ea0[k], wreg[k].x, ev0.x);
            ev0.y = fmaf(ea0[k], wreg[k].y, ev0.y);
            ev0.z = fmaf(ea0[k], wreg[k].z, ev0.z);
            ev0.w = fmaf(ea0[k], wreg[k].w, ev0.w);
            ev1.x = fmaf(ea1[k], wreg[k].x, ev1.x);
            ev1.y = fmaf(ea1[k], wreg[k].y, ev1.y);
            ev1.z = fmaf(ea1[k], wreg[k].z, ev1.z);
            ev1.w = fmaf(ea1[k], wreg[k].w, ev1.w);
        }

        float t0 = q4.x * (k40.x + ev0.x) + q4.y * (k40.y + ev0.y) +
                   q4.z * (k40.z + ev0.z) + q4.w * (k40.w + ev0.w);
        float t1 = q4.x * (k41.x + ev1.x) + q4.y * (k41.y + ev1.y) +
                   q4.z * (k41.z + ev1.z) + q4.w * (k41.w + ev1.w);
        t0 += __shfl_xor_sync(0xffffffffu, t0, 1);
        t1 += __shfl_xor_sync(0xffffffffu, t1, 1);
        t0 += __shfl_xor_sync(0xffffffffu, t0, 2);
        t1 += __shfl_xor_sync(0xffffffffu, t1, 2);
        t0 += __shfl_xor_sync(0xffffffffu, t0, 4);
        t1 += __shfl_xor_sync(0xffffffffu, t1, 4);

        float ex0 = __expf(t0 * 0.17677669529663687f);
        float ex1 = __expf(t1 * 0.17677669529663687f);
        dsum += ex0 + ex1;
        acc.x = fmaf(v40.x + ev0.x, ex0, acc.x);
        acc.y = fmaf(v40.y + ev0.y, ex0, acc.y);
        acc.z = fmaf(v40.z + ev0.z, ex0, acc.z);
        acc.w = fmaf(v40.w + ev0.w, ex0, acc.w);
        acc.x = fmaf(v41.x + ev1.x, ex1, acc.x);
        acc.y = fmaf(v41.y + ev1.y, ex1, acc.y);
        acc.z = fmaf(v41.z + ev1.z, ex1, acc.z);
        acc.w = fmaf(v41.w + ev1.w, ex1, acc.w);
    }

    if (j < deg) {   // tail edge
        int e = __ldg(&d_perm[start + j]);
        int s = __ldg(&src[e]);
        const float4* ea4 = (const float4*)(eattr + (size_t)e * 16);
        float4 a0 = __ldg(ea4 + 0), a1 = __ldg(ea4 + 1),
               a2 = __ldg(ea4 + 2), a3 = __ldg(ea4 + 3);
        float ea[16] = {a0.x, a0.y, a0.z, a0.w, a1.x, a1.y, a1.z, a1.w,
                        a2.x, a2.y, a2.z, a2.w, a3.x, a3.y, a3.z, a3.w};
        float4 ev = make_float4(0.f, 0.f, 0.f, 0.f);
#pragma unroll
        for (int k = 0; k < 16; k++) {
            ev.x = fmaf(ea[k], wreg[k].x, ev.x);
            ev.y = fmaf(ea[k], wreg[k].y, ev.y);
            ev.z = fmaf(ea[k], wreg[k].z, ev.z);
            ev.w = fmaf(ea[k], wreg[k].w, ev.w);
        }
        const float* base = d_qkvs + (size_t)s * 512;
        float4 k4 = *(const float4*)(base + 128 + lane * 4);
        float4 v4 = *(const float4*)(base + 256 + lane * 4);
        float t = q4.x * (k4.x + ev.x) + q4.y * (k4.y + ev.y) +
                  q4.z * (k4.z + ev.z) + q4.w * (k4.w + ev.w);
        t += __shfl_xor_sync(0xffffffffu, t, 1);
        t += __shfl_xor_sync(0xffffffffu, t, 2);
        t += __shfl_xor_sync(0xffffffffu, t, 4);
        float ex = __expf(t * 0.17677669529663687f);
        dsum += ex;
        acc.x = fmaf(v4.x + ev.x, ex, acc.x);
        acc.y = fmaf(v4.y + ev.y, ex, acc.y);
        acc.z = fmaf(v4.z + ev.z, ex, acc.z);
        acc.w = fmaf(v4.w + ev.w, ex, acc.w);
    }

    float inv = 1.0f / (dsum + 1e-16f);
    float4 sk = *(const float4*)(d_qkvs + (size_t)n * 512 + 384 + lane * 4);
    float4 o;
    o.x = fmaxf(fmaf(acc.x, inv, sk.x), 0.0f);
    o.y = fmaxf(fmaf(acc.y, inv, sk.y), 0.0f);
    o.z = fmaxf(fmaf(acc.z, inv, sk.z), 0.0f);
    o.w = fmaxf(fmaf(acc.w, inv, sk.w), 0.0f);
    *(float4*)(d_h + (size_t)n * 128 + lane * 4) = o;
}

// ---------------------------------------------------------------------------
// Output head: logits = h @ Wout + bout; log_softmax. One warp per node.
// ---------------------------------------------------------------------------
__global__ void __launch_bounds__(256) out_kernel(const float* __restrict__ Wout,
                                                  const float* __restrict__ bout,
                                                  float* __restrict__ out) {
    __shared__ float sW[128 * 10];
    __shared__ float sb[10];
    int tid = threadIdx.x;
    for (int i = tid; i < 128 * 10; i += 256) sW[i] = Wout[i];
    if (tid < 10) sb[tid] = bout[tid];
    __syncthreads();

    int warp = (blockIdx.x * 256 + tid) >> 5;
    int lane = tid & 31;
    if (warp >= NN) return;

    float4 hv = *(const float4*)(d_h + (size_t)warp * 128 + lane * 4);
    float lg[10];
#pragma unroll
    for (int c = 0; c < 10; c++) {
        float p = hv.x * sW[(lane * 4 + 0) * 10 + c] +
                  hv.y * sW[(lane * 4 + 1) * 10 + c] +
                  hv.z * sW[(lane * 4 + 2) * 10 + c] +
                  hv.w * sW[(lane * 4 + 3) * 10 + c];
        p += __shfl_xor_sync(0xffffffffu, p, 16);
        p += __shfl_xor_sync(0xffffffffu, p, 8);
        p += __shfl_xor_sync(0xffffffffu, p, 4);
        p += __shfl_xor_sync(0xffffffffu, p, 2);
        p += __shfl_xor_sync(0xffffffffu, p, 1);
        lg[c] = p + sb[c];
    }
    float mx = lg[0];
#pragma unroll
    for (int c = 1; c < 10; c++) mx = fmaxf(mx, lg[c]);
    float ss = 0.0f;
#pragma unroll
    for (int c = 0; c < 10; c++) ss += __expf(lg[c] - mx);
    float lse = mx + logf(ss);
    if (lane == 0) {
#pragma unroll
        for (int c = 0; c < 10; c++)
            out[(size_t)warp * 10 + c] = lg[c] - lse;
    }
}

// ---------------------------------------------------------------------------
// Launch (ordered so launch index 3 = sgemm layer 0 for ncu capture)
// ---------------------------------------------------------------------------
extern "C" void kernel_launch(void* const* d_in, const int* in_sizes, int n_in,
                              void* d_out, int out_size) {
    const float* x     = (const float*)d_in[0];
    const int*   ei    = (const int*)d_in[1];
    const float* eattr = (const float*)d_in[2];
    const float* Wout = (const float*)d_in[21];
    const float* bout = (const float*)d_in[22];
    float* out = (float*)d_out;

    const int* src = ei;       // edge_index[0]
    const int* dst = ei + EE;  // edge_index[1]

    const int PACK_BLKS = (64 * 512 + 255) / 256;
    const int EDGE_BLKS = (EE + 255) / 256;
    const int NODE_BLKS = (NN + 255) / 256;
    const int ATTN_BLKS = (NN * 32 + 127) / 128;
    const int OUT_BLKS  = (NN * 32 + 255) / 256;
    dim3 gemmGrid(4, (NN + 127) / 128);

    const float* W0[9], *W1[9];
    for (int i = 0; i < 9; i++) { W0[i] = (const float*)d_in[3 + i]; W1[i] = (const float*)d_in[12 + i]; }

    // idx0-1: CSR part A
    zero_deg<<<NODE_BLKS, 256>>>();
    hist_kernel<<<EDGE_BLKS, 256>>>(dst);
    // idx2-3: layer0 projections (sgemm at captured launch index 3)
    pack_kernel<<<PACK_BLKS, 256>>>(W0[0], W0[2], W0[4], W0[7], W0[1], W0[3], W0[5], W0[8]);
    sgemm_bf16x3<<<gemmGrid, 256>>>(x, 0, NN);
    // idx4-7: CSR part B
    chunk_sums<<<NCHUNK, 256>>>();
    chunk_offsets<<<1, 256>>>();
    scan_chunks<<<NCHUNK, 256>>>();
    scatter_perm<<<EDGE_BLKS, 256>>>(dst);
    // layer0 attention
    attn_node<<<ATTN_BLKS, 128>>>(src, eattr, W0[6]);
    // layer1
    pack_kernel<<<PACK_BLKS, 256>>>(W1[0], W1[2], W1[4], W1[7], W1[1], W1[3], W1[5], W1[8]);
    sgemm_bf16x3<<<gemmGrid, 256>>>(nullptr, 1, NN);
    attn_node<<<ATTN_BLKS, 128>>>(src, eattr, W1[6]);
    // head
    out_kernel<<<OUT_BLKS, 256>>>(Wout, bout, out);
}

// round 7
// speedup vs baseline: 2.3033x; 1.2099x over previous
#include <cuda_runtime.h>
#include <cuda_bf16.h>
#include <cstdint>

// Problem constants (fixed by the dataset)
#define NN   50000
#define EE   600000
#define FD   128
#define EDIM 16
#define HH   4
#define DD   32
#define HIDD 128
#define CC   10

#define NCHUNK 196   // ceil(NN/256)

// ---------------------------------------------------------------------------
// Scratch (device globals; allocation-free per harness rules)
// ---------------------------------------------------------------------------
__device__ __align__(16) float d_qkvs[(size_t)NN * 512];   // q|k|v|skip packed per node
__device__ __align__(16) float d_h[(size_t)NN * 128];      // layer output
__device__ __align__(16) uint32_t d_WpH[64 * 512];         // B hi, bf16x2 k-pairs [kp][512]
__device__ __align__(16) uint32_t d_WpL[64 * 512];         // B lo
__device__ __align__(16) float d_bp[512];

// CSR-by-dst (built once per launch, shared by both layers)
__device__ int d_deg[NN];
__device__ int d_start[NN];
__device__ int d_cursor[NN];
__device__ int d_perm[EE];   // edge id (for eattr)
__device__ int d_psrc[EE];   // permuted src node id
__device__ int d_csums[256];
__device__ int d_coffs[256];

// ---------------------------------------------------------------------------
// Helpers
// ---------------------------------------------------------------------------
__device__ __forceinline__ int warp_incl_scan(int v, int lane) {
#pragma unroll
    for (int o = 1; o < 32; o <<= 1) {
        int n = __shfl_up_sync(0xffffffffu, v, o);
        if (lane >= o) v += n;
    }
    return v;
}

__device__ __forceinline__ void split_bf16x2(float f0, float f1,
                                             uint32_t& hi, uint32_t& lo) {
    __nv_bfloat162 hp = __float22bfloat162_rn(make_float2(f0, f1));
    hi = *reinterpret_cast<uint32_t*>(&hp);
    float r0 = f0 - __low2float(hp);
    float r1 = f1 - __high2float(hp);
    __nv_bfloat162 lp = __float22bfloat162_rn(make_float2(r0, r1));
    lo = *reinterpret_cast<uint32_t*>(&lp);
}

// ---------------------------------------------------------------------------
// CSR build
// ---------------------------------------------------------------------------
__global__ void zero_deg() {
    int i = blockIdx.x * blockDim.x + threadIdx.x;
    if (i < NN) d_deg[i] = 0;
}

__global__ void hist_kernel(const int* __restrict__ dst) {
    int e = blockIdx.x * blockDim.x + threadIdx.x;
    if (e < EE) atomicAdd(&d_deg[dst[e]], 1);
}

__global__ void chunk_sums() {
    int tid = threadIdx.x, b = blockIdx.x, i = b * 256 + tid;
    int v = (i < NN) ? d_deg[i] : 0;
#pragma unroll
    for (int o = 16; o > 0; o >>= 1) v += __shfl_xor_sync(0xffffffffu, v, o);
    __shared__ int ws[8];
    if ((tid & 31) == 0) ws[tid >> 5] = v;
    __syncthreads();
    if (tid == 0) {
        int s = 0;
#pragma unroll
        for (int k = 0; k < 8; k++) s += ws[k];
        d_csums[b] = s;
    }
}

__global__ void chunk_offsets() {   // single block, 256 threads
    int tid = threadIdx.x;
    int lane = tid & 31, w = tid >> 5;
    __shared__ int ws[8];
    int v = (tid < NCHUNK) ? d_csums[tid] : 0;
    int incl = warp_incl_scan(v, lane);
    if (lane == 31) ws[w] = incl;
    __syncthreads();
    if (w == 0) {
        int t = (lane < 8) ? ws[lane] : 0;
        t = warp_incl_scan(t, lane);
        if (lane < 8) ws[lane] = t;
    }
    __syncthreads();
    int excl = incl - v + (w > 0 ? ws[w - 1] : 0);
    d_coffs[tid] = excl;
}

__global__ void scan_chunks() {
    int tid = threadIdx.x, b = blockIdx.x, i = b * 256 + tid;
    int lane = tid & 31, w = tid >> 5;
    __shared__ int ws[8];
    int v = (i < NN) ? d_deg[i] : 0;
    int incl = warp_incl_scan(v, lane);
    if (lane == 31) ws[w] = incl;
    __syncthreads();
    if (w == 0) {
        int t = (lane < 8) ? ws[lane] : 0;
        t = warp_incl_scan(t, lane);
        if (lane < 8) ws[lane] = t;
    }
    __syncthreads();
    int excl = incl - v + (w > 0 ? ws[w - 1] : 0) + d_coffs[b];
    if (i < NN) { d_start[i] = excl; d_cursor[i] = excl; }
}

__global__ void scatter_perm(const int* __restrict__ dst, const int* __restrict__ src) {
    int e = blockIdx.x * blockDim.x + threadIdx.x;
    if (e < EE) {
        int pos = atomicAdd(&d_cursor[dst[e]], 1);
        d_perm[pos] = e;
        d_psrc[pos] = src[e];
    }
}

// ---------------------------------------------------------------------------
// Pack weights: bf16 hi/lo split, k-pair packed
// ---------------------------------------------------------------------------
__global__ void pack_kernel(const float* __restrict__ Wq, const float* __restrict__ Wk,
                            const float* __restrict__ Wv, const float* __restrict__ Ws,
                            const float* __restrict__ bq, const float* __restrict__ bk,
                            const float* __restrict__ bv, const float* __restrict__ bs) {
    int idx = blockIdx.x * blockDim.x + threadIdx.x;
    if (idx < 64 * 512) {
        int kp = idx >> 9, j = idx & 511;
        int sel = j >> 7, jc = j & 127;
        const float* W = sel == 0 ? Wq : sel == 1 ? Wk : sel == 2 ? Wv : Ws;
        float f0 = W[(2 * kp) * 128 + jc];
        float f1 = W[(2 * kp + 1) * 128 + jc];
        uint32_t hi, lo;
        split_bf16x2(f0, f1, hi, lo);
        d_WpH[idx] = hi;
        d_WpL[idx] = lo;
    }
    if (idx < 512) {
        int sel = idx >> 7, jc = idx & 127;
        const float* b = sel == 0 ? bq : sel == 1 ? bk : sel == 2 ? bv : bs;
        d_bp[idx] = b[jc];
    }
}

// ---------------------------------------------------------------------------
// bf16x3 tensor-core GEMM (unchanged from R5)
// ---------------------------------------------------------------------------
#define KC 16

__global__ void __launch_bounds__(256) sgemm_bf16x3(const float* __restrict__ x,
                                                    int layer, int M) {
    const float* A = (layer == 0) ? x : (const float*)d_h;

    __shared__ uint32_t AsH[2][128][9];
    __shared__ uint32_t AsL[2][128][9];
    __shared__ uint32_t BsH[2][8][132];
    __shared__ uint32_t BsL[2][8][132];

    int tid = threadIdx.x;
    int bx = blockIdx.x;
    int by = blockIdx.y;
    int warp = tid >> 5, lane = tid & 31;
    int wm = warp >> 2, wn = warp & 3;
    int mbase = wm * 64, nbase = wn * 32;
    int rowBase = by * 128;
    int g = lane >> 2;
    int tg = lane & 3;

    int aR0 = tid >> 2,          aC0 = tid & 3;
    int aR1 = (tid + 256) >> 2,  aC1 = (tid + 256) & 3;
    int bR = tid >> 5, bC = (tid & 31) * 4;

    float c[4][4][4];
#pragma unroll
    for (int i = 0; i < 4; i++)
#pragma unroll
        for (int j = 0; j < 4; j++)
#pragma unroll
            for (int r = 0; r < 4; r++) c[i][j][r] = 0.0f;

    float4 aReg0, aReg1;
    uint4 bRegH, bRegL;
    int grA0 = rowBase + aR0, grA1 = rowBase + aR1;
    bool a0OK = (grA0 < M), a1OK = (grA1 < M);

    auto loadChunk = [&](int ch) {
        int k0 = ch * KC;
        aReg0 = a0OK ? *(const float4*)(A + (size_t)grA0 * 128 + k0 + aC0 * 4)
                     : make_float4(0.f, 0.f, 0.f, 0.f);
        aReg1 = a1OK ? *(const float4*)(A + (size_t)grA1 * 128 + k0 + aC1 * 4)
                     : make_float4(0.f, 0.f, 0.f, 0.f);
        int kp0 = ch * 8;
        bRegH = *(const uint4*)(d_WpH + (kp0 + bR) * 512 + bx * 128 + bC);
        bRegL = *(const uint4*)(d_WpL + (kp0 + bR) * 512 + bx * 128 + bC);
    };

    auto storeChunk = [&](int st) {
        uint32_t h0, l0, h1, l1;
        split_bf16x2(aReg0.x, aReg0.y, h0, l0);
        split_bf16x2(aReg0.z, aReg0.w, h1, l1);
        AsH[st][aR0][2 * aC0] = h0;     AsH[st][aR0][2 * aC0 + 1] = h1;
        AsL[st][aR0][2 * aC0] = l0;     AsL[st][aR0][2 * aC0 + 1] = l1;
        split_bf16x2(aReg1.x, aReg1.y, h0, l0);
        split_bf16x2(aReg1.z, aReg1.w, h1, l1);
        AsH[st][aR1][2 * aC1] = h0;     AsH[st][aR1][2 * aC1 + 1] = h1;
        AsL[st][aR1][2 * aC1] = l0;     AsL[st][aR1][2 * aC1 + 1] = l1;
        BsH[st][bR][bC + 0] = bRegH.x;  BsH[st][bR][bC + 1] = bRegH.y;
        BsH[st][bR][bC + 2] = bRegH.z;  BsH[st][bR][bC + 3] = bRegH.w;
        BsL[st][bR][bC + 0] = bRegL.x;  BsL[st][bR][bC + 1] = bRegL.y;
        BsL[st][bR][bC + 2] = bRegL.z;  BsL[st][bR][bC + 3] = bRegL.w;
    };

    auto computeChunk = [&](int st) {
        uint32_t bh[4][2], bl[4][2];
#pragma unroll
        for (int nt = 0; nt < 4; nt++) {
            int nn = nbase + nt * 8 + g;
            bh[nt][0] = BsH[st][tg][nn];     bh[nt][1] = BsH[st][4 + tg][nn];
            bl[nt][0] = BsL[st][tg][nn];     bl[nt][1] = BsL[st][4 + tg][nn];
        }
#pragma unroll
        for (int mt = 0; mt < 4; mt++) {
            int r = mbase + mt * 16 + g;
            uint32_t ah[4], al[4];
            ah[0] = AsH[st][r][tg];     ah[1] = AsH[st][r + 8][tg];
            ah[2] = AsH[st][r][4 + tg]; ah[3] = AsH[st][r + 8][4 + tg];
            al[0] = AsL[st][r][tg];     al[1] = AsL[st][r + 8][tg];
            al[2] = AsL[st][r][4 + tg]; al[3] = AsL[st][r + 8][4 + tg];
#pragma unroll
            for (int nt = 0; nt < 4; nt++) {
                float* cc = c[mt][nt];
                asm volatile(
                    "mma.sync.aligned.m16n8k16.row.col.f32.bf16.bf16.f32 "
                    "{%0,%1,%2,%3},{%4,%5,%6,%7},{%8,%9},{%0,%1,%2,%3};"
                    : "+f"(cc[0]), "+f"(cc[1]), "+f"(cc[2]), "+f"(cc[3])
                    : "r"(ah[0]), "r"(ah[1]), "r"(ah[2]), "r"(ah[3]),
                      "r"(bh[nt][0]), "r"(bh[nt][1]));
                asm volatile(
                    "mma.sync.aligned.m16n8k16.row.col.f32.bf16.bf16.f32 "
                    "{%0,%1,%2,%3},{%4,%5,%6,%7},{%8,%9},{%0,%1,%2,%3};"
                    : "+f"(cc[0]), "+f"(cc[1]), "+f"(cc[2]), "+f"(cc[3])
                    : "r"(ah[0]), "r"(ah[1]), "r"(ah[2]), "r"(ah[3]),
                      "r"(bl[nt][0]), "r"(bl[nt][1]));
                asm volatile(
                    "mma.sync.aligned.m16n8k16.row.col.f32.bf16.bf16.f32 "
                    "{%0,%1,%2,%3},{%4,%5,%6,%7},{%8,%9},{%0,%1,%2,%3};"
                    : "+f"(cc[0]), "+f"(cc[1]), "+f"(cc[2]), "+f"(cc[3])
                    : "r"(al[0]), "r"(al[1]), "r"(al[2]), "r"(al[3]),
                      "r"(bh[nt][0]), "r"(bh[nt][1]));
            }
        }
    };

    loadChunk(0);
    storeChunk(0);
    __syncthreads();
#pragma unroll
    for (int ch = 0; ch < 8; ch++) {
        int cur = ch & 1;
        if (ch < 7) loadChunk(ch + 1);
        computeChunk(cur);
        if (ch < 7) {
            storeChunk(cur ^ 1);
            __syncthreads();
        }
    }

#pragma unroll
    for (int mt = 0; mt < 4; mt++) {
        int r0 = rowBase + mbase + mt * 16 + g;
        int r1 = r0 + 8;
#pragma unroll
        for (int nt = 0; nt < 4; nt++) {
            int col = bx * 128 + nbase + nt * 8 + 2 * tg;
            float2 b2 = *(const float2*)(d_bp + col);
            if (r0 < M) {
                float2 o = make_float2(c[mt][nt][0] + b2.x, c[mt][nt][1] + b2.y);
                *(float2*)(d_qkvs + (size_t)r0 * 512 + col) = o;
            }
            if (r1 < M) {
                float2 o = make_float2(c[mt][nt][2] + b2.x, c[mt][nt][3] + b2.y);
                *(float2*)(d_qkvs + (size_t)r1 * 512 + col) = o;
            }
        }
    }
}

// ---------------------------------------------------------------------------
// Node-centric attention, algebraically restructured:
//   logit = (q.k + eattr . (We^T q|head)) / sqrt(D)
//   out   = [ Sum ex*v + (Sum ex*eattr) @ We|head ] / Sum ex + skip
// We^T q computed once per node; per-edge edge-work is a 16-dim dot.
// One warp per dst node; lane owns 4 channels; 8-lane group = 1 head;
// within the group, lane position p owns eattr indices {2p, 2p+1}.
// ---------------------------------------------------------------------------
__global__ void __launch_bounds__(128) attn_node(const float* __restrict__ eattr,
                                                 const float* __restrict__ We) {
    const unsigned FULL = 0xffffffffu;
    int warp = (blockIdx.x * 128 + threadIdx.x) >> 5;
    int lane = threadIdx.x & 31;
    if (warp >= NN) return;
    int n = warp;
    int p = lane & 7;          // position in head group
    int gb = lane & 24;        // group base lane

    // We columns for this lane's 4 output channels
    float4 wreg[16];
#pragma unroll
    for (int k = 0; k < 16; k++)
        wreg[k] = __ldg((const float4*)(We + k * 128) + lane);

    float4 q4 = *(const float4*)(d_qkvs + (size_t)n * 512 + lane * 4);

    // ---- w~ = We^T q restricted to this head's 32 channels -------------
    float pk[16];
#pragma unroll
    for (int k = 0; k < 16; k++)
        pk[k] = q4.x * wreg[k].x + q4.y * wreg[k].y +
                q4.z * wreg[k].z + q4.w * wreg[k].w;
    // recursive halving across the 8-lane group: lane p ends with k=2p,2p+1
    float u[8];
#pragma unroll
    for (int i = 0; i < 8; i++) {
        float keep  = (lane & 4) ? pk[i + 8] : pk[i];
        float other = (lane & 4) ? pk[i] : pk[i + 8];
        u[i] = keep + __shfl_xor_sync(FULL, other, 4);
    }
    float w4[4];
#pragma unroll
    for (int i = 0; i < 4; i++) {
        float keep  = (lane & 2) ? u[i + 4] : u[i];
        float other = (lane & 2) ? u[i] : u[i + 4];
        w4[i] = keep + __shfl_xor_sync(FULL, other, 2);
    }
    float z0, z1;
    {
        float k0 = (lane & 1) ? w4[2] : w4[0];
        float o0 = (lane & 1) ? w4[0] : w4[2];
        z0 = k0 + __shfl_xor_sync(FULL, o0, 1);
        float k1 = (lane & 1) ? w4[3] : w4[1];
        float o1 = (lane & 1) ? w4[1] : w4[3];
        z1 = k1 + __shfl_xor_sync(FULL, o1, 1);
    }

    float4 acc = make_float4(0.f, 0.f, 0.f, 0.f);
    float s0a = 0.0f, s1a = 0.0f;   // Sum ex * eattr[2p], [2p+1] (per head)
    float dsum = 0.0f;

    int start = d_start[n];
    int deg = d_deg[n];
    const float SC = 0.17677669529663687f;   // 1/sqrt(32)

    int j = 0;
    for (; j + 1 < deg; j += 2) {
        int e0 = __ldg(&d_perm[start + j]);
        int e1 = __ldg(&d_perm[start + j + 1]);
        int s0 = __ldg(&d_psrc[start + j]);
        int s1 = __ldg(&d_psrc[start + j + 1]);

        float2 ep0 = *(const float2*)(eattr + (size_t)e0 * 16 + 2 * p);
        float2 ep1 = *(const float2*)(eattr + (size_t)e1 * 16 + 2 * p);

        const float* base0 = d_qkvs + (size_t)s0 * 512;
        const float* base1 = d_qkvs + (size_t)s1 * 512;
        float4 k40 = *(const float4*)(base0 + 128 + lane * 4);
        float4 v40 = *(const float4*)(base0 + 256 + lane * 4);
        float4 k41 = *(const float4*)(base1 + 128 + lane * 4);
        float4 v41 = *(const float4*)(base1 + 256 + lane * 4);

        float t0 = q4.x * k40.x + q4.y * k40.y + q4.z * k40.z + q4.w * k40.w +
                   ep0.x * z0 + ep0.y * z1;
        float t1 = q4.x * k41.x + q4.y * k41.y + q4.z * k41.z + q4.w * k41.w +
                   ep1.x * z0 + ep1.y * z1;
        t0 += __shfl_xor_sync(FULL, t0, 1);
        t1 += __shfl_xor_sync(FULL, t1, 1);
        t0 += __shfl_xor_sync(FULL, t0, 2);
        t1 += __shfl_xor_sync(FULL, t1, 2);
        t0 += __shfl_xor_sync(FULL, t0, 4);
        t1 += __shfl_xor_sync(FULL, t1, 4);

        float ex0 = __expf(t0 * SC);
        float ex1 = __expf(t1 * SC);
        dsum += ex0 + ex1;
        acc.x = fmaf(v40.x, ex0, acc.x);  acc.x = fmaf(v41.x, ex1, acc.x);
        acc.y = fmaf(v40.y, ex0, acc.y);  acc.y = fmaf(v41.y, ex1, acc.y);
        acc.z = fmaf(v40.z, ex0, acc.z);  acc.z = fmaf(v41.z, ex1, acc.z);
        acc.w = fmaf(v40.w, ex0, acc.w);  acc.w = fmaf(v41.w, ex1, acc.w);
        s0a = fmaf(ep0.x, ex0, s0a);      s0a = fmaf(ep1.x, ex1, s0a);
        s1a = fmaf(ep0.y, ex0, s1a);      s1a = fmaf(ep1.y, ex1, s1a);
    }

    if (j < deg) {   // tail edge
        int e = __ldg(&d_perm[start + j]);
        int s = __ldg(&d_psrc[start + j]);
        float2 ep = *(const float2*)(eattr + (size_t)e * 16 + 2 * p);
        const float* base = d_qkvs + (size_t)s * 512;
        float4 k4 = *(const float4*)(base + 128 + lane * 4);
        float4 v4 = *(const float4*)(base + 256 + lane * 4);
        float t = q4.x * k4.x + q4.y * k4.y + q4.z * k4.z + q4.w * k4.w +
                  ep.x * z0 + ep.y * z1;
        t += __shfl_xor_sync(FULL, t, 1);
        t += __shfl_xor_sync(FULL, t, 2);
        t += __shfl_xor_sync(FULL, t, 4);
        float ex = __expf(t * SC);
        dsum += ex;
        acc.x = fmaf(v4.x, ex, acc.x);
        acc.y = fmaf(v4.y, ex, acc.y);
        acc.z = fmaf(v4.z, ex, acc.z);
        acc.w = fmaf(v4.w, ex, acc.w);
        s0a = fmaf(ep.x, ex, s0a);
        s1a = fmaf(ep.y, ex, s1a);
    }

    // ---- finalize: numer = acc + S @ We|head; out = numer/dsum + skip --
    float4 num = acc;
#pragma unroll
    for (int i = 0; i < 8; i++) {
        float sa = __shfl_sync(FULL, s0a, gb + i);
        float sb = __shfl_sync(FULL, s1a, gb + i);
        num.x = fmaf(sa, wreg[2 * i].x, num.x); num.x = fmaf(sb, wreg[2 * i + 1].x, num.x);
        num.y = fmaf(sa, wreg[2 * i].y, num.y); num.y = fmaf(sb, wreg[2 * i + 1].y, num.y);
        num.z = fmaf(sa, wreg[2 * i].z, num.z); num.z = fmaf(sb, wreg[2 * i + 1].z, num.z);
        num.w = fmaf(sa, wreg[2 * i].w, num.w); num.w = fmaf(sb, wreg[2 * i + 1].w, num.w);
    }

    float inv = 1.0f / (dsum + 1e-16f);
    float4 sk = *(const float4*)(d_qkvs + (size_t)n * 512 + 384 + lane * 4);
    float4 o;
    o.x = fmaxf(fmaf(num.x, inv, sk.x), 0.0f);
    o.y = fmaxf(fmaf(num.y, inv, sk.y), 0.0f);
    o.z = fmaxf(fmaf(num.z, inv, sk.z), 0.0f);
    o.w = fmaxf(fmaf(num.w, inv, sk.w), 0.0f);
    *(float4*)(d_h + (size_t)n * 128 + lane * 4) = o;
}

// ---------------------------------------------------------------------------
// Output head: logits = h @ Wout + bout; log_softmax. One warp per node.
// ---------------------------------------------------------------------------
__global__ void __launch_bounds__(256) out_kernel(const float* __restrict__ Wout,
                                                  const float* __restrict__ bout,
                                                  float* __restrict__ out) {
    __shared__ float sW[128 * 10];
    __shared__ float sb[10];
    int tid = threadIdx.x;
    for (int i = tid; i < 128 * 10; i += 256) sW[i] = Wout[i];
    if (tid < 10) sb[tid] = bout[tid];
    __syncthreads();

    int warp = (blockIdx.x * 256 + tid) >> 5;
    int lane = tid & 31;
    if (warp >= NN) return;

    float4 hv = *(const float4*)(d_h + (size_t)warp * 128 + lane * 4);
    float lg[10];
#pragma unroll
    for (int c = 0; c < 10; c++) {
        float pp = hv.x * sW[(lane * 4 + 0) * 10 + c] +
                   hv.y * sW[(lane * 4 + 1) * 10 + c] +
                   hv.z * sW[(lane * 4 + 2) * 10 + c] +
                   hv.w * sW[(lane * 4 + 3) * 10 + c];
        pp += __shfl_xor_sync(0xffffffffu, pp, 16);
        pp += __shfl_xor_sync(0xffffffffu, pp, 8);
        pp += __shfl_xor_sync(0xffffffffu, pp, 4);
        pp += __shfl_xor_sync(0xffffffffu, pp, 2);
        pp += __shfl_xor_sync(0xffffffffu, pp, 1);
        lg[c] = pp + sb[c];
    }
    float mx = lg[0];
#pragma unroll
    for (int c = 1; c < 10; c++) mx = fmaxf(mx, lg[c]);
    float ss = 0.0f;
#pragma unroll
    for (int c = 0; c < 10; c++) ss += __expf(lg[c] - mx);
    float lse = mx + logf(ss);
    if (lane == 0) {
#pragma unroll
        for (int c = 0; c < 10; c++)
            out[(size_t)warp * 10 + c] = lg[c] - lse;
    }
}

// ---------------------------------------------------------------------------
// Launch (sgemm at captured launch index 3 for ncu)
// ---------------------------------------------------------------------------
extern "C" void kernel_launch(void* const* d_in, const int* in_sizes, int n_in,
                              void* d_out, int out_size) {
    const float* x     = (const float*)d_in[0];
    const int*   ei    = (const int*)d_in[1];
    const float* eattr = (const float*)d_in[2];
    const float* Wout = (const float*)d_in[21];
    const float* bout = (const float*)d_in[22];
    float* out = (float*)d_out;

    const int* src = ei;       // edge_index[0]
    const int* dst = ei + EE;  // edge_index[1]

    const int PACK_BLKS = (64 * 512 + 255) / 256;
    const int EDGE_BLKS = (EE + 255) / 256;
    const int NODE_BLKS = (NN + 255) / 256;
    const int ATTN_BLKS = (NN * 32 + 127) / 128;
    const int OUT_BLKS  = (NN * 32 + 255) / 256;
    dim3 gemmGrid(4, (NN + 127) / 128);

    const float* W0[9], *W1[9];
    for (int i = 0; i < 9; i++) { W0[i] = (const float*)d_in[3 + i]; W1[i] = (const float*)d_in[12 + i]; }

    // idx0-1: CSR part A
    zero_deg<<<NODE_BLKS, 256>>>();
    hist_kernel<<<EDGE_BLKS, 256>>>(dst);
    // idx2-3: layer0 projections (sgemm at captured launch index 3)
    pack_kernel<<<PACK_BLKS, 256>>>(W0[0], W0[2], W0[4], W0[7], W0[1], W0[3], W0[5], W0[8]);
    sgemm_bf16x3<<<gemmGrid, 256>>>(x, 0, NN);
    // CSR part B
    chunk_sums<<<NCHUNK, 256>>>();
    chunk_offsets<<<1, 256>>>();
    scan_chunks<<<NCHUNK, 256>>>();
    scatter_perm<<<EDGE_BLKS, 256>>>(dst, src);
    // layer0 attention
    attn_node<<<ATTN_BLKS, 128>>>(eattr, W0[6]);
    // layer1
    pack_kernel<<<PACK_BLKS, 256>>>(W1[0], W1[2], W1[4], W1[7], W1[1], W1[3], W1[5], W1[8]);
    sgemm_bf16x3<<<gemmGrid, 256>>>(nullptr, 1, NN);
    attn_node<<<ATTN_BLKS, 128>>>(eattr, W1[6]);
    // head
    out_kernel<<<OUT_BLKS, 256>>>(Wout, bout, out);
}

// round 8
// speedup vs baseline: 2.4696x; 1.0722x over previous
#include <cuda_runtime.h>
#include <cuda_bf16.h>
#include <cstdint>

// Problem constants (fixed by the dataset)
#define NN   50000
#define EE   600000
#define FD   128
#define EDIM 16
#define HH   4
#define DD   32
#define HIDD 128
#define CC   10

#define NCHUNK 196   // ceil(NN/256)

// ---------------------------------------------------------------------------
// Scratch (device globals; allocation-free per harness rules)
// ---------------------------------------------------------------------------
__device__ __align__(16) float d_qkvs[(size_t)NN * 512];   // q|k|v|skip packed per node
__device__ __align__(16) float d_h[(size_t)NN * 128];      // layer output
// B in bf16 hi/lo, FRAGMENT-ordered: [ch(8)][seg(16)][lane(32)][idx(8)]
//   seg=col>>5, lane=(col&7)*4+(kpl&3), idx=(kpl>>2)*4+((col>>3)&3)
__device__ __align__(16) uint32_t d_WfH[8 * 16 * 32 * 8];
__device__ __align__(16) uint32_t d_WfL[8 * 16 * 32 * 8];
__device__ __align__(16) float d_bp[512];

// CSR-by-dst (built once per launch, shared by both layers)
__device__ int d_deg[NN];
__device__ int d_start[NN];
__device__ int d_cursor[NN];
__device__ int d_perm[EE];   // edge id (for eattr)
__device__ int d_psrc[EE];   // permuted src node id
__device__ int d_csums[256];
__device__ int d_coffs[256];

// ---------------------------------------------------------------------------
// Helpers
// ---------------------------------------------------------------------------
__device__ __forceinline__ int warp_incl_scan(int v, int lane) {
#pragma unroll
    for (int o = 1; o < 32; o <<= 1) {
        int n = __shfl_up_sync(0xffffffffu, v, o);
        if (lane >= o) v += n;
    }
    return v;
}

__device__ __forceinline__ void split_bf16x2(float f0, float f1,
                                             uint32_t& hi, uint32_t& lo) {
    __nv_bfloat162 hp = __float22bfloat162_rn(make_float2(f0, f1));
    hi = *reinterpret_cast<uint32_t*>(&hp);
    float r0 = f0 - __low2float(hp);
    float r1 = f1 - __high2float(hp);
    __nv_bfloat162 lp = __float22bfloat162_rn(make_float2(r0, r1));
    lo = *reinterpret_cast<uint32_t*>(&lp);
}

__device__ __forceinline__ uint32_t smem_u32(const void* p) {
    return (uint32_t)__cvta_generic_to_shared(p);
}

// ---------------------------------------------------------------------------
// CSR build
// ---------------------------------------------------------------------------
__global__ void zero_deg() {
    int i = blockIdx.x * blockDim.x + threadIdx.x;
    if (i < NN) d_deg[i] = 0;
}

__global__ void hist_kernel(const int* __restrict__ dst) {
    int e = blockIdx.x * blockDim.x + threadIdx.x;
    if (e < EE) atomicAdd(&d_deg[dst[e]], 1);
}

__global__ void chunk_sums() {
    int tid = threadIdx.x, b = blockIdx.x, i = b * 256 + tid;
    int v = (i < NN) ? d_deg[i] : 0;
#pragma unroll
    for (int o = 16; o > 0; o >>= 1) v += __shfl_xor_sync(0xffffffffu, v, o);
    __shared__ int ws[8];
    if ((tid & 31) == 0) ws[tid >> 5] = v;
    __syncthreads();
    if (tid == 0) {
        int s = 0;
#pragma unroll
        for (int k = 0; k < 8; k++) s += ws[k];
        d_csums[b] = s;
    }
}

__global__ void chunk_offsets() {   // single block, 256 threads
    int tid = threadIdx.x;
    int lane = tid & 31, w = tid >> 5;
    __shared__ int ws[8];
    int v = (tid < NCHUNK) ? d_csums[tid] : 0;
    int incl = warp_incl_scan(v, lane);
    if (lane == 31) ws[w] = incl;
    __syncthreads();
    if (w == 0) {
        int t = (lane < 8) ? ws[lane] : 0;
        t = warp_incl_scan(t, lane);
        if (lane < 8) ws[lane] = t;
    }
    __syncthreads();
    int excl = incl - v + (w > 0 ? ws[w - 1] : 0);
    d_coffs[tid] = excl;
}

__global__ void scan_chunks() {
    int tid = threadIdx.x, b = blockIdx.x, i = b * 256 + tid;
    int lane = tid & 31, w = tid >> 5;
    __shared__ int ws[8];
    int v = (i < NN) ? d_deg[i] : 0;
    int incl = warp_incl_scan(v, lane);
    if (lane == 31) ws[w] = incl;
    __syncthreads();
    if (w == 0) {
        int t = (lane < 8) ? ws[lane] : 0;
        t = warp_incl_scan(t, lane);
        if (lane < 8) ws[lane] = t;
    }
    __syncthreads();
    int excl = incl - v + (w > 0 ? ws[w - 1] : 0) + d_coffs[b];
    if (i < NN) { d_start[i] = excl; d_cursor[i] = excl; }
}

__global__ void scatter_perm(const int* __restrict__ dst, const int* __restrict__ src) {
    int e = blockIdx.x * blockDim.x + threadIdx.x;
    if (e < EE) {
        int pos = atomicAdd(&d_cursor[dst[e]], 1);
        d_perm[pos] = e;
        d_psrc[pos] = src[e];
    }
}

// ---------------------------------------------------------------------------
// Pack weights: bf16 hi/lo split, FRAGMENT order (see d_WfH layout comment)
// ---------------------------------------------------------------------------
__global__ void pack_kernel(const float* __restrict__ Wq, const float* __restrict__ Wk,
                            const float* __restrict__ Wv, const float* __restrict__ Ws,
                            const float* __restrict__ bq, const float* __restrict__ bk,
                            const float* __restrict__ bv, const float* __restrict__ bs) {
    int idx = blockIdx.x * blockDim.x + threadIdx.x;
    if (idx < 64 * 512) {
        int kp = idx >> 9, col = idx & 511;
        int sel = col >> 7, jc = col & 127;
        const float* W = sel == 0 ? Wq : sel == 1 ? Wk : sel == 2 ? Wv : Ws;
        float f0 = W[(2 * kp) * 128 + jc];
        float f1 = W[(2 * kp + 1) * 128 + jc];
        uint32_t hi, lo;
        split_bf16x2(f0, f1, hi, lo);
        int ch = kp >> 3, kpl = kp & 7;
        int kh = kpl >> 2, tg = kpl & 3;
        int seg = col >> 5, g = col & 7, nt = (col >> 3) & 3;
        int off = ((ch * 16 + seg) * 32 + g * 4 + tg) * 8 + kh * 4 + nt;
        d_WfH[off] = hi;
        d_WfL[off] = lo;
    }
    if (idx < 512) {
        int sel = idx >> 7, jc = idx & 127;
        const float* b = sel == 0 ? bq : sel == 1 ? bk : sel == 2 ? bv : bs;
        d_bp[idx] = b[jc];
    }
}

// ---------------------------------------------------------------------------
// bf16x3 tensor-core GEMM, double-buffered, 2 CTAs/SM target.
// B staged via cp.async in fragment order; A staged through regs (needs cvt).
// ---------------------------------------------------------------------------
#define KC 16

__global__ void __launch_bounds__(256, 2) sgemm_bf16x3(const float* __restrict__ x,
                                                       int layer, int M) {
    const float* A = (layer == 0) ? x : (const float*)d_h;

    __shared__ __align__(16) uint32_t AsH[2][128][9];
    __shared__ __align__(16) uint32_t AsL[2][128][9];
    __shared__ __align__(16) uint32_t BfH[2][4][32][8];   // [st][wn][lane][idx]
    __shared__ __align__(16) uint32_t BfL[2][4][32][8];

    int tid = threadIdx.x;
    int bx = blockIdx.x;
    int by = blockIdx.y;
    int warp = tid >> 5, lane = tid & 31;
    int wm = warp >> 2, wn = warp & 3;
    int mbase = wm * 64, nbase = wn * 32;
    int rowBase = by * 128;
    int g = lane >> 2;
    int tg = lane & 3;

    int aR0 = tid >> 2,          aC0 = tid & 3;
    int aR1 = (tid + 256) >> 2,  aC1 = (tid + 256) & 3;

    float c[4][4][4];
#pragma unroll
    for (int i = 0; i < 4; i++)
#pragma unroll
        for (int j = 0; j < 4; j++)
#pragma unroll
            for (int r = 0; r < 4; r++) c[i][j][r] = 0.0f;

    float4 aReg0, aReg1;
    int grA0 = rowBase + aR0, grA1 = rowBase + aR1;
    bool a0OK = (grA0 < M), a1OK = (grA1 < M);

    // cp.async staging addresses for B (16B per thread per H/L per chunk)
    uint32_t sBH0 = smem_u32(&BfH[0][0][0][0]) + tid * 16;
    uint32_t sBL0 = smem_u32(&BfL[0][0][0][0]) + tid * 16;
    const uint32_t* gBH = d_WfH + (size_t)bx * 4 * 256 + tid * 4;
    const uint32_t* gBL = d_WfL + (size_t)bx * 4 * 256 + tid * 4;

    auto stageB = [&](int ch, int st) {
        uint32_t dH = sBH0 + st * 4096;   // 4*32*8*4 bytes per stage
        uint32_t dL = sBL0 + st * 4096;
        const uint32_t* sH = gBH + ch * 4096;   // 16*256 words per chunk
        const uint32_t* sL = gBL + ch * 4096;
        asm volatile("cp.async.ca.shared.global [%0], [%1], 16;" :: "r"(dH), "l"(sH));
        asm volatile("cp.async.ca.shared.global [%0], [%1], 16;" :: "r"(dL), "l"(sL));
        asm volatile("cp.async.commit_group;");
    };

    auto loadA = [&](int ch) {
        int k0 = ch * KC;
        aReg0 = a0OK ? *(const float4*)(A + (size_t)grA0 * 128 + k0 + aC0 * 4)
                     : make_float4(0.f, 0.f, 0.f, 0.f);
        aReg1 = a1OK ? *(const float4*)(A + (size_t)grA1 * 128 + k0 + aC1 * 4)
                     : make_float4(0.f, 0.f, 0.f, 0.f);
    };

    auto storeA = [&](int st) {
        uint32_t h0, l0, h1, l1;
        split_bf16x2(aReg0.x, aReg0.y, h0, l0);
        split_bf16x2(aReg0.z, aReg0.w, h1, l1);
        AsH[st][aR0][2 * aC0] = h0;     AsH[st][aR0][2 * aC0 + 1] = h1;
        AsL[st][aR0][2 * aC0] = l0;     AsL[st][aR0][2 * aC0 + 1] = l1;
        split_bf16x2(aReg1.x, aReg1.y, h0, l0);
        split_bf16x2(aReg1.z, aReg1.w, h1, l1);
        AsH[st][aR1][2 * aC1] = h0;     AsH[st][aR1][2 * aC1 + 1] = h1;
        AsL[st][aR1][2 * aC1] = l0;     AsL[st][aR1][2 * aC1 + 1] = l1;
    };

    auto computeChunk = [&](int st) {
        // B fragments: 4 x LDS.128 (idx 0..3 = kh0/nt0..3, idx 4..7 = kh1)
        uint4 bh0 = *(const uint4*)&BfH[st][wn][lane][0];
        uint4 bh1 = *(const uint4*)&BfH[st][wn][lane][4];
        uint4 bl0 = *(const uint4*)&BfL[st][wn][lane][0];
        uint4 bl1 = *(const uint4*)&BfL[st][wn][lane][4];
        uint32_t bh[4][2] = {{bh0.x, bh1.x}, {bh0.y, bh1.y}, {bh0.z, bh1.z}, {bh0.w, bh1.w}};
        uint32_t bl[4][2] = {{bl0.x, bl1.x}, {bl0.y, bl1.y}, {bl0.z, bl1.z}, {bl0.w, bl1.w}};
#pragma unroll
        for (int mt = 0; mt < 4; mt++) {
            int r = mbase + mt * 16 + g;
            uint32_t ah[4], al[4];
            ah[0] = AsH[st][r][tg];     ah[1] = AsH[st][r + 8][tg];
            ah[2] = AsH[st][r][4 + tg]; ah[3] = AsH[st][r + 8][4 + tg];
            al[0] = AsL[st][r][tg];     al[1] = AsL[st][r + 8][tg];
            al[2] = AsL[st][r][4 + tg]; al[3] = AsL[st][r + 8][4 + tg];
#pragma unroll
            for (int nt = 0; nt < 4; nt++) {
                float* cc = c[mt][nt];
                asm volatile(
                    "mma.sync.aligned.m16n8k16.row.col.f32.bf16.bf16.f32 "
                    "{%0,%1,%2,%3},{%4,%5,%6,%7},{%8,%9},{%0,%1,%2,%3};"
                    : "+f"(cc[0]), "+f"(cc[1]), "+f"(cc[2]), "+f"(cc[3])
                    : "r"(ah[0]), "r"(ah[1]), "r"(ah[2]), "r"(ah[3]),
                      "r"(bh[nt][0]), "r"(bh[nt][1]));
                asm volatile(
                    "mma.sync.aligned.m16n8k16.row.col.f32.bf16.bf16.f32 "
                    "{%0,%1,%2,%3},{%4,%5,%6,%7},{%8,%9},{%0,%1,%2,%3};"
                    : "+f"(cc[0]), "+f"(cc[1]), "+f"(cc[2]), "+f"(cc[3])
                    : "r"(ah[0]), "r"(ah[1]), "r"(ah[2]), "r"(ah[3]),
                      "r"(bl[nt][0]), "r"(bl[nt][1]));
                asm volatile(
                    "mma.sync.aligned.m16n8k16.row.col.f32.bf16.bf16.f32 "
                    "{%0,%1,%2,%3},{%4,%5,%6,%7},{%8,%9},{%0,%1,%2,%3};"
                    : "+f"(cc[0]), "+f"(cc[1]), "+f"(cc[2]), "+f"(cc[3])
                    : "r"(al[0]), "r"(al[1]), "r"(al[2]), "r"(al[3]),
                      "r"(bh[nt][0]), "r"(bh[nt][1]));
            }
        }
    };

    // ---- pipelined mainloop ----
    stageB(0, 0);
    loadA(0);
    storeA(0);
    asm volatile("cp.async.wait_group 0;" ::: "memory");
    __syncthreads();
#pragma unroll
    for (int ch = 0; ch < 8; ch++) {
        int cur = ch & 1;
        if (ch < 7) {
            loadA(ch + 1);
            stageB(ch + 1, cur ^ 1);
        }
        computeChunk(cur);
        if (ch < 7) {
            storeA(cur ^ 1);
            asm volatile("cp.async.wait_group 0;" ::: "memory");
            __syncthreads();
        }
    }

    // epilogue: bias add, write to d_qkvs
#pragma unroll
    for (int mt = 0; mt < 4; mt++) {
        int r0 = rowBase + mbase + mt * 16 + g;
        int r1 = r0 + 8;
#pragma unroll
        for (int nt = 0; nt < 4; nt++) {
            int col = bx * 128 + nbase + nt * 8 + 2 * tg;
            float2 b2 = *(const float2*)(d_bp + col);
            if (r0 < M) {
                float2 o = make_float2(c[mt][nt][0] + b2.x, c[mt][nt][1] + b2.y);
                *(float2*)(d_qkvs + (size_t)r0 * 512 + col) = o;
            }
            if (r1 < M) {
                float2 o = make_float2(c[mt][nt][2] + b2.x, c[mt][nt][3] + b2.y);
                *(float2*)(d_qkvs + (size_t)r1 * 512 + col) = o;
            }
        }
    }
}

// ---------------------------------------------------------------------------
// Node-centric attention (R6 algebraic form, unchanged)
// ---------------------------------------------------------------------------
__global__ void __launch_bounds__(128) attn_node(const float* __restrict__ eattr,
                                                 const float* __restrict__ We) {
    const unsigned FULL = 0xffffffffu;
    int warp = (blockIdx.x * 128 + threadIdx.x) >> 5;
    int lane = threadIdx.x & 31;
    if (warp >= NN) return;
    int n = warp;
    int p = lane & 7;
    int gb = lane & 24;

    float4 wreg[16];
#pragma unroll
    for (int k = 0; k < 16; k++)
        wreg[k] = __ldg((const float4*)(We + k * 128) + lane);

    float4 q4 = *(const float4*)(d_qkvs + (size_t)n * 512 + lane * 4);

    float pk[16];
#pragma unroll
    for (int k = 0; k < 16; k++)
        pk[k] = q4.x * wreg[k].x + q4.y * wreg[k].y +
                q4.z * wreg[k].z + q4.w * wreg[k].w;
    float u[8];
#pragma unroll
    for (int i = 0; i < 8; i++) {
        float keep  = (lane & 4) ? pk[i + 8] : pk[i];
        float other = (lane & 4) ? pk[i] : pk[i + 8];
        u[i] = keep + __shfl_xor_sync(FULL, other, 4);
    }
    float w4[4];
#pragma unroll
    for (int i = 0; i < 4; i++) {
        float keep  = (lane & 2) ? u[i + 4] : u[i];
        float other = (lane & 2) ? u[i] : u[i + 4];
        w4[i] = keep + __shfl_xor_sync(FULL, other, 2);
    }
    float z0, z1;
    {
        float k0 = (lane & 1) ? w4[2] : w4[0];
        float o0 = (lane & 1) ? w4[0] : w4[2];
        z0 = k0 + __shfl_xor_sync(FULL, o0, 1);
        float k1 = (lane & 1) ? w4[3] : w4[1];
        float o1 = (lane & 1) ? w4[1] : w4[3];
        z1 = k1 + __shfl_xor_sync(FULL, o1, 1);
    }

    float4 acc = make_float4(0.f, 0.f, 0.f, 0.f);
    float s0a = 0.0f, s1a = 0.0f;
    float dsum = 0.0f;

    int start = d_start[n];
    int deg = d_deg[n];
    const float SC = 0.17677669529663687f;

    int j = 0;
    for (; j + 1 < deg; j += 2) {
        int e0 = __ldg(&d_perm[start + j]);
        int e1 = __ldg(&d_perm[start + j + 1]);
        int s0 = __ldg(&d_psrc[start + j]);
        int s1 = __ldg(&d_psrc[start + j + 1]);

        float2 ep0 = *(const float2*)(eattr + (size_t)e0 * 16 + 2 * p);
        float2 ep1 = *(const float2*)(eattr + (size_t)e1 * 16 + 2 * p);

        const float* base0 = d_qkvs + (size_t)s0 * 512;
        const float* base1 = d_qkvs + (size_t)s1 * 512;
        float4 k40 = *(const float4*)(base0 + 128 + lane * 4);
        float4 v40 = *(const float4*)(base0 + 256 + lane * 4);
        float4 k41 = *(const float4*)(base1 + 128 + lane * 4);
        float4 v41 = *(const float4*)(base1 + 256 + lane * 4);

        float t0 = q4.x * k40.x + q4.y * k40.y + q4.z * k40.z + q4.w * k40.w +
                   ep0.x * z0 + ep0.y * z1;
        float t1 = q4.x * k41.x + q4.y * k41.y + q4.z * k41.z + q4.w * k41.w +
                   ep1.x * z0 + ep1.y * z1;
        t0 += __shfl_xor_sync(FULL, t0, 1);
        t1 += __shfl_xor_sync(FULL, t1, 1);
        t0 += __shfl_xor_sync(FULL, t0, 2);
        t1 += __shfl_xor_sync(FULL, t1, 2);
        t0 += __shfl_xor_sync(FULL, t0, 4);
        t1 += __shfl_xor_sync(FULL, t1, 4);

        float ex0 = __expf(t0 * SC);
        float ex1 = __expf(t1 * SC);
        dsum += ex0 + ex1;
        acc.x = fmaf(v40.x, ex0, acc.x);  acc.x = fmaf(v41.x, ex1, acc.x);
        acc.y = fmaf(v40.y, ex0, acc.y);  acc.y = fmaf(v41.y, ex1, acc.y);
        acc.z = fmaf(v40.z, ex0, acc.z);  acc.z = fmaf(v41.z, ex1, acc.z);
        acc.w = fmaf(v40.w, ex0, acc.w);  acc.w = fmaf(v41.w, ex1, acc.w);
        s0a = fmaf(ep0.x, ex0, s0a);      s0a = fmaf(ep1.x, ex1, s0a);
        s1a = fmaf(ep0.y, ex0, s1a);      s1a = fmaf(ep1.y, ex1, s1a);
    }

    if (j < deg) {
        int e = __ldg(&d_perm[start + j]);
        int s = __ldg(&d_psrc[start + j]);
        float2 ep = *(const float2*)(eattr + (size_t)e * 16 + 2 * p);
        const float* base = d_qkvs + (size_t)s * 512;
        float4 k4 = *(const float4*)(base + 128 + lane * 4);
        float4 v4 = *(const float4*)(base + 256 + lane * 4);
        float t = q4.x * k4.x + q4.y * k4.y + q4.z * k4.z + q4.w * k4.w +
                  ep.x * z0 + ep.y * z1;
        t += __shfl_xor_sync(FULL, t, 1);
        t += __shfl_xor_sync(FULL, t, 2);
        t += __shfl_xor_sync(FULL, t, 4);
        float ex = __expf(t * SC);
        dsum += ex;
        acc.x = fmaf(v4.x, ex, acc.x);
        acc.y = fmaf(v4.y, ex, acc.y);
        acc.z = fmaf(v4.z, ex, acc.z);
        acc.w = fmaf(v4.w, ex, acc.w);
        s0a = fmaf(ep.x, ex, s0a);
        s1a = fmaf(ep.y, ex, s1a);
    }

    float4 num = acc;
#pragma unroll
    for (int i = 0; i < 8; i++) {
        float sa = __shfl_sync(FULL, s0a, gb + i);
        float sb = __shfl_sync(FULL, s1a, gb + i);
        num.x = fmaf(sa, wreg[2 * i].x, num.x); num.x = fmaf(sb, wreg[2 * i + 1].x, num.x);
        num.y = fmaf(sa, wreg[2 * i].y, num.y); num.y = fmaf(sb, wreg[2 * i + 1].y, num.y);
        num.z = fmaf(sa, wreg[2 * i].z, num.z); num.z = fmaf(sb, wreg[2 * i + 1].z, num.z);
        num.w = fmaf(sa, wreg[2 * i].w, num.w); num.w = fmaf(sb, wreg[2 * i + 1].w, num.w);
    }

    float inv = 1.0f / (dsum + 1e-16f);
    float4 sk = *(const float4*)(d_qkvs + (size_t)n * 512 + 384 + lane * 4);
    float4 o;
    o.x = fmaxf(fmaf(num.x, inv, sk.x), 0.0f);
    o.y = fmaxf(fmaf(num.y, inv, sk.y), 0.0f);
    o.z = fmaxf(fmaf(num.z, inv, sk.z), 0.0f);
    o.w = fmaxf(fmaf(num.w, inv, sk.w), 0.0f);
    *(float4*)(d_h + (size_t)n * 128 + lane * 4) = o;
}

// ---------------------------------------------------------------------------
// Output head: logits = h @ Wout + bout; log_softmax. One warp per node.
// ---------------------------------------------------------------------------
__global__ void __launch_bounds__(256) out_kernel(const float* __restrict__ Wout,
                                                  const float* __restrict__ bout,
                                                  float* __restrict__ out) {
    __shared__ float sW[128 * 10];
    __shared__ float sb[10];
    int tid = threadIdx.x;
    for (int i = tid; i < 128 * 10; i += 256) sW[i] = Wout[i];
    if (tid < 10) sb[tid] = bout[tid];
    __syncthreads();

    int warp = (blockIdx.x * 256 + tid) >> 5;
    int lane = tid & 31;
    if (warp >= NN) return;

    float4 hv = *(const float4*)(d_h + (size_t)warp * 128 + lane * 4);
    float lg[10];
#pragma unroll
    for (int c = 0; c < 10; c++) {
        float pp = hv.x * sW[(lane * 4 + 0) * 10 + c] +
                   hv.y * sW[(lane * 4 + 1) * 10 + c] +
                   hv.z * sW[(lane * 4 + 2) * 10 + c] +
                   hv.w * sW[(lane * 4 + 3) * 10 + c];
        pp += __shfl_xor_sync(0xffffffffu, pp, 16);
        pp += __shfl_xor_sync(0xffffffffu, pp, 8);
        pp += __shfl_xor_sync(0xffffffffu, pp, 4);
        pp += __shfl_xor_sync(0xffffffffu, pp, 2);
        pp += __shfl_xor_sync(0xffffffffu, pp, 1);
        lg[c] = pp + sb[c];
    }
    float mx = lg[0];
#pragma unroll
    for (int c = 1; c < 10; c++) mx = fmaxf(mx, lg[c]);
    float ss = 0.0f;
#pragma unroll
    for (int c = 0; c < 10; c++) ss += __expf(lg[c] - mx);
    float lse = mx + logf(ss);
    if (lane == 0) {
#pragma unroll
        for (int c = 0; c < 10; c++)
            out[(size_t)warp * 10 + c] = lg[c] - lse;
    }
}

// ---------------------------------------------------------------------------
// Launch (sgemm at captured launch index 3 for ncu)
// ---------------------------------------------------------------------------
extern "C" void kernel_launch(void* const* d_in, const int* in_sizes, int n_in,
                              void* d_out, int out_size) {
    const float* x     = (const float*)d_in[0];
    const int*   ei    = (const int*)d_in[1];
    const float* eattr = (const float*)d_in[2];
    const float* Wout = (const float*)d_in[21];
    const float* bout = (const float*)d_in[22];
    float* out = (float*)d_out;

    const int* src = ei;       // edge_index[0]
    const int* dst = ei + EE;  // edge_index[1]

    const int PACK_BLKS = (64 * 512 + 255) / 256;
    const int EDGE_BLKS = (EE + 255) / 256;
    const int NODE_BLKS = (NN + 255) / 256;
    const int ATTN_BLKS = (NN * 32 + 127) / 128;
    const int OUT_BLKS  = (NN * 32 + 255) / 256;
    dim3 gemmGrid(4, (NN + 127) / 128);

    const float* W0[9], *W1[9];
    for (int i = 0; i < 9; i++) { W0[i] = (const float*)d_in[3 + i]; W1[i] = (const float*)d_in[12 + i]; }

    // idx0-1: CSR part A
    zero_deg<<<NODE_BLKS, 256>>>();
    hist_kernel<<<EDGE_BLKS, 256>>>(dst);
    // idx2-3: layer0 projections (sgemm at captured launch index 3)
    pack_kernel<<<PACK_BLKS, 256>>>(W0[0], W0[2], W0[4], W0[7], W0[1], W0[3], W0[5], W0[8]);
    sgemm_bf16x3<<<gemmGrid, 256>>>(x, 0, NN);
    // CSR part B
    chunk_sums<<<NCHUNK, 256>>>();
    chunk_offsets<<<1, 256>>>();
    scan_chunks<<<NCHUNK, 256>>>();
    scatter_perm<<<EDGE_BLKS, 256>>>(dst, src);
    // layer0 attention
    attn_node<<<ATTN_BLKS, 128>>>(eattr, W0[6]);
    // layer1
    pack_kernel<<<PACK_BLKS, 256>>>(W1[0], W1[2], W1[4], W1[7], W1[1], W1[3], W1[5], W1[8]);
    sgemm_bf16x3<<<gemmGrid, 256>>>(nullptr, 1, NN);
    attn_node<<<ATTN_BLKS, 128>>>(eattr, W1[6]);
    // head
    out_kernel<<<OUT_BLKS, 256>>>(Wout, bout, out);
}

// round 10
// speedup vs baseline: 2.6257x; 1.0632x over previous
#include <cuda_runtime.h>
#include <cuda_bf16.h>
#include <cstdint>

// Problem constants (fixed by the dataset)
#define NN   50000
#define EE   600000
#define FD   128
#define EDIM 16
#define HH   4
#define DD   32
#define HIDD 128
#define CC   10

#define NCHUNK 196   // ceil(NN/256)

// ---------------------------------------------------------------------------
// Scratch (device globals; allocation-free per harness rules)
// ---------------------------------------------------------------------------
__device__ __align__(16) float d_qkvs[(size_t)NN * 512];   // q|k|v|skip packed per node
__device__ __align__(16) float d_h[(size_t)NN * 128];      // layer output
// B in bf16 hi/lo, FRAGMENT-ordered: [ch(8)][seg(16)][lane(32)][idx(8)]
__device__ __align__(16) uint32_t d_WfH[8 * 16 * 32 * 8];
__device__ __align__(16) uint32_t d_WfL[8 * 16 * 32 * 8];
__device__ __align__(16) float d_bp[512];

// CSR-by-dst (built once per launch, shared by both layers)
__device__ int d_deg[NN];
__device__ int d_start[NN];
__device__ int d_cursor[NN];
__device__ int2 d_edge[EE];  // (edge id, src node) permuted by dst
__device__ int d_csums[256];
__device__ int d_coffs[256];

// ---------------------------------------------------------------------------
// Helpers
// ---------------------------------------------------------------------------
__device__ __forceinline__ int warp_incl_scan(int v, int lane) {
#pragma unroll
    for (int o = 1; o < 32; o <<= 1) {
        int n = __shfl_up_sync(0xffffffffu, v, o);
        if (lane >= o) v += n;
    }
    return v;
}

__device__ __forceinline__ void split_bf16x2(float f0, float f1,
                                             uint32_t& hi, uint32_t& lo) {
    __nv_bfloat162 hp = __float22bfloat162_rn(make_float2(f0, f1));
    hi = *reinterpret_cast<uint32_t*>(&hp);
    float r0 = f0 - __low2float(hp);
    float r1 = f1 - __high2float(hp);
    __nv_bfloat162 lp = __float22bfloat162_rn(make_float2(r0, r1));
    lo = *reinterpret_cast<uint32_t*>(&lp);
}

__device__ __forceinline__ uint32_t smem_u32(const void* p) {
    return (uint32_t)__cvta_generic_to_shared(p);
}

// ---------------------------------------------------------------------------
// CSR build
// ---------------------------------------------------------------------------
__global__ void zero_deg() {
    int i = blockIdx.x * blockDim.x + threadIdx.x;
    if (i < NN) d_deg[i] = 0;
}

__global__ void hist_kernel(const int* __restrict__ dst) {
    int e = blockIdx.x * blockDim.x + threadIdx.x;
    if (e < EE) atomicAdd(&d_deg[dst[e]], 1);
}

__global__ void chunk_sums() {
    int tid = threadIdx.x, b = blockIdx.x, i = b * 256 + tid;
    int v = (i < NN) ? d_deg[i] : 0;
#pragma unroll
    for (int o = 16; o > 0; o >>= 1) v += __shfl_xor_sync(0xffffffffu, v, o);
    __shared__ int ws[8];
    if ((tid & 31) == 0) ws[tid >> 5] = v;
    __syncthreads();
    if (tid == 0) {
        int s = 0;
#pragma unroll
        for (int k = 0; k < 8; k++) s += ws[k];
        d_csums[b] = s;
    }
}

__global__ void chunk_offsets() {   // single block, 256 threads
    int tid = threadIdx.x;
    int lane = tid & 31, w = tid >> 5;
    __shared__ int ws[8];
    int v = (tid < NCHUNK) ? d_csums[tid] : 0;
    int incl = warp_incl_scan(v, lane);
    if (lane == 31) ws[w] = incl;
    __syncthreads();
    if (w == 0) {
        int t = (lane < 8) ? ws[lane] : 0;
        t = warp_incl_scan(t, lane);
        if (lane < 8) ws[lane] = t;
    }
    __syncthreads();
    int excl = incl - v + (w > 0 ? ws[w - 1] : 0);
    d_coffs[tid] = excl;
}

__global__ void scan_chunks() {
    int tid = threadIdx.x, b = blockIdx.x, i = b * 256 + tid;
    int lane = tid & 31, w = tid >> 5;
    __shared__ int ws[8];
    int v = (i < NN) ? d_deg[i] : 0;
    int incl = warp_incl_scan(v, lane);
    if (lane == 31) ws[w] = incl;
    __syncthreads();
    if (w == 0) {
        int t = (lane < 8) ? ws[lane] : 0;
        t = warp_incl_scan(t, lane);
        if (lane < 8) ws[lane] = t;
    }
    __syncthreads();
    int excl = incl - v + (w > 0 ? ws[w - 1] : 0) + d_coffs[b];
    if (i < NN) { d_start[i] = excl; d_cursor[i] = excl; }
}

__global__ void scatter_perm(const int* __restrict__ dst, const int* __restrict__ src) {
    int e = blockIdx.x * blockDim.x + threadIdx.x;
    if (e < EE) {
        int pos = atomicAdd(&d_cursor[dst[e]], 1);
        d_edge[pos] = make_int2(e, src[e]);
    }
}

// ---------------------------------------------------------------------------
// Pack weights: bf16 hi/lo split, FRAGMENT order
// ---------------------------------------------------------------------------
__global__ void pack_kernel(const float* __restrict__ Wq, const float* __restrict__ Wk,
                            const float* __restrict__ Wv, const float* __restrict__ Ws,
                            const float* __restrict__ bq, const float* __restrict__ bk,
                            const float* __restrict__ bv, const float* __restrict__ bs) {
    int idx = blockIdx.x * blockDim.x + threadIdx.x;
    if (idx < 64 * 512) {
        int kp = idx >> 9, col = idx & 511;
        int sel = col >> 7, jc = col & 127;
        const float* W = sel == 0 ? Wq : sel == 1 ? Wk : sel == 2 ? Wv : Ws;
        float f0 = W[(2 * kp) * 128 + jc];
        float f1 = W[(2 * kp + 1) * 128 + jc];
        uint32_t hi, lo;
        split_bf16x2(f0, f1, hi, lo);
        int ch = kp >> 3, kpl = kp & 7;
        int kh = kpl >> 2, tg = kpl & 3;
        int seg = col >> 5, g = col & 7, nt = (col >> 3) & 3;
        int off = ((ch * 16 + seg) * 32 + g * 4 + tg) * 8 + kh * 4 + nt;
        d_WfH[off] = hi;
        d_WfL[off] = lo;
    }
    if (idx < 512) {
        int sel = idx >> 7, jc = idx & 127;
        const float* b = sel == 0 ? bq : sel == 1 ? bk : sel == 2 ? bv : bs;
        d_bp[idx] = b[jc];
    }
}

// ---------------------------------------------------------------------------
// bf16x3 tensor-core GEMM (R7 known-good: cp.async B, 2 CTAs/SM)
// ---------------------------------------------------------------------------
#define KC 16

__global__ void __launch_bounds__(256, 2) sgemm_bf16x3(const float* __restrict__ x,
                                                       int layer, int M) {
    const float* A = (layer == 0) ? x : (const float*)d_h;

    __shared__ __align__(16) uint32_t AsH[2][128][9];
    __shared__ __align__(16) uint32_t AsL[2][128][9];
    __shared__ __align__(16) uint32_t BfH[2][4][32][8];
    __shared__ __align__(16) uint32_t BfL[2][4][32][8];

    int tid = threadIdx.x;
    int bx = blockIdx.x;
    int by = blockIdx.y;
    int warp = tid >> 5, lane = tid & 31;
    int wm = warp >> 2, wn = warp & 3;
    int mbase = wm * 64, nbase = wn * 32;
    int rowBase = by * 128;
    int g = lane >> 2;
    int tg = lane & 3;

    int aR0 = tid >> 2,          aC0 = tid & 3;
    int aR1 = (tid + 256) >> 2,  aC1 = (tid + 256) & 3;

    float c[4][4][4];
#pragma unroll
    for (int i = 0; i < 4; i++)
#pragma unroll
        for (int j = 0; j < 4; j++)
#pragma unroll
            for (int r = 0; r < 4; r++) c[i][j][r] = 0.0f;

    float4 aReg0, aReg1;
    int grA0 = rowBase + aR0, grA1 = rowBase + aR1;
    bool a0OK = (grA0 < M), a1OK = (grA1 < M);

    uint32_t sBH0 = smem_u32(&BfH[0][0][0][0]) + tid * 16;
    uint32_t sBL0 = smem_u32(&BfL[0][0][0][0]) + tid * 16;
    const uint32_t* gBH = d_WfH + (size_t)bx * 4 * 256 + tid * 4;
    const uint32_t* gBL = d_WfL + (size_t)bx * 4 * 256 + tid * 4;

    auto stageB = [&](int ch, int st) {
        uint32_t dH = sBH0 + st * 4096;
        uint32_t dL = sBL0 + st * 4096;
        const uint32_t* sH = gBH + ch * 4096;
        const uint32_t* sL = gBL + ch * 4096;
        asm volatile("cp.async.ca.shared.global [%0], [%1], 16;" :: "r"(dH), "l"(sH));
        asm volatile("cp.async.ca.shared.global [%0], [%1], 16;" :: "r"(dL), "l"(sL));
        asm volatile("cp.async.commit_group;");
    };

    auto loadA = [&](int ch) {
        int k0 = ch * KC;
        aReg0 = a0OK ? *(const float4*)(A + (size_t)grA0 * 128 + k0 + aC0 * 4)
                     : make_float4(0.f, 0.f, 0.f, 0.f);
        aReg1 = a1OK ? *(const float4*)(A + (size_t)grA1 * 128 + k0 + aC1 * 4)
                     : make_float4(0.f, 0.f, 0.f, 0.f);
    };

    auto storeA = [&](int st) {
        uint32_t h0, l0, h1, l1;
        split_bf16x2(aReg0.x, aReg0.y, h0, l0);
        split_bf16x2(aReg0.z, aReg0.w, h1, l1);
        AsH[st][aR0][2 * aC0] = h0;     AsH[st][aR0][2 * aC0 + 1] = h1;
        AsL[st][aR0][2 * aC0] = l0;     AsL[st][aR0][2 * aC0 + 1] = l1;
        split_bf16x2(aReg1.x, aReg1.y, h0, l0);
        split_bf16x2(aReg1.z, aReg1.w, h1, l1);
        AsH[st][aR1][2 * aC1] = h0;     AsH[st][aR1][2 * aC1 + 1] = h1;
        AsL[st][aR1][2 * aC1] = l0;     AsL[st][aR1][2 * aC1 + 1] = l1;
    };

    auto computeChunk = [&](int st) {
        uint4 bh0 = *(const uint4*)&BfH[st][wn][lane][0];
        uint4 bh1 = *(const uint4*)&BfH[st][wn][lane][4];
        uint4 bl0 = *(const uint4*)&BfL[st][wn][lane][0];
        uint4 bl1 = *(const uint4*)&BfL[st][wn][lane][4];
        uint32_t bh[4][2] = {{bh0.x, bh1.x}, {bh0.y, bh1.y}, {bh0.z, bh1.z}, {bh0.w, bh1.w}};
        uint32_t bl[4][2] = {{bl0.x, bl1.x}, {bl0.y, bl1.y}, {bl0.z, bl1.z}, {bl0.w, bl1.w}};
#pragma unroll
        for (int mt = 0; mt < 4; mt++) {
            int r = mbase + mt * 16 + g;
            uint32_t ah[4], al[4];
            ah[0] = AsH[st][r][tg];     ah[1] = AsH[st][r + 8][tg];
            ah[2] = AsH[st][r][4 + tg]; ah[3] = AsH[st][r + 8][4 + tg];
            al[0] = AsL[st][r][tg];     al[1] = AsL[st][r + 8][tg];
            al[2] = AsL[st][r][4 + tg]; al[3] = AsL[st][r + 8][4 + tg];
#pragma unroll
            for (int nt = 0; nt < 4; nt++) {
                float* cc = c[mt][nt];
                asm volatile(
                    "mma.sync.aligned.m16n8k16.row.col.f32.bf16.bf16.f32 "
                    "{%0,%1,%2,%3},{%4,%5,%6,%7},{%8,%9},{%0,%1,%2,%3};"
                    : "+f"(cc[0]), "+f"(cc[1]), "+f"(cc[2]), "+f"(cc[3])
                    : "r"(ah[0]), "r"(ah[1]), "r"(ah[2]), "r"(ah[3]),
                      "r"(bh[nt][0]), "r"(bh[nt][1]));
                asm volatile(
                    "mma.sync.aligned.m16n8k16.row.col.f32.bf16.bf16.f32 "
                    "{%0,%1,%2,%3},{%4,%5,%6,%7},{%8,%9},{%0,%1,%2,%3};"
                    : "+f"(cc[0]), "+f"(cc[1]), "+f"(cc[2]), "+f"(cc[3])
                    : "r"(ah[0]), "r"(ah[1]), "r"(ah[2]), "r"(ah[3]),
                      "r"(bl[nt][0]), "r"(bl[nt][1]));
                asm volatile(
                    "mma.sync.aligned.m16n8k16.row.col.f32.bf16.bf16.f32 "
                    "{%0,%1,%2,%3},{%4,%5,%6,%7},{%8,%9},{%0,%1,%2,%3};"
                    : "+f"(cc[0]), "+f"(cc[1]), "+f"(cc[2]), "+f"(cc[3])
                    : "r"(al[0]), "r"(al[1]), "r"(al[2]), "r"(al[3]),
                      "r"(bh[nt][0]), "r"(bh[nt][1]));
            }
        }
    };

    stageB(0, 0);
    loadA(0);
    storeA(0);
    asm volatile("cp.async.wait_group 0;" ::: "memory");
    __syncthreads();
#pragma unroll
    for (int ch = 0; ch < 8; ch++) {
        int cur = ch & 1;
        if (ch < 7) {
            loadA(ch + 1);
            stageB(ch + 1, cur ^ 1);
        }
        computeChunk(cur);
        if (ch < 7) {
            storeA(cur ^ 1);
            asm volatile("cp.async.wait_group 0;" ::: "memory");
            __syncthreads();
        }
    }

#pragma unroll
    for (int mt = 0; mt < 4; mt++) {
        int r0 = rowBase + mbase + mt * 16 + g;
        int r1 = r0 + 8;
#pragma unroll
        for (int nt = 0; nt < 4; nt++) {
            int col = bx * 128 + nbase + nt * 8 + 2 * tg;
            float2 b2 = *(const float2*)(d_bp + col);
            if (r0 < M) {
                float2 o = make_float2(c[mt][nt][0] + b2.x, c[mt][nt][1] + b2.y);
                *(float2*)(d_qkvs + (size_t)r0 * 512 + col) = o;
            }
            if (r1 < M) {
                float2 o = make_float2(c[mt][nt][2] + b2.x, c[mt][nt][3] + b2.y);
                *(float2*)(d_qkvs + (size_t)r1 * 512 + col) = o;
            }
        }
    }
}

// ---------------------------------------------------------------------------
// Node-centric attention: algebraic form + int2 edge array + 4-wide unroll
// ---------------------------------------------------------------------------
__global__ void __launch_bounds__(128) attn_node(const float* __restrict__ eattr,
                                                 const float* __restrict__ We) {
    const unsigned FULL = 0xffffffffu;
    int warp = (blockIdx.x * 128 + threadIdx.x) >> 5;
    int lane = threadIdx.x & 31;
    if (warp >= NN) return;
    int n = warp;
    int p = lane & 7;
    int gb = lane & 24;

    float4 wreg[16];
#pragma unroll
    for (int k = 0; k < 16; k++)
        wreg[k] = __ldg((const float4*)(We + k * 128) + lane);

    float4 q4 = *(const float4*)(d_qkvs + (size_t)n * 512 + lane * 4);

    // w~ = We^T q restricted to this head
    float pk[16];
#pragma unroll
    for (int k = 0; k < 16; k++)
        pk[k] = q4.x * wreg[k].x + q4.y * wreg[k].y +
                q4.z * wreg[k].z + q4.w * wreg[k].w;
    float u[8];
#pragma unroll
    for (int i = 0; i < 8; i++) {
        float keep  = (lane & 4) ? pk[i + 8] : pk[i];
        float other = (lane & 4) ? pk[i] : pk[i + 8];
        u[i] = keep + __shfl_xor_sync(FULL, other, 4);
    }
    float w4[4];
#pragma unroll
    for (int i = 0; i < 4; i++) {
        float keep  = (lane & 2) ? u[i + 4] : u[i];
        float other = (lane & 2) ? u[i] : u[i + 4];
        w4[i] = keep + __shfl_xor_sync(FULL, other, 2);
    }
    float z0, z1;
    {
        float k0 = (lane & 1) ? w4[2] : w4[0];
        float o0 = (lane & 1) ? w4[0] : w4[2];
        z0 = k0 + __shfl_xor_sync(FULL, o0, 1);
        float k1 = (lane & 1) ? w4[3] : w4[1];
        float o1 = (lane & 1) ? w4[1] : w4[3];
        z1 = k1 + __shfl_xor_sync(FULL, o1, 1);
    }

    float4 acc = make_float4(0.f, 0.f, 0.f, 0.f);
    float s0a = 0.0f, s1a = 0.0f;
    float dsum = 0.0f;

    int start = d_start[n];
    int deg = d_deg[n];
    const float SC = 0.17677669529663687f;

    int j = 0;
    for (; j + 3 < deg; j += 4) {
        int2 ed0 = __ldg(&d_edge[start + j]);
        int2 ed1 = __ldg(&d_edge[start + j + 1]);
        int2 ed2 = __ldg(&d_edge[start + j + 2]);
        int2 ed3 = __ldg(&d_edge[start + j + 3]);

        float2 ep0 = *(const float2*)(eattr + (size_t)ed0.x * 16 + 2 * p);
        float2 ep1 = *(const float2*)(eattr + (size_t)ed1.x * 16 + 2 * p);
        float2 ep2 = *(const float2*)(eattr + (size_t)ed2.x * 16 + 2 * p);
        float2 ep3 = *(const float2*)(eattr + (size_t)ed3.x * 16 + 2 * p);

        const float* b0 = d_qkvs + (size_t)ed0.y * 512;
        const float* b1 = d_qkvs + (size_t)ed1.y * 512;
        const float* b2 = d_qkvs + (size_t)ed2.y * 512;
        const float* b3 = d_qkvs + (size_t)ed3.y * 512;
        float4 k40 = *(const float4*)(b0 + 128 + lane * 4);
        float4 k41 = *(const float4*)(b1 + 128 + lane * 4);
        float4 k42 = *(const float4*)(b2 + 128 + lane * 4);
        float4 k43 = *(const float4*)(b3 + 128 + lane * 4);
        float4 v40 = *(const float4*)(b0 + 256 + lane * 4);
        float4 v41 = *(const float4*)(b1 + 256 + lane * 4);
        float4 v42 = *(const float4*)(b2 + 256 + lane * 4);
        float4 v43 = *(const float4*)(b3 + 256 + lane * 4);

        float t0 = q4.x * k40.x + q4.y * k40.y + q4.z * k40.z + q4.w * k40.w +
                   ep0.x * z0 + ep0.y * z1;
        float t1 = q4.x * k41.x + q4.y * k41.y + q4.z * k41.z + q4.w * k41.w +
                   ep1.x * z0 + ep1.y * z1;
        float t2 = q4.x * k42.x + q4.y * k42.y + q4.z * k42.z + q4.w * k42.w +
                   ep2.x * z0 + ep2.y * z1;
        float t3 = q4.x * k43.x + q4.y * k43.y + q4.z * k43.z + q4.w * k43.w +
                   ep3.x * z0 + ep3.y * z1;
        t0 += __shfl_xor_sync(FULL, t0, 1);
        t1 += __shfl_xor_sync(FULL, t1, 1);
        t2 += __shfl_xor_sync(FULL, t2, 1);
        t3 += __shfl_xor_sync(FULL, t3, 1);
        t0 += __shfl_xor_sync(FULL, t0, 2);
        t1 += __shfl_xor_sync(FULL, t1, 2);
        t2 += __shfl_xor_sync(FULL, t2, 2);
        t3 += __shfl_xor_sync(FULL, t3, 2);
        t0 += __shfl_xor_sync(FULL, t0, 4);
        t1 += __shfl_xor_sync(FULL, t1, 4);
        t2 += __shfl_xor_sync(FULL, t2, 4);
        t3 += __shfl_xor_sync(FULL, t3, 4);

        float ex0 = __expf(t0 * SC);
        float ex1 = __expf(t1 * SC);
        float ex2 = __expf(t2 * SC);
        float ex3 = __expf(t3 * SC);
        dsum += (ex0 + ex1) + (ex2 + ex3);
        acc.x = fmaf(v40.x, ex0, acc.x);  acc.x = fmaf(v41.x, ex1, acc.x);
        acc.x = fmaf(v42.x, ex2, acc.x);  acc.x = fmaf(v43.x, ex3, acc.x);
        acc.y = fmaf(v40.y, ex0, acc.y);  acc.y = fmaf(v41.y, ex1, acc.y);
        acc.y = fmaf(v42.y, ex2, acc.y);  acc.y = fmaf(v43.y, ex3, acc.y);
        acc.z = fmaf(v40.z, ex0, acc.z);  acc.z = fmaf(v41.z, ex1, acc.z);
        acc.z = fmaf(v42.z, ex2, acc.z);  acc.z = fmaf(v43.z, ex3, acc.z);
        acc.w = fmaf(v40.w, ex0, acc.w);  acc.w = fmaf(v41.w, ex1, acc.w);
        acc.w = fmaf(v42.w, ex2, acc.w);  acc.w = fmaf(v43.w, ex3, acc.w);
        s0a = fmaf(ep0.x, ex0, s0a);      s0a = fmaf(ep1.x, ex1, s0a);
        s0a = fmaf(ep2.x, ex2, s0a);      s0a = fmaf(ep3.x, ex3, s0a);
        s1a = fmaf(ep0.y, ex0, s1a);      s1a = fmaf(ep1.y, ex1, s1a);
        s1a = fmaf(ep2.y, ex2, s1a);      s1a = fmaf(ep3.y, ex3, s1a);
    }

    for (; j < deg; j++) {   // tail edges (<=3)
        int2 ed = __ldg(&d_edge[start + j]);
        float2 ep = *(const float2*)(eattr + (size_t)ed.x * 16 + 2 * p);
        const float* base = d_qkvs + (size_t)ed.y * 512;
        float4 k4 = *(const float4*)(base + 128 + lane * 4);
        float4 v4 = *(const float4*)(base + 256 + lane * 4);
        float t = q4.x * k4.x + q4.y * k4.y + q4.z * k4.z + q4.w * k4.w +
                  ep.x * z0 + ep.y * z1;
        t += __shfl_xor_sync(FULL, t, 1);
        t += __shfl_xor_sync(FULL, t, 2);
        t += __shfl_xor_sync(FULL, t, 4);
        float ex = __expf(t * SC);
        dsum += ex;
        acc.x = fmaf(v4.x, ex, acc.x);
        acc.y = fmaf(v4.y, ex, acc.y);
        acc.z = fmaf(v4.z, ex, acc.z);
        acc.w = fmaf(v4.w, ex, acc.w);
        s0a = fmaf(ep.x, ex, s0a);
        s1a = fmaf(ep.y, ex, s1a);
    }

    // finalize: numer = acc + S @ We|head
    float4 num = acc;
#pragma unroll
    for (int i = 0; i < 8; i++) {
        float sa = __shfl_sync(FULL, s0a, gb + i);
        float sb2 = __shfl_sync(FULL, s1a, gb + i);
        num.x = fmaf(sa, wreg[2 * i].x, num.x); num.x = fmaf(sb2, wreg[2 * i + 1].x, num.x);
        num.y = fmaf(sa, wreg[2 * i].y, num.y); num.y = fmaf(sb2, wreg[2 * i + 1].y, num.y);
        num.z = fmaf(sa, wreg[2 * i].z, num.z); num.z = fmaf(sb2, wreg[2 * i + 1].z, num.z);
        num.w = fmaf(sa, wreg[2 * i].w, num.w); num.w = fmaf(sb2, wreg[2 * i + 1].w, num.w);
    }

    float inv = 1.0f / (dsum + 1e-16f);
    float4 sk = *(const float4*)(d_qkvs + (size_t)n * 512 + 384 + lane * 4);
    float4 o;
    o.x = fmaxf(fmaf(num.x, inv, sk.x), 0.0f);
    o.y = fmaxf(fmaf(num.y, inv, sk.y), 0.0f);
    o.z = fmaxf(fmaf(num.z, inv, sk.z), 0.0f);
    o.w = fmaxf(fmaf(num.w, inv, sk.w), 0.0f);
    *(float4*)(d_h + (size_t)n * 128 + lane * 4) = o;
}

// ---------------------------------------------------------------------------
// Output head: logits = h @ Wout + bout; log_softmax. One warp per node.
// ---------------------------------------------------------------------------
__global__ void __launch_bounds__(256) out_kernel(const float* __restrict__ Wout,
                                                  const float* __restrict__ bout,
                                                  float* __restrict__ out) {
    __shared__ float sW[128 * 10];
    __shared__ float sb[10];
    int tid = threadIdx.x;
    for (int i = tid; i < 128 * 10; i += 256) sW[i] = Wout[i];
    if (tid < 10) sb[tid] = bout[tid];
    __syncthreads();

    int warp = (blockIdx.x * 256 + tid) >> 5;
    int lane = tid & 31;
    if (warp >= NN) return;

    float4 hv = *(const float4*)(d_h + (size_t)warp * 128 + lane * 4);
    float lg[10];
#pragma unroll
    for (int c = 0; c < 10; c++) {
        float pp = hv.x * sW[(lane * 4 + 0) * 10 + c] +
                   hv.y * sW[(lane * 4 + 1) * 10 + c] +
                   hv.z * sW[(lane * 4 + 2) * 10 + c] +
                   hv.w * sW[(lane * 4 + 3) * 10 + c];
        pp += __shfl_xor_sync(0xffffffffu, pp, 16);
        pp += __shfl_xor_sync(0xffffffffu, pp, 8);
        pp += __shfl_xor_sync(0xffffffffu, pp, 4);
        pp += __shfl_xor_sync(0xffffffffu, pp, 2);
        pp += __shfl_xor_sync(0xffffffffu, pp, 1);
        lg[c] = pp + sb[c];
    }
    float mx = lg[0];
#pragma unroll
    for (int c = 1; c < 10; c++) mx = fmaxf(mx, lg[c]);
    float ss = 0.0f;
#pragma unroll
    for (int c = 0; c < 10; c++) ss += __expf(lg[c] - mx);
    float lse = mx + logf(ss);
    if (lane == 0) {
#pragma unroll
        for (int c = 0; c < 10; c++)
            out[(size_t)warp * 10 + c] = lg[c] - lse;
    }
}

// ---------------------------------------------------------------------------
// Launch (sgemm at captured launch index 3 for ncu)
// ---------------------------------------------------------------------------
extern "C" void kernel_launch(void* const* d_in, const int* in_sizes, int n_in,
                              void* d_out, int out_size) {
    const float* x     = (const float*)d_in[0];
    const int*   ei    = (const int*)d_in[1];
    const float* eattr = (const float*)d_in[2];
    const float* Wout = (const float*)d_in[21];
    const float* bout = (const float*)d_in[22];
    float* out = (float*)d_out;

    const int* src = ei;
    const int* dst = ei + EE;

    const int PACK_BLKS = (64 * 512 + 255) / 256;
    const int EDGE_BLKS = (EE + 255) / 256;
    const int NODE_BLKS = (NN + 255) / 256;
    const int ATTN_BLKS = (NN * 32 + 127) / 128;
    const int OUT_BLKS  = (NN * 32 + 255) / 256;
    dim3 gemmGrid(4, (NN + 127) / 128);

    const float* W0[9], *W1[9];
    for (int i = 0; i < 9; i++) { W0[i] = (const float*)d_in[3 + i]; W1[i] = (const float*)d_in[12 + i]; }

    zero_deg<<<NODE_BLKS, 256>>>();
    hist_kernel<<<EDGE_BLKS, 256>>>(dst);
    pack_kernel<<<PACK_BLKS, 256>>>(W0[0], W0[2], W0[4], W0[7], W0[1], W0[3], W0[5], W0[8]);
    sgemm_bf16x3<<<gemmGrid, 256>>>(x, 0, NN);
    chunk_sums<<<NCHUNK, 256>>>();
    chunk_offsets<<<1, 256>>>();
    scan_chunks<<<NCHUNK, 256>>>();
    scatter_perm<<<EDGE_BLKS, 256>>>(dst, src);
    attn_node<<<ATTN_BLKS, 128>>>(eattr, W0[6]);
    pack_kernel<<<PACK_BLKS, 256>>>(W1[0], W1[2], W1[4], W1[7], W1[1], W1[3], W1[5], W1[8]);
    sgemm_bf16x3<<<gemmGrid, 256>>>(nullptr, 1, NN);
    attn_node<<<ATTN_BLKS, 128>>>(eattr, W1[6]);
    out_kernel<<<OUT_BLKS, 256>>>(Wout, bout, out);
}

// round 11
// speedup vs baseline: 2.7365x; 1.0422x over previous
#include <cuda_runtime.h>
#include <cuda_bf16.h>
#include <cstdint>

// Problem constants (fixed by the dataset)
#define NN   50000
#define EE   600000
#define FD   128
#define EDIM 16
#define HH   4
#define DD   32
#define HIDD 128
#define CC   10

#define NCHUNK 196   // ceil(NN/256)

// ---------------------------------------------------------------------------
// Scratch (device globals; allocation-free per harness rules)
// ---------------------------------------------------------------------------
__device__ __align__(16) float d_qkvs[(size_t)NN * 512];   // q|k|v|skip packed per node
__device__ __align__(16) float d_h[(size_t)NN * 128];      // layer output
// B in bf16 hi/lo, FRAGMENT-ordered: [ch(8)][seg(16)][lane(32)][idx(8)]
__device__ __align__(16) uint32_t d_WfH[8 * 16 * 32 * 8];
__device__ __align__(16) uint32_t d_WfL[8 * 16 * 32 * 8];
__device__ __align__(16) float d_bp[512];

// CSR-by-dst (built once per launch, shared by both layers)
__device__ int d_deg[NN];
__device__ int d_start[NN];
__device__ int d_cursor[NN];
__device__ int2 d_edge[EE];  // (edge id, src node) permuted by dst
__device__ int d_csums[256];
__device__ int d_coffs[256];

// ---------------------------------------------------------------------------
// Helpers
// ---------------------------------------------------------------------------
__device__ __forceinline__ int warp_incl_scan(int v, int lane) {
#pragma unroll
    for (int o = 1; o < 32; o <<= 1) {
        int n = __shfl_up_sync(0xffffffffu, v, o);
        if (lane >= o) v += n;
    }
    return v;
}

__device__ __forceinline__ void split_bf16x2(float f0, float f1,
                                             uint32_t& hi, uint32_t& lo) {
    __nv_bfloat162 hp = __float22bfloat162_rn(make_float2(f0, f1));
    hi = *reinterpret_cast<uint32_t*>(&hp);
    float r0 = f0 - __low2float(hp);
    float r1 = f1 - __high2float(hp);
    __nv_bfloat162 lp = __float22bfloat162_rn(make_float2(r0, r1));
    lo = *reinterpret_cast<uint32_t*>(&lp);
}

__device__ __forceinline__ uint32_t smem_u32(const void* p) {
    return (uint32_t)__cvta_generic_to_shared(p);
}

// ---------------------------------------------------------------------------
// CSR build
// ---------------------------------------------------------------------------
__global__ void zero_deg() {
    int i = blockIdx.x * blockDim.x + threadIdx.x;
    if (i < NN) d_deg[i] = 0;
}

__global__ void hist_kernel(const int* __restrict__ dst) {
    int e = blockIdx.x * blockDim.x + threadIdx.x;
    if (e < EE) atomicAdd(&d_deg[dst[e]], 1);
}

__global__ void chunk_sums() {
    int tid = threadIdx.x, b = blockIdx.x, i = b * 256 + tid;
    int v = (i < NN) ? d_deg[i] : 0;
#pragma unroll
    for (int o = 16; o > 0; o >>= 1) v += __shfl_xor_sync(0xffffffffu, v, o);
    __shared__ int ws[8];
    if ((tid & 31) == 0) ws[tid >> 5] = v;
    __syncthreads();
    if (tid == 0) {
        int s = 0;
#pragma unroll
        for (int k = 0; k < 8; k++) s += ws[k];
        d_csums[b] = s;
    }
}

__global__ void chunk_offsets() {   // single block, 256 threads
    int tid = threadIdx.x;
    int lane = tid & 31, w = tid >> 5;
    __shared__ int ws[8];
    int v = (tid < NCHUNK) ? d_csums[tid] : 0;
    int incl = warp_incl_scan(v, lane);
    if (lane == 31) ws[w] = incl;
    __syncthreads();
    if (w == 0) {
        int t = (lane < 8) ? ws[lane] : 0;
        t = warp_incl_scan(t, lane);
        if (lane < 8) ws[lane] = t;
    }
    __syncthreads();
    int excl = incl - v + (w > 0 ? ws[w - 1] : 0);
    d_coffs[tid] = excl;
}

__global__ void scan_chunks() {
    int tid = threadIdx.x, b = blockIdx.x, i = b * 256 + tid;
    int lane = tid & 31, w = tid >> 5;
    __shared__ int ws[8];
    int v = (i < NN) ? d_deg[i] : 0;
    int incl = warp_incl_scan(v, lane);
    if (lane == 31) ws[w] = incl;
    __syncthreads();
    if (w == 0) {
        int t = (lane < 8) ? ws[lane] : 0;
        t = warp_incl_scan(t, lane);
        if (lane < 8) ws[lane] = t;
    }
    __syncthreads();
    int excl = incl - v + (w > 0 ? ws[w - 1] : 0) + d_coffs[b];
    if (i < NN) { d_start[i] = excl; d_cursor[i] = excl; }
}

__global__ void scatter_perm(const int* __restrict__ dst, const int* __restrict__ src) {
    int e = blockIdx.x * blockDim.x + threadIdx.x;
    if (e < EE) {
        int pos = atomicAdd(&d_cursor[dst[e]], 1);
        d_edge[pos] = make_int2(e, src[e]);
    }
}

// ---------------------------------------------------------------------------
// Pack weights: bf16 hi/lo split, FRAGMENT order
// ---------------------------------------------------------------------------
__global__ void pack_kernel(const float* __restrict__ Wq, const float* __restrict__ Wk,
                            const float* __restrict__ Wv, const float* __restrict__ Ws,
                            const float* __restrict__ bq, const float* __restrict__ bk,
                            const float* __restrict__ bv, const float* __restrict__ bs) {
    int idx = blockIdx.x * blockDim.x + threadIdx.x;
    if (idx < 64 * 512) {
        int kp = idx >> 9, col = idx & 511;
        int sel = col >> 7, jc = col & 127;
        const float* W = sel == 0 ? Wq : sel == 1 ? Wk : sel == 2 ? Wv : Ws;
        float f0 = W[(2 * kp) * 128 + jc];
        float f1 = W[(2 * kp + 1) * 128 + jc];
        uint32_t hi, lo;
        split_bf16x2(f0, f1, hi, lo);
        int ch = kp >> 3, kpl = kp & 7;
        int kh = kpl >> 2, tg = kpl & 3;
        int seg = col >> 5, g = col & 7, nt = (col >> 3) & 3;
        int off = ((ch * 16 + seg) * 32 + g * 4 + tg) * 8 + kh * 4 + nt;
        d_WfH[off] = hi;
        d_WfL[off] = lo;
    }
    if (idx < 512) {
        int sel = idx >> 7, jc = idx & 127;
        const float* b = sel == 0 ? bq : sel == 1 ? bk : sel == 2 ? bv : bs;
        d_bp[idx] = b[jc];
    }
}

// ---------------------------------------------------------------------------
// bf16x3 tensor-core GEMM, cp.async B, LDS.64 A fragments, conflict-free B.
// A smem: [2][128][8], k-pair interleave idx = (kp&3)*2 + (kp>>2) (stride 8).
// B smem: [2][4][32][12] (lane stride padded to 12 words for LDS.128).
// ---------------------------------------------------------------------------
#define KC 16

__global__ void __launch_bounds__(256, 2) sgemm_bf16x3(const float* __restrict__ x,
                                                       int layer, int M) {
    const float* A = (layer == 0) ? x : (const float*)d_h;

    __shared__ __align__(16) uint32_t AsH[2][128][8];
    __shared__ __align__(16) uint32_t AsL[2][128][8];
    __shared__ __align__(16) uint32_t BfH[2][4][32][12];
    __shared__ __align__(16) uint32_t BfL[2][4][32][12];

    int tid = threadIdx.x;
    int bx = blockIdx.x;
    int by = blockIdx.y;
    int warp = tid >> 5, lane = tid & 31;
    int wm = warp >> 2, wn = warp & 3;
    int mbase = wm * 64, nbase = wn * 32;
    int rowBase = by * 128;
    int g = lane >> 2;
    int tg = lane & 3;

    int aR0 = tid >> 2,          aC0 = tid & 3;
    int aR1 = (tid + 256) >> 2,  aC1 = (tid + 256) & 3;
    // interleaved store indices for pairs (2c, 2c+1)
    int aI0a = (aC0 & 1) * 4 + (aC0 >> 1), aI0b = aI0a + 2;
    int aI1a = (aC1 & 1) * 4 + (aC1 >> 1), aI1b = aI1a + 2;

    float c[4][4][4];
#pragma unroll
    for (int i = 0; i < 4; i++)
#pragma unroll
        for (int j = 0; j < 4; j++)
#pragma unroll
            for (int r = 0; r < 4; r++) c[i][j][r] = 0.0f;

    float4 aReg0, aReg1;
    int grA0 = rowBase + aR0, grA1 = rowBase + aR1;
    bool a0OK = (grA0 < M), a1OK = (grA1 < M);

    // cp.async B staging: thread -> (wn, lane, half)
    int wnT = tid >> 6, laneT = (tid >> 1) & 31, halfT = tid & 1;
    uint32_t dBH0 = smem_u32(&BfH[0][0][0][0]) + ((wnT * 32 + laneT) * 12 + halfT * 4) * 4;
    uint32_t dBL0 = smem_u32(&BfL[0][0][0][0]) + ((wnT * 32 + laneT) * 12 + halfT * 4) * 4;
    const uint32_t* gBH = d_WfH + (size_t)bx * 4 * 256 + tid * 4;
    const uint32_t* gBL = d_WfL + (size_t)bx * 4 * 256 + tid * 4;
    const uint32_t stageBytes = 4 * 32 * 12 * 4;   // 6144

    auto stageB = [&](int ch, int st) {
        uint32_t dH = dBH0 + st * stageBytes;
        uint32_t dL = dBL0 + st * stageBytes;
        const uint32_t* sH = gBH + ch * 4096;
        const uint32_t* sL = gBL + ch * 4096;
        asm volatile("cp.async.ca.shared.global [%0], [%1], 16;" :: "r"(dH), "l"(sH));
        asm volatile("cp.async.ca.shared.global [%0], [%1], 16;" :: "r"(dL), "l"(sL));
        asm volatile("cp.async.commit_group;");
    };

    auto loadA = [&](int ch) {
        int k0 = ch * KC;
        aReg0 = a0OK ? *(const float4*)(A + (size_t)grA0 * 128 + k0 + aC0 * 4)
                     : make_float4(0.f, 0.f, 0.f, 0.f);
        aReg1 = a1OK ? *(const float4*)(A + (size_t)grA1 * 128 + k0 + aC1 * 4)
                     : make_float4(0.f, 0.f, 0.f, 0.f);
    };

    auto storeA = [&](int st) {
        uint32_t h0, l0, h1, l1;
        split_bf16x2(aReg0.x, aReg0.y, h0, l0);
        split_bf16x2(aReg0.z, aReg0.w, h1, l1);
        AsH[st][aR0][aI0a] = h0;  AsH[st][aR0][aI0b] = h1;
        AsL[st][aR0][aI0a] = l0;  AsL[st][aR0][aI0b] = l1;
        split_bf16x2(aReg1.x, aReg1.y, h0, l0);
        split_bf16x2(aReg1.z, aReg1.w, h1, l1);
        AsH[st][aR1][aI1a] = h0;  AsH[st][aR1][aI1b] = h1;
        AsL[st][aR1][aI1a] = l0;  AsL[st][aR1][aI1b] = l1;
    };

    auto computeChunk = [&](int st) {
        const uint32_t* pH = &BfH[st][wn][lane][0];
        const uint32_t* pL = &BfL[st][wn][lane][0];
        uint4 bh0 = *(const uint4*)pH;
        uint4 bh1 = *(const uint4*)(pH + 4);
        uint4 bl0 = *(const uint4*)pL;
        uint4 bl1 = *(const uint4*)(pL + 4);
        uint32_t bh[4][2] = {{bh0.x, bh1.x}, {bh0.y, bh1.y}, {bh0.z, bh1.z}, {bh0.w, bh1.w}};
        uint32_t bl[4][2] = {{bl0.x, bl1.x}, {bl0.y, bl1.y}, {bl0.z, bl1.z}, {bl0.w, bl1.w}};
#pragma unroll
        for (int mt = 0; mt < 4; mt++) {
            int r = mbase + mt * 16 + g;
            uint2 ah0 = *(const uint2*)&AsH[st][r][2 * tg];
            uint2 ah1 = *(const uint2*)&AsH[st][r + 8][2 * tg];
            uint2 al0 = *(const uint2*)&AsL[st][r][2 * tg];
            uint2 al1 = *(const uint2*)&AsL[st][r + 8][2 * tg];
#pragma unroll
            for (int nt = 0; nt < 4; nt++) {
                float* cc = c[mt][nt];
                asm volatile(
                    "mma.sync.aligned.m16n8k16.row.col.f32.bf16.bf16.f32 "
                    "{%0,%1,%2,%3},{%4,%5,%6,%7},{%8,%9},{%0,%1,%2,%3};"
                    : "+f"(cc[0]), "+f"(cc[1]), "+f"(cc[2]), "+f"(cc[3])
                    : "r"(ah0.x), "r"(ah1.x), "r"(ah0.y), "r"(ah1.y),
                      "r"(bh[nt][0]), "r"(bh[nt][1]));
                asm volatile(
                    "mma.sync.aligned.m16n8k16.row.col.f32.bf16.bf16.f32 "
                    "{%0,%1,%2,%3},{%4,%5,%6,%7},{%8,%9},{%0,%1,%2,%3};"
                    : "+f"(cc[0]), "+f"(cc[1]), "+f"(cc[2]), "+f"(cc[3])
                    : "r"(ah0.x), "r"(ah1.x), "r"(ah0.y), "r"(ah1.y),
                      "r"(bl[nt][0]), "r"(bl[nt][1]));
                asm volatile(
                    "mma.sync.aligned.m16n8k16.row.col.f32.bf16.bf16.f32 "
                    "{%0,%1,%2,%3},{%4,%5,%6,%7},{%8,%9},{%0,%1,%2,%3};"
                    : "+f"(cc[0]), "+f"(cc[1]), "+f"(cc[2]), "+f"(cc[3])
                    : "r"(al0.x), "r"(al1.x), "r"(al0.y), "r"(al1.y),
                      "r"(bh[nt][0]), "r"(bh[nt][1]));
            }
        }
    };

    stageB(0, 0);
    loadA(0);
    storeA(0);
    asm volatile("cp.async.wait_group 0;" ::: "memory");
    __syncthreads();
#pragma unroll
    for (int ch = 0; ch < 8; ch++) {
        int cur = ch & 1;
        if (ch < 7) {
            loadA(ch + 1);
            stageB(ch + 1, cur ^ 1);
        }
        computeChunk(cur);
        if (ch < 7) {
            storeA(cur ^ 1);
            asm volatile("cp.async.wait_group 0;" ::: "memory");
            __syncthreads();
        }
    }

#pragma unroll
    for (int mt = 0; mt < 4; mt++) {
        int r0 = rowBase + mbase + mt * 16 + g;
        int r1 = r0 + 8;
#pragma unroll
        for (int nt = 0; nt < 4; nt++) {
            int col = bx * 128 + nbase + nt * 8 + 2 * tg;
            float2 b2 = *(const float2*)(d_bp + col);
            if (r0 < M) {
                float2 o = make_float2(c[mt][nt][0] + b2.x, c[mt][nt][1] + b2.y);
                *(float2*)(d_qkvs + (size_t)r0 * 512 + col) = o;
            }
            if (r1 < M) {
                float2 o = make_float2(c[mt][nt][2] + b2.x, c[mt][nt][3] + b2.y);
                *(float2*)(d_qkvs + (size_t)r1 * 512 + col) = o;
            }
        }
    }
}

// ---------------------------------------------------------------------------
// Node-centric attention (R9 form: algebraic + int2 edges + 4-wide unroll)
// ---------------------------------------------------------------------------
__global__ void __launch_bounds__(128) attn_node(const float* __restrict__ eattr,
                                                 const float* __restrict__ We) {
    const unsigned FULL = 0xffffffffu;
    int warp = (blockIdx.x * 128 + threadIdx.x) >> 5;
    int lane = threadIdx.x & 31;
    if (warp >= NN) return;
    int n = warp;
    int p = lane & 7;
    int gb = lane & 24;

    float4 wreg[16];
#pragma unroll
    for (int k = 0; k < 16; k++)
        wreg[k] = __ldg((const float4*)(We + k * 128) + lane);

    float4 q4 = *(const float4*)(d_qkvs + (size_t)n * 512 + lane * 4);

    float pk[16];
#pragma unroll
    for (int k = 0; k < 16; k++)
        pk[k] = q4.x * wreg[k].x + q4.y * wreg[k].y +
                q4.z * wreg[k].z + q4.w * wreg[k].w;
    float u[8];
#pragma unroll
    for (int i = 0; i < 8; i++) {
        float keep  = (lane & 4) ? pk[i + 8] : pk[i];
        float other = (lane & 4) ? pk[i] : pk[i + 8];
        u[i] = keep + __shfl_xor_sync(FULL, other, 4);
    }
    float w4[4];
#pragma unroll
    for (int i = 0; i < 4; i++) {
        float keep  = (lane & 2) ? u[i + 4] : u[i];
        float other = (lane & 2) ? u[i] : u[i + 4];
        w4[i] = keep + __shfl_xor_sync(FULL, other, 2);
    }
    float z0, z1;
    {
        float k0 = (lane & 1) ? w4[2] : w4[0];
        float o0 = (lane & 1) ? w4[0] : w4[2];
        z0 = k0 + __shfl_xor_sync(FULL, o0, 1);
        float k1 = (lane & 1) ? w4[3] : w4[1];
        float o1 = (lane & 1) ? w4[1] : w4[3];
        z1 = k1 + __shfl_xor_sync(FULL, o1, 1);
    }

    float4 acc = make_float4(0.f, 0.f, 0.f, 0.f);
    float s0a = 0.0f, s1a = 0.0f;
    float dsum = 0.0f;

    int start = d_start[n];
    int deg = d_deg[n];
    const float SC = 0.17677669529663687f;

    int j = 0;
    for (; j + 3 < deg; j += 4) {
        int2 ed0 = __ldg(&d_edge[start + j]);
        int2 ed1 = __ldg(&d_edge[start + j + 1]);
        int2 ed2 = __ldg(&d_edge[start + j + 2]);
        int2 ed3 = __ldg(&d_edge[start + j + 3]);

        float2 ep0 = *(const float2*)(eattr + (size_t)ed0.x * 16 + 2 * p);
        float2 ep1 = *(const float2*)(eattr + (size_t)ed1.x * 16 + 2 * p);
        float2 ep2 = *(const float2*)(eattr + (size_t)ed2.x * 16 + 2 * p);
        float2 ep3 = *(const float2*)(eattr + (size_t)ed3.x * 16 + 2 * p);

        const float* b0 = d_qkvs + (size_t)ed0.y * 512;
        const float* b1 = d_qkvs + (size_t)ed1.y * 512;
        const float* b2 = d_qkvs + (size_t)ed2.y * 512;
        const float* b3 = d_qkvs + (size_t)ed3.y * 512;
        float4 k40 = *(const float4*)(b0 + 128 + lane * 4);
        float4 k41 = *(const float4*)(b1 + 128 + lane * 4);
        float4 k42 = *(const float4*)(b2 + 128 + lane * 4);
        float4 k43 = *(const float4*)(b3 + 128 + lane * 4);
        float4 v40 = *(const float4*)(b0 + 256 + lane * 4);
        float4 v41 = *(const float4*)(b1 + 256 + lane * 4);
        float4 v42 = *(const float4*)(b2 + 256 + lane * 4);
        float4 v43 = *(const float4*)(b3 + 256 + lane * 4);

        float t0 = q4.x * k40.x + q4.y * k40.y + q4.z * k40.z + q4.w * k40.w +
                   ep0.x * z0 + ep0.y * z1;
        float t1 = q4.x * k41.x + q4.y * k41.y + q4.z * k41.z + q4.w * k41.w +
                   ep1.x * z0 + ep1.y * z1;
        float t2 = q4.x * k42.x + q4.y * k42.y + q4.z * k42.z + q4.w * k42.w +
                   ep2.x * z0 + ep2.y * z1;
        float t3 = q4.x * k43.x + q4.y * k43.y + q4.z * k43.z + q4.w * k43.w +
                   ep3.x * z0 + ep3.y * z1;
        t0 += __shfl_xor_sync(FULL, t0, 1);
        t1 += __shfl_xor_sync(FULL, t1, 1);
        t2 += __shfl_xor_sync(FULL, t2, 1);
        t3 += __shfl_xor_sync(FULL, t3, 1);
        t0 += __shfl_xor_sync(FULL, t0, 2);
        t1 += __shfl_xor_sync(FULL, t1, 2);
        t2 += __shfl_xor_sync(FULL, t2, 2);
        t3 += __shfl_xor_sync(FULL, t3, 2);
        t0 += __shfl_xor_sync(FULL, t0, 4);
        t1 += __shfl_xor_sync(FULL, t1, 4);
        t2 += __shfl_xor_sync(FULL, t2, 4);
        t3 += __shfl_xor_sync(FULL, t3, 4);

        float ex0 = __expf(t0 * SC);
        float ex1 = __expf(t1 * SC);
        float ex2 = __expf(t2 * SC);
        float ex3 = __expf(t3 * SC);
        dsum += (ex0 + ex1) + (ex2 + ex3);
        acc.x = fmaf(v40.x, ex0, acc.x);  acc.x = fmaf(v41.x, ex1, acc.x);
        acc.x = fmaf(v42.x, ex2, acc.x);  acc.x = fmaf(v43.x, ex3, acc.x);
        acc.y = fmaf(v40.y, ex0, acc.y);  acc.y = fmaf(v41.y, ex1, acc.y);
        acc.y = fmaf(v42.y, ex2, acc.y);  acc.y = fmaf(v43.y, ex3, acc.y);
        acc.z = fmaf(v40.z, ex0, acc.z);  acc.z = fmaf(v41.z, ex1, acc.z);
        acc.z = fmaf(v42.z, ex2, acc.z);  acc.z = fmaf(v43.z, ex3, acc.z);
        acc.w = fmaf(v40.w, ex0, acc.w);  acc.w = fmaf(v41.w, ex1, acc.w);
        acc.w = fmaf(v42.w, ex2, acc.w);  acc.w = fmaf(v43.w, ex3, acc.w);
        s0a = fmaf(ep0.x, ex0, s0a);      s0a = fmaf(ep1.x, ex1, s0a);
        s0a = fmaf(ep2.x, ex2, s0a);      s0a = fmaf(ep3.x, ex3, s0a);
        s1a = fmaf(ep0.y, ex0, s1a);      s1a = fmaf(ep1.y, ex1, s1a);
        s1a = fmaf(ep2.y, ex2, s1a);      s1a = fmaf(ep3.y, ex3, s1a);
    }

    for (; j < deg; j++) {
        int2 ed = __ldg(&d_edge[start + j]);
        float2 ep = *(const float2*)(eattr + (size_t)ed.x * 16 + 2 * p);
        const float* base = d_qkvs + (size_t)ed.y * 512;
        float4 k4 = *(const float4*)(base + 128 + lane * 4);
        float4 v4 = *(const float4*)(base + 256 + lane * 4);
        float t = q4.x * k4.x + q4.y * k4.y + q4.z * k4.z + q4.w * k4.w +
                  ep.x * z0 + ep.y * z1;
        t += __shfl_xor_sync(FULL, t, 1);
        t += __shfl_xor_sync(FULL, t, 2);
        t += __shfl_xor_sync(FULL, t, 4);
        float ex = __expf(t * SC);
        dsum += ex;
        acc.x = fmaf(v4.x, ex, acc.x);
        acc.y = fmaf(v4.y, ex, acc.y);
        acc.z = fmaf(v4.z, ex, acc.z);
        acc.w = fmaf(v4.w, ex, acc.w);
        s0a = fmaf(ep.x, ex, s0a);
        s1a = fmaf(ep.y, ex, s1a);
    }

    float4 num = acc;
#pragma unroll
    for (int i = 0; i < 8; i++) {
        float sa = __shfl_sync(FULL, s0a, gb + i);
        float sb2 = __shfl_sync(FULL, s1a, gb + i);
        num.x = fmaf(sa, wreg[2 * i].x, num.x); num.x = fmaf(sb2, wreg[2 * i + 1].x, num.x);
        num.y = fmaf(sa, wreg[2 * i].y, num.y); num.y = fmaf(sb2, wreg[2 * i + 1].y, num.y);
        num.z = fmaf(sa, wreg[2 * i].z, num.z); num.z = fmaf(sb2, wreg[2 * i + 1].z, num.z);
        num.w = fmaf(sa, wreg[2 * i].w, num.w); num.w = fmaf(sb2, wreg[2 * i + 1].w, num.w);
    }

    float inv = 1.0f / (dsum + 1e-16f);
    float4 sk = *(const float4*)(d_qkvs + (size_t)n * 512 + 384 + lane * 4);
    float4 o;
    o.x = fmaxf(fmaf(num.x, inv, sk.x), 0.0f);
    o.y = fmaxf(fmaf(num.y, inv, sk.y), 0.0f);
    o.z = fmaxf(fmaf(num.z, inv, sk.z), 0.0f);
    o.w = fmaxf(fmaf(num.w, inv, sk.w), 0.0f);
    *(float4*)(d_h + (size_t)n * 128 + lane * 4) = o;
}

// ---------------------------------------------------------------------------
// Output head: logits = h @ Wout + bout; log_softmax. One warp per node.
// ---------------------------------------------------------------------------
__global__ void __launch_bounds__(256) out_kernel(const float* __restrict__ Wout,
                                                  const float* __restrict__ bout,
                                                  float* __restrict__ out) {
    __shared__ float sW[128 * 10];
    __shared__ float sb[10];
    int tid = threadIdx.x;
    for (int i = tid; i < 128 * 10; i += 256) sW[i] = Wout[i];
    if (tid < 10) sb[tid] = bout[tid];
    __syncthreads();

    int warp = (blockIdx.x * 256 + tid) >> 5;
    int lane = tid & 31;
    if (warp >= NN) return;

    float4 hv = *(const float4*)(d_h + (size_t)warp * 128 + lane * 4);
    float lg[10];
#pragma unroll
    for (int c = 0; c < 10; c++) {
        float pp = hv.x * sW[(lane * 4 + 0) * 10 + c] +
                   hv.y * sW[(lane * 4 + 1) * 10 + c] +
                   hv.z * sW[(lane * 4 + 2) * 10 + c] +
                   hv.w * sW[(lane * 4 + 3) * 10 + c];
        pp += __shfl_xor_sync(0xffffffffu, pp, 16);
        pp += __shfl_xor_sync(0xffffffffu, pp, 8);
        pp += __shfl_xor_sync(0xffffffffu, pp, 4);
        pp += __shfl_xor_sync(0xffffffffu, pp, 2);
        pp += __shfl_xor_sync(0xffffffffu, pp, 1);
        lg[c] = pp + sb[c];
    }
    float mx = lg[0];
#pragma unroll
    for (int c = 1; c < 10; c++) mx = fmaxf(mx, lg[c]);
    float ss = 0.0f;
#pragma unroll
    for (int c = 0; c < 10; c++) ss += __expf(lg[c] - mx);
    float lse = mx + logf(ss);
    if (lane == 0) {
#pragma unroll
        for (int c = 0; c < 10; c++)
            out[(size_t)warp * 10 + c] = lg[c] - lse;
    }
}

// ---------------------------------------------------------------------------
// Launch: CSR build forked onto a second stream, overlapping pack0+sgemm0.
// Stream/events created once on the first (uncaptured) correctness call.
// ---------------------------------------------------------------------------
extern "C" void kernel_launch(void* const* d_in, const int* in_sizes, int n_in,
                              void* d_out, int out_size) {
    const float* x     = (const float*)d_in[0];
    const int*   ei    = (const int*)d_in[1];
    const float* eattr = (const float*)d_in[2];
    const float* Wout = (const float*)d_in[21];
    const float* bout = (const float*)d_in[22];
    float* out = (float*)d_out;

    const int* src = ei;
    const int* dst = ei + EE;

    const int PACK_BLKS = (64 * 512 + 255) / 256;
    const int EDGE_BLKS = (EE + 255) / 256;
    const int NODE_BLKS = (NN + 255) / 256;
    const int ATTN_BLKS = (NN * 32 + 127) / 128;
    const int OUT_BLKS  = (NN * 32 + 255) / 256;
    dim3 gemmGrid(4, (NN + 127) / 128);

    const float* W0[9], *W1[9];
    for (int i = 0; i < 9; i++) { W0[i] = (const float*)d_in[3 + i]; W1[i] = (const float*)d_in[12 + i]; }

    static cudaStream_t s2 = nullptr;
    static cudaEvent_t evFork = nullptr, evJoin = nullptr;
    if (s2 == nullptr) {
        cudaStreamCreateWithFlags(&s2, cudaStreamNonBlocking);
        cudaEventCreateWithFlags(&evFork, cudaEventDisableTiming);
        cudaEventCreateWithFlags(&evJoin, cudaEventDisableTiming);
    }

    // fork: CSR build on s2, projections on main stream
    cudaEventRecord(evFork, 0);
    cudaStreamWaitEvent(s2, evFork, 0);

    zero_deg<<<NODE_BLKS, 256, 0, s2>>>();
    hist_kernel<<<EDGE_BLKS, 256, 0, s2>>>(dst);
    chunk_sums<<<NCHUNK, 256, 0, s2>>>();
    chunk_offsets<<<1, 256, 0, s2>>>();
    scan_chunks<<<NCHUNK, 256, 0, s2>>>();
    scatter_perm<<<EDGE_BLKS, 256, 0, s2>>>(dst, src);
    cudaEventRecord(evJoin, s2);

    pack_kernel<<<PACK_BLKS, 256>>>(W0[0], W0[2], W0[4], W0[7], W0[1], W0[3], W0[5], W0[8]);
    sgemm_bf16x3<<<gemmGrid, 256>>>(x, 0, NN);

    // join before attention needs CSR
    cudaStreamWaitEvent(0, evJoin, 0);
    attn_node<<<ATTN_BLKS, 128>>>(eattr, W0[6]);

    pack_kernel<<<PACK_BLKS, 256>>>(W1[0], W1[2], W1[4], W1[7], W1[1], W1[3], W1[5], W1[8]);
    sgemm_bf16x3<<<gemmGrid, 256>>>(nullptr, 1, NN);
    attn_node<<<ATTN_BLKS, 128>>>(eattr, W1[6]);
    out_kernel<<<OUT_BLKS, 256>>>(Wout, bout, out);
}